// round 1
// baseline (speedup 1.0000x reference)
#include <cuda_runtime.h>
#include <math.h>

#define NA   4096
#define HD   256
#define HG   256      // H*G is 256 for both GAT layers
#define ACT  64
#define MMB  1024

// ---------------- device scratch (static: no allocs allowed) ----------------
__device__ float g_enc[NA*HD];
__device__ float g_gates[NA*4*HD];
__device__ float g_commq[NA*HD];     // quantized comm (reused for both quant stages)
__device__ float g_hW[NA*HD];        // GAT projection (reused GAT1/GAT2)
__device__ float g_comm1[NA*HD];     // elu(GAT1 out + b1)
__device__ float g_comm2[NA*HD];     // GAT2 out + b2
__device__ float g_logits[NA*ACT];
__device__ float g_ci[4*NA];
__device__ float g_cj[4*NA];
__device__ float g_cmax[4];
__device__ int   g_kcount[4*NA];
__device__ int   g_sidx[4*NA];
__device__ float g_wA[4*NA];
__device__ float g_wB[4*NA];
__device__ float g_sufA_s[4*NA];
__device__ float g_preB_s[4*NA];
__device__ float g_sufA_v[HG*NA];    // [h*G+g][r]
__device__ float g_preB_v[HG*NA];
__device__ float g_pmin[MMB];
__device__ float g_pmax[MMB];
__device__ float g_qparam[2];        // scale, zp
__device__ double g_loss;

// ---------------- kernels ----------------

__global__ void k_init() { g_loss = 0.0; }

// C[M,N] = A[M,K] @ op(B) (+bias[n]) (+= C if accum). op(B)=B[K,N] or B^T with B=[N,K].
__global__ void sgemm(const float* __restrict__ A, const float* __restrict__ B,
                      const float* __restrict__ bias, float* __restrict__ C,
                      int M, int N, int K, int transB, int accum)
{
    __shared__ float As[16][65];
    __shared__ float Bs[16][65];
    int tid = threadIdx.x;              // 256 threads
    int tx = tid & 15, ty = tid >> 4;
    int row0 = blockIdx.y * 64, col0 = blockIdx.x * 64;
    float acc[4][4] = {};
    for (int k0 = 0; k0 < K; k0 += 16) {
        #pragma unroll
        for (int l = 0; l < 4; l++) {
            int idx = tid + l * 256;
            int m = idx >> 4, kk = idx & 15;
            As[kk][m] = A[(row0 + m) * K + k0 + kk];
        }
        if (!transB) {
            #pragma unroll
            for (int l = 0; l < 4; l++) {
                int idx = tid + l * 256;
                int kk = idx >> 6, n = idx & 63;
                Bs[kk][n] = B[(k0 + kk) * N + col0 + n];
            }
        } else {
            #pragma unroll
            for (int l = 0; l < 4; l++) {
                int idx = tid + l * 256;
                int n = idx >> 4, kk = idx & 15;
                Bs[kk][n] = B[(col0 + n) * K + k0 + kk];
            }
        }
        __syncthreads();
        #pragma unroll
        for (int kk = 0; kk < 16; kk++) {
            float a[4], b[4];
            #pragma unroll
            for (int i = 0; i < 4; i++) a[i] = As[kk][ty*4+i];
            #pragma unroll
            for (int j = 0; j < 4; j++) b[j] = Bs[kk][tx*4+j];
            #pragma unroll
            for (int i = 0; i < 4; i++)
                #pragma unroll
                for (int j = 0; j < 4; j++)
                    acc[i][j] = fmaf(a[i], b[j], acc[i][j]);
        }
        __syncthreads();
    }
    #pragma unroll
    for (int i = 0; i < 4; i++) {
        int m = row0 + ty*4 + i;
        if (m >= M) continue;
        #pragma unroll
        for (int j = 0; j < 4; j++) {
            int n = col0 + tx*4 + j;
            if (n >= N) continue;
            float v = acc[i][j];
            if (bias)  v += bias[n];
            if (accum) v += C[m*N + n];
            C[m*N + n] = v;
        }
    }
}

__global__ void lstm_pw(const float* __restrict__ gates, const float* __restrict__ c0,
                        float* __restrict__ h, float* __restrict__ c)
{
    int idx = blockIdx.x * blockDim.x + threadIdx.x;
    if (idx >= NA*HD) return;
    int n = idx / HD, k = idx % HD;
    const float* gr = gates + n * (4*HD);
    float ig = gr[k], fg = gr[HD+k], gg = gr[2*HD+k], og = gr[3*HD+k];
    float si = 1.f/(1.f+expf(-ig));
    float sf = 1.f/(1.f+expf(-fg));
    float so = 1.f/(1.f+expf(-og));
    float c2 = sf * c0[idx] + si * tanhf(gg);
    h[idx] = so * tanhf(c2);
    c[idx] = c2;
}

__global__ void minmax1(const float* __restrict__ x, int n)
{
    __shared__ float smn[256], smx[256];
    float mn = 1e30f, mx = -1e30f;
    for (int i = blockIdx.x*256 + threadIdx.x; i < n; i += gridDim.x*256) {
        float v = x[i]; mn = fminf(mn, v); mx = fmaxf(mx, v);
    }
    smn[threadIdx.x] = mn; smx[threadIdx.x] = mx; __syncthreads();
    for (int s = 128; s > 0; s >>= 1) {
        if (threadIdx.x < s) {
            smn[threadIdx.x] = fminf(smn[threadIdx.x], smn[threadIdx.x+s]);
            smx[threadIdx.x] = fmaxf(smx[threadIdx.x], smx[threadIdx.x+s]);
        }
        __syncthreads();
    }
    if (threadIdx.x == 0) { g_pmin[blockIdx.x] = smn[0]; g_pmax[blockIdx.x] = smx[0]; }
}

__global__ void minmax2()
{
    __shared__ float smn[MMB], smx[MMB];
    int t = threadIdx.x;
    smn[t] = g_pmin[t]; smx[t] = g_pmax[t];
    __syncthreads();
    for (int s = MMB/2; s > 0; s >>= 1) {
        if (t < s) { smn[t] = fminf(smn[t], smn[t+s]); smx[t] = fmaxf(smx[t], smx[t+s]); }
        __syncthreads();
    }
    if (t == 0) {
        float mn = smn[0], mx = smx[0];
        if (mn == mx) { mn -= 0.01f; mx += 0.01f; }
        float scale = (mx - mn) / 255.f;
        g_qparam[0] = scale;
        g_qparam[1] = rintf(-mn / scale);
    }
}

__global__ void quant_loss(const float* __restrict__ x, float* __restrict__ q, int n)
{
    float scale = g_qparam[0], zp = g_qparam[1];
    double part = 0.0;
    for (int i = blockIdx.x*blockDim.x + threadIdx.x; i < n; i += gridDim.x*blockDim.x) {
        float t = x[i];
        float r = rintf(t/scale + zp);
        r = fminf(fmaxf(r, 0.f), 255.f);
        float d = (r - zp) * scale;
        q[i] = d;
        part += (double)log2f(510.f * fabsf(d) + 1.f);
    }
    __shared__ double sd[256];
    sd[threadIdx.x] = part; __syncthreads();
    for (int s = 128; s > 0; s >>= 1) { if (threadIdx.x < s) sd[threadIdx.x] += sd[threadIdx.x+s]; __syncthreads(); }
    if (threadIdx.x == 0) atomicAdd(&g_loss, sd[0]);
}

// ci[h,n] = sum_g hW[n,h,g]*ai[h,g]; cj similarly. One warp per (n,h).
__global__ void cicj(const float* __restrict__ ai, const float* __restrict__ aj, int H, int G)
{
    int warp = (blockIdx.x*blockDim.x + threadIdx.x) >> 5;
    int lane = threadIdx.x & 31;
    if (warp >= NA * H) return;
    int n = warp / H, h = warp % H;
    float si = 0.f, sj = 0.f;
    for (int g = lane; g < G; g += 32) {
        float v = g_hW[n*HG + h*G + g];
        si += v * ai[h*G + g];
        sj += v * aj[h*G + g];
    }
    for (int o = 16; o > 0; o >>= 1) {
        si += __shfl_down_sync(0xffffffffu, si, o);
        sj += __shfl_down_sync(0xffffffffu, sj, o);
    }
    if (lane == 0) { g_ci[h*NA + n] = si; g_cj[h*NA + n] = sj; }
}

__global__ void cmaxk()   // grid = H
{
    __shared__ float s[1024];
    int h = blockIdx.x;
    float m = -1e30f;
    for (int i = threadIdx.x; i < NA; i += 1024) m = fmaxf(m, g_cj[h*NA + i]);
    s[threadIdx.x] = m; __syncthreads();
    for (int st = 512; st > 0; st >>= 1) {
        if (threadIdx.x < st) s[threadIdx.x] = fmaxf(s[threadIdx.x], s[threadIdx.x+st]);
        __syncthreads();
    }
    if (threadIdx.x == 0) g_cmax[h] = s[0];
}

// grid = H*4, block = 1024: computes sort rank of each cj (scatter perm+weights)
// and the per-query count k_i = #{ cj <= -ci }.
__global__ void rankcount()
{
    __shared__ float s[NA];
    int h = blockIdx.x >> 2, part = blockIdx.x & 3;
    for (int i = threadIdx.x; i < NA; i += 1024) s[i] = g_cj[h*NA + i];
    __syncthreads();
    int j = part*1024 + threadIdx.x;
    float my = s[j];
    float t  = -g_ci[h*NA + j];
    int rank = 0, k = 0;
    for (int jj = 0; jj < NA; jj++) {
        float v = s[jj];
        rank += (v < my) || (v == my && jj < j);
        k    += (v <= t);
    }
    float cm = g_cmax[h];
    g_sidx[h*NA + rank] = j;
    g_wA[h*NA + rank]   = expf(my - cm);
    g_wB[h*NA + rank]   = expf(0.2f * (my - cm));
    g_kcount[h*NA + j]  = k;
}

// grid = H, 32 threads: scalar prefix(wB) and suffix(wA) over sorted order.
__global__ void scan_scalar()
{
    int h = blockIdx.x, lane = threadIdx.x;
    float carry = 0.f;
    for (int b = 0; b < NA; b += 32) {
        float v = g_wB[h*NA + b + lane];
        #pragma unroll
        for (int o = 1; o < 32; o <<= 1) { float t = __shfl_up_sync(0xffffffffu, v, o); if (lane >= o) v += t; }
        float tot = __shfl_sync(0xffffffffu, v, 31);
        g_preB_s[h*NA + b + lane] = v + carry;
        carry += tot;
    }
    carry = 0.f;
    for (int b = NA - 32; b >= 0; b -= 32) {
        float v = g_wA[h*NA + b + lane];
        #pragma unroll
        for (int o = 1; o < 32; o <<= 1) { float t = __shfl_down_sync(0xffffffffu, v, o); if (lane + o < 32) v += t; }
        float tot = __shfl_sync(0xffffffffu, v, 0);
        g_sufA_s[h*NA + b + lane] = v + carry;
        carry += tot;
    }
}

// one warp per (h,g): vector prefix(wB*hW) and suffix(wA*hW) over sorted order.
__global__ void scan_vec(int H, int G)
{
    int warp = (blockIdx.x*blockDim.x + threadIdx.x) >> 5;
    int lane = threadIdx.x & 31;
    if (warp >= H * G) return;
    int h = warp / G, g = warp % G;
    int base_out = (h*G + g) * NA;
    float carry = 0.f;
    for (int b = 0; b < NA; b += 32) {
        int id = g_sidx[h*NA + b + lane];
        float x = g_hW[id*HG + h*G + g];
        float v = g_wB[h*NA + b + lane] * x;
        #pragma unroll
        for (int o = 1; o < 32; o <<= 1) { float t = __shfl_up_sync(0xffffffffu, v, o); if (lane >= o) v += t; }
        float tot = __shfl_sync(0xffffffffu, v, 31);
        g_preB_v[base_out + b + lane] = v + carry;
        carry += tot;
    }
    carry = 0.f;
    for (int b = NA - 32; b >= 0; b -= 32) {
        int id = g_sidx[h*NA + b + lane];
        float x = g_hW[id*HG + h*G + g];
        float v = g_wA[h*NA + b + lane] * x;
        #pragma unroll
        for (int o = 1; o < 32; o <<= 1) { float t = __shfl_down_sync(0xffffffffu, v, o); if (lane + o < 32) v += t; }
        float tot = __shfl_sync(0xffffffffu, v, 0);
        g_sufA_v[base_out + b + lane] = v + carry;
        carry += tot;
    }
}

// out[n, h*G+g] = (r*Av + Bv)/(r*A + B) + bias, optional elu. r = exp(0.8*(ci+cmax))
__global__ void combine(const float* __restrict__ bias, float* __restrict__ out,
                        int H, int G, int do_elu)
{
    int idx = blockIdx.x*blockDim.x + threadIdx.x;
    if (idx >= NA*HG) return;
    int gi = idx % G;
    int h  = (idx / G) % H;
    int n  = idx / HG;
    int k  = g_kcount[h*NA + n];
    float r = expf(0.8f * (g_ci[h*NA + n] + g_cmax[h]));
    float A = (k < NA) ? g_sufA_s[h*NA + k]     : 0.f;
    float B = (k > 0)  ? g_preB_s[h*NA + k - 1] : 0.f;
    int vb = (h*G + gi) * NA;
    float Av = (k < NA) ? g_sufA_v[vb + k]     : 0.f;
    float Bv = (k > 0)  ? g_preB_v[vb + k - 1] : 0.f;
    float val = (r*Av + Bv) / (r*A + B);
    val += bias[h*G + gi];
    if (do_elu) val = (val > 0.f) ? val : expm1f(val);
    out[idx] = val;
}

__global__ void valuek(const float* __restrict__ h, const float* __restrict__ comm2,
                       const float* __restrict__ Wv, const float* __restrict__ bv,
                       float* __restrict__ val)
{
    int warp = (blockIdx.x*blockDim.x + threadIdx.x) >> 5;
    int lane = threadIdx.x & 31;
    if (warp >= NA) return;
    float s = 0.f;
    for (int k = lane; k < HD; k += 32)
        s += h[warp*HD + k] * Wv[k] + comm2[warp*HD + k] * Wv[HD + k];
    for (int o = 16; o > 0; o >>= 1) s += __shfl_down_sync(0xffffffffu, s, o);
    if (lane == 0) val[warp] = s + bv[0];
}

__global__ void logsm(const float* __restrict__ logits, float* __restrict__ out)
{
    int warp = (blockIdx.x*blockDim.x + threadIdx.x) >> 5;
    int lane = threadIdx.x & 31;
    if (warp >= NA) return;
    float x0 = logits[warp*ACT + lane];
    float x1 = logits[warp*ACT + 32 + lane];
    float m = fmaxf(x0, x1);
    for (int o = 16; o > 0; o >>= 1) m = fmaxf(m, __shfl_xor_sync(0xffffffffu, m, o));
    float s = expf(x0 - m) + expf(x1 - m);
    for (int o = 16; o > 0; o >>= 1) s += __shfl_xor_sync(0xffffffffu, s, o);
    float lse = m + logf(s);
    out[warp*ACT + lane]      = x0 - lse;
    out[warp*ACT + 32 + lane] = x1 - lse;
}

__global__ void k_writeloss(float* __restrict__ dst) { dst[0] = (float)g_loss; }

// ---------------- host ----------------
extern "C" void kernel_launch(void* const* d_in, const int* in_sizes, int n_in,
                              void* d_out, int out_size)
{
    const float* obs  = (const float*)d_in[0];
    const float* h0   = (const float*)d_in[1];
    const float* c0   = (const float*)d_in[2];
    const float* Wobs = (const float*)d_in[3];
    const float* bobs = (const float*)d_in[4];
    const float* Wih  = (const float*)d_in[5];
    const float* Whh  = (const float*)d_in[6];
    const float* bih  = (const float*)d_in[7];
    const float* bhh  = (const float*)d_in[8];
    const float* W1   = (const float*)d_in[9];
    const float* ai1  = (const float*)d_in[10];
    const float* aj1  = (const float*)d_in[11];
    const float* b1   = (const float*)d_in[12];
    const float* W2   = (const float*)d_in[13];
    const float* ai2  = (const float*)d_in[14];
    const float* aj2  = (const float*)d_in[15];
    const float* b2   = (const float*)d_in[16];
    const float* Wv   = (const float*)d_in[17];
    const float* bv   = (const float*)d_in[18];
    const float* Wa   = (const float*)d_in[19];
    const float* ba   = (const float*)d_in[20];

    float* out       = (float*)d_out;
    float* out_logp  = out;
    float* out_value = out + NA*ACT;
    float* out_h     = out_value + NA;
    float* out_c     = out_h + NA*HD;
    float* out_loss  = out_c + NA*HD;

    float *p_enc, *p_gates, *p_commq, *p_hW, *p_comm1, *p_comm2, *p_logits;
    cudaGetSymbolAddress((void**)&p_enc,    g_enc);
    cudaGetSymbolAddress((void**)&p_gates,  g_gates);
    cudaGetSymbolAddress((void**)&p_commq,  g_commq);
    cudaGetSymbolAddress((void**)&p_hW,     g_hW);
    cudaGetSymbolAddress((void**)&p_comm1,  g_comm1);
    cudaGetSymbolAddress((void**)&p_comm2,  g_comm2);
    cudaGetSymbolAddress((void**)&p_logits, g_logits);

    k_init<<<1, 1>>>();

    // 1. enc = obs @ Wobs + bobs
    sgemm<<<dim3(HD/64, NA/64), 256>>>(obs, Wobs, bobs, p_enc, NA, HD, HD, 0, 0);
    // 2. gates = enc @ Wih^T + bih ; gates += h0 @ Whh^T + bhh
    sgemm<<<dim3(4*HD/64, NA/64), 256>>>(p_enc, Wih, bih, p_gates, NA, 4*HD, HD, 1, 0);
    sgemm<<<dim3(4*HD/64, NA/64), 256>>>(h0,    Whh, bhh, p_gates, NA, 4*HD, HD, 1, 1);
    // 3. LSTM pointwise -> h, c (direct to output)
    lstm_pw<<<(NA*HD)/256, 256>>>(p_gates, c0, out_h, out_c);
    // 4. fake quant #1 on h
    minmax1<<<MMB, 256>>>(out_h, NA*HD);
    minmax2<<<1, MMB>>>();
    quant_loss<<<MMB, 256>>>(out_h, p_commq, NA*HD);
    // 5. GAT1 projection
    sgemm<<<dim3(HD/64, NA/64), 256>>>(p_commq, W1, nullptr, p_hW, NA, HD, HD, 0, 0);
    // 6. GAT1 attention (separable exact softmax)
    cicj<<<(NA*4*32)/256, 256>>>(ai1, aj1, 4, 64);
    cmaxk<<<4, 1024>>>();
    rankcount<<<16, 1024>>>();
    scan_scalar<<<4, 32>>>();
    scan_vec<<<(4*64*32)/256, 256>>>(4, 64);
    combine<<<(NA*HG)/256, 256>>>(b1, p_comm1, 4, 64, 1);
    // 7. fake quant #2 on elu(GAT1 out)
    minmax1<<<MMB, 256>>>(p_comm1, NA*HD);
    minmax2<<<1, MMB>>>();
    quant_loss<<<MMB, 256>>>(p_comm1, p_commq, NA*HD);
    // 8. GAT2 projection
    sgemm<<<dim3(HD/64, NA/64), 256>>>(p_commq, W2, nullptr, p_hW, NA, HD, HD, 0, 0);
    // 9. GAT2 attention (H=1, G=256)
    cicj<<<(NA*1*32)/256, 256>>>(ai2, aj2, 1, 256);
    cmaxk<<<1, 1024>>>();
    rankcount<<<4, 1024>>>();
    scan_scalar<<<1, 32>>>();
    scan_vec<<<(1*256*32)/256, 256>>>(1, 256);
    combine<<<(NA*HG)/256, 256>>>(b2, p_comm2, 1, 256, 0);
    // 10. value head
    valuek<<<(NA*32)/256, 256>>>(out_h, p_comm2, Wv, bv, out_value);
    // 11. policy head: logits = h @ Wa[:256] + ba ; += comm2 @ Wa[256:]
    sgemm<<<dim3(1, NA/64), 256>>>(out_h,   Wa,          ba,      p_logits, NA, ACT, HD, 0, 0);
    sgemm<<<dim3(1, NA/64), 256>>>(p_comm2, Wa + HD*ACT, nullptr, p_logits, NA, ACT, HD, 0, 1);
    logsm<<<(NA*32)/256, 256>>>(p_logits, out_logp);
    // 12. loss scalar
    k_writeloss<<<1, 1>>>(out_loss);
}

// round 2
// speedup vs baseline: 2.6940x; 2.6940x over previous
#include <cuda_runtime.h>
#include <math.h>

#define NA   4096
#define HD   256
#define HG   256
#define ACT  64
#define MMB  1024

// ---------------- device scratch ----------------
__device__ float g_enc[NA*HD];
__device__ float g_gates[NA*4*HD];
__device__ float g_commq[NA*HD];
__device__ float g_hW[NA*HG];
__device__ float g_hWT[HG*NA];
__device__ float g_comm1[NA*HD];
__device__ float g_comm2[NA*HD];
__device__ float g_logits[NA*ACT];
__device__ float g_cat[NA*2*HD];
__device__ float g_Wcat[4*HD*2*HD];
__device__ float g_bsum[4*HD];
__device__ float g_ci[4*NA];
__device__ float g_cj[4*NA];
__device__ float g_cjs[4*NA];
__device__ float g_cmax[4];
__device__ int   g_kcount[4*NA];
__device__ int   g_sidx[4*NA];
__device__ float g_wA[4*NA];
__device__ float g_wB[4*NA];
__device__ float g_sufA_s[4*NA];
__device__ float g_preB_s[4*NA];
__device__ float g_sufA_v[HG*NA];
__device__ float g_preB_v[HG*NA];
__device__ float g_pmin[MMB];
__device__ float g_pmax[MMB];
__device__ float g_qparam[2];
__device__ double g_loss;

__global__ void k_init() { g_loss = 0.0; }

// ---------------- GEMM: BMxBN tile, TMxTN micro, 256 threads ----------------
template<int BM, int BN, int TM, int TN>
__global__ void __launch_bounds__(256, 2)
gemmT(const float* __restrict__ A, const float* __restrict__ B,
      const float* __restrict__ bias, float* __restrict__ C,
      int M, int N, int K, int transB)
{
    const int BK = 16;
    __shared__ float As[BK][BM+4];
    __shared__ float Bs[BK][BN+4];
    int tid = threadIdx.x;
    int tx = tid % (BN/TN);
    int ty = tid / (BN/TN);
    int row0 = blockIdx.y * BM, col0 = blockIdx.x * BN;
    float acc[TM][TN] = {};
    for (int k0 = 0; k0 < K; k0 += BK) {
        #pragma unroll
        for (int p = 0; p < (BM*BK)/1024; p++) {
            int lin = (p*256 + tid) * 4;
            int m = lin / BK, kk = lin % BK;
            float4 v = *(const float4*)&A[(size_t)(row0+m)*K + k0 + kk];
            As[kk+0][m] = v.x; As[kk+1][m] = v.y; As[kk+2][m] = v.z; As[kk+3][m] = v.w;
        }
        if (!transB) {
            #pragma unroll
            for (int p = 0; p < (BN*BK)/1024; p++) {
                int lin = (p*256 + tid) * 4;
                int kk = lin / BN, n = lin % BN;
                *(float4*)&Bs[kk][n] = *(const float4*)&B[(size_t)(k0+kk)*N + col0 + n];
            }
        } else {
            #pragma unroll
            for (int p = 0; p < (BN*BK)/1024; p++) {
                int lin = (p*256 + tid) * 4;
                int n = lin / BK, kk = lin % BK;
                float4 v = *(const float4*)&B[(size_t)(col0+n)*K + k0 + kk];
                Bs[kk+0][n] = v.x; Bs[kk+1][n] = v.y; Bs[kk+2][n] = v.z; Bs[kk+3][n] = v.w;
            }
        }
        __syncthreads();
        #pragma unroll
        for (int kk = 0; kk < BK; kk++) {
            float a[TM], bb[TN];
            #pragma unroll
            for (int i = 0; i < TM; i++) a[i] = As[kk][ty*TM+i];
            #pragma unroll
            for (int j = 0; j < TN; j++) bb[j] = Bs[kk][tx*TN+j];
            #pragma unroll
            for (int i = 0; i < TM; i++)
                #pragma unroll
                for (int j = 0; j < TN; j++)
                    acc[i][j] = fmaf(a[i], bb[j], acc[i][j]);
        }
        __syncthreads();
    }
    #pragma unroll
    for (int i = 0; i < TM; i++) {
        int m = row0 + ty*TM + i;
        #pragma unroll
        for (int j = 0; j < TN; j++) {
            int n = col0 + tx*TN + j;
            float v = acc[i][j];
            if (bias) v += bias[n];
            C[(size_t)m*N + n] = v;
        }
    }
}

// ---------------- concat helpers ----------------
__global__ void catWk(const float* __restrict__ Wih, const float* __restrict__ Whh,
                      const float* __restrict__ bih, const float* __restrict__ bhh)
{
    int idx = blockIdx.x*256 + threadIdx.x;
    if (idx < 1024*512) {
        int r = idx >> 9, k = idx & 511;
        g_Wcat[idx] = (k < 256) ? Wih[r*256+k] : Whh[r*256 + k - 256];
    }
    if (idx < 1024) g_bsum[idx] = bih[idx] + bhh[idx];
}

__global__ void cat2k(const float* __restrict__ A0, const float* __restrict__ A1,
                      float* __restrict__ dst)
{
    int idx = blockIdx.x*256 + threadIdx.x;   // over NA*512
    int n = idx >> 9, k = idx & 511;
    dst[idx] = (k < 256) ? A0[n*256 + k] : A1[n*256 + k - 256];
}

// ---------------- LSTM pointwise ----------------
__global__ void lstm_pw(const float* __restrict__ gates, const float* __restrict__ c0,
                        float* __restrict__ h, float* __restrict__ c)
{
    int idx = blockIdx.x * blockDim.x + threadIdx.x;
    if (idx >= NA*HD) return;
    int n = idx / HD, k = idx % HD;
    const float* gr = gates + n * (4*HD);
    float ig = gr[k], fg = gr[HD+k], gg = gr[2*HD+k], og = gr[3*HD+k];
    float si = 1.f/(1.f+expf(-ig));
    float sf = 1.f/(1.f+expf(-fg));
    float so = 1.f/(1.f+expf(-og));
    float c2 = sf * c0[idx] + si * tanhf(gg);
    h[idx] = so * tanhf(c2);
    c[idx] = c2;
}

// ---------------- fake quant ----------------
__global__ void minmax1(const float* __restrict__ x, int n)
{
    __shared__ float smn[256], smx[256];
    float mn = 1e30f, mx = -1e30f;
    for (int i = blockIdx.x*256 + threadIdx.x; i < n; i += gridDim.x*256) {
        float v = x[i]; mn = fminf(mn, v); mx = fmaxf(mx, v);
    }
    smn[threadIdx.x] = mn; smx[threadIdx.x] = mx; __syncthreads();
    for (int s = 128; s > 0; s >>= 1) {
        if (threadIdx.x < s) {
            smn[threadIdx.x] = fminf(smn[threadIdx.x], smn[threadIdx.x+s]);
            smx[threadIdx.x] = fmaxf(smx[threadIdx.x], smx[threadIdx.x+s]);
        }
        __syncthreads();
    }
    if (threadIdx.x == 0) { g_pmin[blockIdx.x] = smn[0]; g_pmax[blockIdx.x] = smx[0]; }
}

__global__ void minmax2()
{
    __shared__ float smn[MMB], smx[MMB];
    int t = threadIdx.x;
    smn[t] = g_pmin[t]; smx[t] = g_pmax[t];
    __syncthreads();
    for (int s = MMB/2; s > 0; s >>= 1) {
        if (t < s) { smn[t] = fminf(smn[t], smn[t+s]); smx[t] = fmaxf(smx[t], smx[t+s]); }
        __syncthreads();
    }
    if (t == 0) {
        float mn = smn[0], mx = smx[0];
        if (mn == mx) { mn -= 0.01f; mx += 0.01f; }
        float scale = (mx - mn) / 255.f;
        g_qparam[0] = scale;
        g_qparam[1] = rintf(-mn / scale);
    }
}

__global__ void quant_loss(const float* __restrict__ x, float* __restrict__ q, int n)
{
    float scale = g_qparam[0], zp = g_qparam[1];
    double part = 0.0;
    for (int i = blockIdx.x*blockDim.x + threadIdx.x; i < n; i += gridDim.x*blockDim.x) {
        float t = x[i];
        float r = rintf(t/scale + zp);
        r = fminf(fmaxf(r, 0.f), 255.f);
        float d = (r - zp) * scale;
        q[i] = d;
        part += (double)log2f(510.f * fabsf(d) + 1.f);
    }
    __shared__ double sd[256];
    sd[threadIdx.x] = part; __syncthreads();
    for (int s = 128; s > 0; s >>= 1) { if (threadIdx.x < s) sd[threadIdx.x] += sd[threadIdx.x+s]; __syncthreads(); }
    if (threadIdx.x == 0) atomicAdd(&g_loss, sd[0]);
}

// ---------------- GAT attention (separable exact softmax) ----------------
__global__ void cicj(const float* __restrict__ ai, const float* __restrict__ aj, int H, int G)
{
    int warp = (blockIdx.x*blockDim.x + threadIdx.x) >> 5;
    int lane = threadIdx.x & 31;
    if (warp >= NA * H) return;
    int n = warp / H, h = warp % H;
    float si = 0.f, sj = 0.f;
    for (int g = lane; g < G; g += 32) {
        float v = g_hW[n*HG + h*G + g];
        si += v * ai[h*G + g];
        sj += v * aj[h*G + g];
    }
    for (int o = 16; o > 0; o >>= 1) {
        si += __shfl_down_sync(0xffffffffu, si, o);
        sj += __shfl_down_sync(0xffffffffu, sj, o);
    }
    if (lane == 0) { g_ci[h*NA + n] = si; g_cj[h*NA + n] = sj; }
}

// in-block bitonic sort of the 4096 cj keys (ascending); emits perm, sorted keys,
// weights and cmax. grid = H, block = 1024.
__global__ void sortk()
{
    __shared__ float key[NA];
    __shared__ int   idx[NA];
    int h = blockIdx.x;
    for (int i = threadIdx.x; i < NA; i += 1024) { key[i] = g_cj[h*NA + i]; idx[i] = i; }
    __syncthreads();
    for (int k = 2; k <= NA; k <<= 1) {
        for (int j = k >> 1; j > 0; j >>= 1) {
            for (int t = threadIdx.x; t < NA; t += 1024) {
                int ixj = t ^ j;
                if (ixj > t) {
                    bool up = ((t & k) == 0);
                    float a = key[t], b = key[ixj];
                    bool sw = up ? (a > b) : (a < b);
                    if (sw) {
                        key[t] = b; key[ixj] = a;
                        int tmp = idx[t]; idx[t] = idx[ixj]; idx[ixj] = tmp;
                    }
                }
            }
            __syncthreads();
        }
    }
    float cm = key[NA-1];
    for (int i = threadIdx.x; i < NA; i += 1024) {
        g_sidx[h*NA + i] = idx[i];
        g_cjs [h*NA + i] = key[i];
        g_wA  [h*NA + i] = expf(key[i] - cm);
        g_wB  [h*NA + i] = expf(0.2f * (key[i] - cm));
    }
    if (threadIdx.x == 0) g_cmax[h] = cm;
}

// k_i = #{ cj <= -ci } via binary search in sorted keys
__global__ void bsearchk(int H)
{
    int idx = blockIdx.x*256 + threadIdx.x;
    if (idx >= NA*H) return;
    int h = idx / NA, i = idx % NA;
    float t = -g_ci[h*NA + i];
    const float* keys = g_cjs + h*NA;
    int lo = 0, hi = NA;
    while (lo < hi) {
        int mid = (lo + hi) >> 1;
        if (keys[mid] <= t) lo = mid + 1; else hi = mid;
    }
    g_kcount[h*NA + i] = lo;
}

// hW_T[c][r] = hW[sidx_h(r)][c]  (permute to sorted order + transpose)
__global__ void permT(int G)
{
    __shared__ float tile[32][33];
    int r0 = blockIdx.x * 32, c0 = blockIdx.y * 32;
    int h = c0 / G;
    for (int rr = threadIdx.y; rr < 32; rr += 8) {
        int src = g_sidx[h*NA + r0 + rr];
        tile[rr][threadIdx.x] = g_hW[src*HG + c0 + threadIdx.x];
    }
    __syncthreads();
    for (int cc = threadIdx.y; cc < 32; cc += 8) {
        g_hWT[(size_t)(c0+cc)*NA + r0 + threadIdx.x] = tile[threadIdx.x][cc];
    }
}

// block scan: prefix of wB*x and suffix of wA*x over sorted order.
// grid = H*G (vector cols) + H (scalar cols, x=1). block = 1024, 4 elems/thread.
__global__ void scank(int H, int G)
{
    __shared__ float wsum[32];
    int b = blockIdx.x;
    bool scalar = (b >= H*G);
    int c = scalar ? 0 : b;
    int h = scalar ? (b - H*G) : (c / G);
    int tid = threadIdx.x, lane = tid & 31, warp = tid >> 5;
    int t0 = tid * 4;

    // ---- pass 1: inclusive prefix of wB*x ----
    float4 w4 = *(const float4*)&g_wB[h*NA + t0];
    float x0 = 1.f, x1 = 1.f, x2 = 1.f, x3 = 1.f;
    if (!scalar) {
        float4 xv = *(const float4*)&g_hWT[(size_t)c*NA + t0];
        x0 = xv.x; x1 = xv.y; x2 = xv.z; x3 = xv.w;
    }
    float v0 = w4.x*x0;
    float v1 = v0 + w4.y*x1;
    float v2 = v1 + w4.z*x2;
    float v3 = v2 + w4.w*x3;
    float tot = v3, s = tot;
    #pragma unroll
    for (int o = 1; o < 32; o <<= 1) { float u = __shfl_up_sync(0xffffffffu, s, o); if (lane >= o) s += u; }
    if (lane == 31) wsum[warp] = s;
    __syncthreads();
    if (warp == 0) {
        float y = wsum[lane];
        #pragma unroll
        for (int o = 1; o < 32; o <<= 1) { float u = __shfl_up_sync(0xffffffffu, y, o); if (lane >= o) y += u; }
        wsum[lane] = y;
    }
    __syncthreads();
    float off = (warp ? wsum[warp-1] : 0.f) + (s - tot);
    {
        float4 o4 = make_float4(off+v0, off+v1, off+v2, off+v3);
        if (scalar) *(float4*)&g_preB_s[h*NA + t0] = o4;
        else        *(float4*)&g_preB_v[(size_t)c*NA + t0] = o4;
    }
    __syncthreads();

    // ---- pass 2: suffix of wA*x (prefix over reversed order) ----
    int rbase = NA - 4 - t0;             // float4 at [rbase .. rbase+3]
    float4 wa = *(const float4*)&g_wA[h*NA + rbase];
    float y0 = 1.f, y1 = 1.f, y2 = 1.f, y3 = 1.f;
    if (!scalar) {
        float4 xv = *(const float4*)&g_hWT[(size_t)c*NA + rbase];
        y0 = xv.x; y1 = xv.y; y2 = xv.z; y3 = xv.w;
    }
    // reversed local order: i=0 -> r=rbase+3 (.w), i=3 -> r=rbase (.x)
    float u0 = wa.w*y3;
    float u1 = u0 + wa.z*y2;
    float u2 = u1 + wa.y*y1;
    float u3 = u2 + wa.x*y0;
    float tot2 = u3, s2 = tot2;
    #pragma unroll
    for (int o = 1; o < 32; o <<= 1) { float u = __shfl_up_sync(0xffffffffu, s2, o); if (lane >= o) s2 += u; }
    if (lane == 31) wsum[warp] = s2;
    __syncthreads();
    if (warp == 0) {
        float y = wsum[lane];
        #pragma unroll
        for (int o = 1; o < 32; o <<= 1) { float u = __shfl_up_sync(0xffffffffu, y, o); if (lane >= o) y += u; }
        wsum[lane] = y;
    }
    __syncthreads();
    float off2 = (warp ? wsum[warp-1] : 0.f) + (s2 - tot2);
    {
        // r = rbase+3 gets u0, rbase+2 -> u1, rbase+1 -> u2, rbase -> u3
        float4 o4 = make_float4(off2+u3, off2+u2, off2+u1, off2+u0);
        if (scalar) *(float4*)&g_sufA_s[h*NA + rbase] = o4;
        else        *(float4*)&g_sufA_v[(size_t)c*NA + rbase] = o4;
    }
}

// out[n, c] = (r*Av + Bv)/(r*A + B) + bias, optional elu. r = exp(0.8*(ci+cmax))
__global__ void combine(const float* __restrict__ bias, float* __restrict__ out,
                        int H, int G, int do_elu)
{
    int idx = blockIdx.x*blockDim.x + threadIdx.x;
    if (idx >= NA*HG) return;
    int gi = idx % G;
    int h  = (idx / G) % H;
    int n  = idx / HG;
    int k  = g_kcount[h*NA + n];
    float r = expf(0.8f * (g_ci[h*NA + n] + g_cmax[h]));
    float A = (k < NA) ? g_sufA_s[h*NA + k]     : 0.f;
    float B = (k > 0)  ? g_preB_s[h*NA + k - 1] : 0.f;
    size_t vb = (size_t)(h*G + gi) * NA;
    float Av = (k < NA) ? g_sufA_v[vb + k]     : 0.f;
    float Bv = (k > 0)  ? g_preB_v[vb + k - 1] : 0.f;
    float val = (r*Av + Bv) / (r*A + B);
    val += bias[h*G + gi];
    if (do_elu) val = (val > 0.f) ? val : expm1f(val);
    out[idx] = val;
}

// ---------------- heads ----------------
__global__ void valuek(const float* __restrict__ h, const float* __restrict__ comm2,
                       const float* __restrict__ Wv, const float* __restrict__ bv,
                       float* __restrict__ val)
{
    int warp = (blockIdx.x*blockDim.x + threadIdx.x) >> 5;
    int lane = threadIdx.x & 31;
    if (warp >= NA) return;
    float s = 0.f;
    for (int k = lane; k < HD; k += 32)
        s += h[warp*HD + k] * Wv[k] + comm2[warp*HD + k] * Wv[HD + k];
    for (int o = 16; o > 0; o >>= 1) s += __shfl_down_sync(0xffffffffu, s, o);
    if (lane == 0) val[warp] = s + bv[0];
}

__global__ void logsm(const float* __restrict__ logits, float* __restrict__ out)
{
    int warp = (blockIdx.x*blockDim.x + threadIdx.x) >> 5;
    int lane = threadIdx.x & 31;
    if (warp >= NA) return;
    float x0 = logits[warp*ACT + lane];
    float x1 = logits[warp*ACT + 32 + lane];
    float m = fmaxf(x0, x1);
    for (int o = 16; o > 0; o >>= 1) m = fmaxf(m, __shfl_xor_sync(0xffffffffu, m, o));
    float s = expf(x0 - m) + expf(x1 - m);
    for (int o = 16; o > 0; o >>= 1) s += __shfl_xor_sync(0xffffffffu, s, o);
    float lse = m + logf(s);
    out[warp*ACT + lane]      = x0 - lse;
    out[warp*ACT + 32 + lane] = x1 - lse;
}

__global__ void k_writeloss(float* __restrict__ dst) { dst[0] = (float)g_loss; }

// ---------------- host ----------------
extern "C" void kernel_launch(void* const* d_in, const int* in_sizes, int n_in,
                              void* d_out, int out_size)
{
    const float* obs  = (const float*)d_in[0];
    const float* h0   = (const float*)d_in[1];
    const float* c0   = (const float*)d_in[2];
    const float* Wobs = (const float*)d_in[3];
    const float* bobs = (const float*)d_in[4];
    const float* Wih  = (const float*)d_in[5];
    const float* Whh  = (const float*)d_in[6];
    const float* bih  = (const float*)d_in[7];
    const float* bhh  = (const float*)d_in[8];
    const float* W1   = (const float*)d_in[9];
    const float* ai1  = (const float*)d_in[10];
    const float* aj1  = (const float*)d_in[11];
    const float* b1   = (const float*)d_in[12];
    const float* W2   = (const float*)d_in[13];
    const float* ai2  = (const float*)d_in[14];
    const float* aj2  = (const float*)d_in[15];
    const float* b2   = (const float*)d_in[16];
    const float* Wv   = (const float*)d_in[17];
    const float* bv   = (const float*)d_in[18];
    const float* Wa   = (const float*)d_in[19];
    const float* ba   = (const float*)d_in[20];

    float* out       = (float*)d_out;
    float* out_logp  = out;
    float* out_value = out + NA*ACT;
    float* out_h     = out_value + NA;
    float* out_c     = out_h + NA*HD;
    float* out_loss  = out_c + NA*HD;

    float *p_enc, *p_gates, *p_commq, *p_hW, *p_comm1, *p_comm2, *p_logits, *p_cat, *p_Wcat, *p_bsum;
    cudaGetSymbolAddress((void**)&p_enc,    g_enc);
    cudaGetSymbolAddress((void**)&p_gates,  g_gates);
    cudaGetSymbolAddress((void**)&p_commq,  g_commq);
    cudaGetSymbolAddress((void**)&p_hW,     g_hW);
    cudaGetSymbolAddress((void**)&p_comm1,  g_comm1);
    cudaGetSymbolAddress((void**)&p_comm2,  g_comm2);
    cudaGetSymbolAddress((void**)&p_logits, g_logits);
    cudaGetSymbolAddress((void**)&p_cat,    g_cat);
    cudaGetSymbolAddress((void**)&p_Wcat,   g_Wcat);
    cudaGetSymbolAddress((void**)&p_bsum,   g_bsum);

    k_init<<<1, 1>>>();

    // 1. enc = obs @ Wobs + bobs   [4096,256] = [4096,256]@[256,256]
    gemmT<128,64,8,4><<<dim3(HD/64, NA/128), 256>>>(obs, Wobs, bobs, p_enc, NA, HD, HD, 0);
    // 2. merged LSTM gates: [enc|h0] @ [Wih;Whh]^T + (bih+bhh)
    catWk<<<2048, 256>>>(Wih, Whh, bih, bhh);
    cat2k<<<(NA*512)/256, 256>>>(p_enc, h0, p_cat);
    gemmT<128,128,8,8><<<dim3(1024/128, NA/128), 256>>>(p_cat, p_Wcat, p_bsum, p_gates, NA, 4*HD, 2*HD, 1);
    // 3. LSTM pointwise
    lstm_pw<<<(NA*HD)/256, 256>>>(p_gates, c0, out_h, out_c);
    // 4. fake quant #1
    minmax1<<<MMB, 256>>>(out_h, NA*HD);
    minmax2<<<1, MMB>>>();
    quant_loss<<<MMB, 256>>>(out_h, p_commq, NA*HD);
    // 5. GAT1 projection
    gemmT<128,64,8,4><<<dim3(HD/64, NA/128), 256>>>(p_commq, W1, nullptr, p_hW, NA, HD, HD, 0);
    // 6. GAT1 attention
    cicj<<<(NA*4*32)/256, 256>>>(ai1, aj1, 4, 64);
    sortk<<<4, 1024>>>();
    bsearchk<<<(NA*4)/256, 256>>>(4);
    permT<<<dim3(NA/32, HG/32), dim3(32,8)>>>(64);
    scank<<<4*64 + 4, 1024>>>(4, 64);
    combine<<<(NA*HG)/256, 256>>>(b1, p_comm1, 4, 64, 1);
    // 7. fake quant #2
    minmax1<<<MMB, 256>>>(p_comm1, NA*HD);
    minmax2<<<1, MMB>>>();
    quant_loss<<<MMB, 256>>>(p_comm1, p_commq, NA*HD);
    // 8. GAT2 projection
    gemmT<128,64,8,4><<<dim3(HD/64, NA/128), 256>>>(p_commq, W2, nullptr, p_hW, NA, HD, HD, 0);
    // 9. GAT2 attention
    cicj<<<(NA*1*32)/256, 256>>>(ai2, aj2, 1, 256);
    sortk<<<1, 1024>>>();
    bsearchk<<<(NA*1)/256, 256>>>(1);
    permT<<<dim3(NA/32, HG/32), dim3(32,8)>>>(256);
    scank<<<1*256 + 1, 1024>>>(1, 256);
    combine<<<(NA*HG)/256, 256>>>(b2, p_comm2, 1, 256, 0);
    // 10. value head
    valuek<<<(NA*32)/256, 256>>>(out_h, p_comm2, Wv, bv, out_value);
    // 11. policy head (merged): [h|comm2] @ Wa + ba
    cat2k<<<(NA*512)/256, 256>>>(out_h, p_comm2, p_cat);
    gemmT<64,64,4,4><<<dim3(1, NA/64), 256>>>(p_cat, Wa, ba, p_logits, NA, ACT, 2*HD, 0);
    logsm<<<(NA*32)/256, 256>>>(p_logits, out_logp);
    // 12. loss
    k_writeloss<<<1, 1>>>(out_loss);
}

// round 4
// speedup vs baseline: 3.1915x; 1.1847x over previous
#include <cuda_runtime.h>
#include <cuda_bf16.h>
#include <math.h>
#include <stdint.h>

#define NA   4096
#define HD   256
#define HG   256
#define ACT  64
#define MMB  1024

// ---------------- device scratch ----------------
__device__ float g_enc[NA*HD];
__device__ float g_gates[NA*4*HD];
__device__ float g_commq[NA*HD];
__device__ float g_hW[NA*HG];
__device__ float g_hWT[HG*NA];
__device__ float g_comm1[NA*HD];
__device__ float g_comm2[NA*HD];
__device__ float g_logits[NA*ACT];
__device__ float g_cat[NA*2*HD];
__device__ float g_bsum[4*HD];
__device__ __nv_bfloat16 g_Ah[NA*512];
__device__ __nv_bfloat16 g_Al[NA*512];
__device__ __nv_bfloat16 g_Bh[1024*512];
__device__ __nv_bfloat16 g_Bl[1024*512];
__device__ float g_ci[4*NA];
__device__ float g_cj[4*NA];
__device__ float g_cjs[4*NA];
__device__ float g_cmax[4];
__device__ int   g_kcount[4*NA];
__device__ int   g_sidx[4*NA];
__device__ float g_wA[4*NA];
__device__ float g_wB[4*NA];
__device__ float g_sufA_s[4*NA];
__device__ float g_preB_s[4*NA];
__device__ float g_sufA_v[HG*NA];
__device__ float g_preB_v[HG*NA];
__device__ float g_pmin[MMB];
__device__ float g_pmax[MMB];
__device__ float g_qparam[2];
__device__ double g_loss;

__global__ void k_init() { g_loss = 0.0; }

// ---------------- mma.sync helpers (arch-portable tensor cores) ----------------
__device__ __forceinline__ uint32_t cvta_sm(const void* p) {
    uint32_t a;
    asm("{ .reg .u64 t; cvta.to.shared.u64 t, %1; cvt.u32.u64 %0, t; }" : "=r"(a) : "l"(p));
    return a;
}
__device__ __forceinline__ void ldm_x4(uint32_t (&d)[4], uint32_t addr) {
    asm volatile("ldmatrix.sync.aligned.m8n8.x4.shared.b16 {%0,%1,%2,%3}, [%4];"
        : "=r"(d[0]), "=r"(d[1]), "=r"(d[2]), "=r"(d[3]) : "r"(addr));
}
__device__ __forceinline__ void mma16816(float (&c)[4], const uint32_t (&a)[4],
                                         uint32_t b0, uint32_t b1) {
    asm volatile("mma.sync.aligned.m16n8k16.row.col.f32.bf16.bf16.f32 "
        "{%0,%1,%2,%3},{%4,%5,%6,%7},{%8,%9},{%0,%1,%2,%3};"
        : "+f"(c[0]), "+f"(c[1]), "+f"(c[2]), "+f"(c[3])
        : "r"(a[0]), "r"(a[1]), "r"(a[2]), "r"(a[3]), "r"(b0), "r"(b1));
}

// ---------------- split-bf16 tensor GEMM: D[M,N] = A[M,K]@B[N,K]^T (+bias) ----
// CTA 128x128, 8 warps (4x2), warp tile 32x64, BK=32 bf16. 3 passes: AhBh+AhBl+AlBh.
#define TG_STRIDE 40     // bf16 row stride in SMEM (pad 32 -> 40; ldmatrix conflict-free)
#define TG_ARR    5120   // 128 * 40 bf16 per array

__global__ void __launch_bounds__(256)
tgemm(const __nv_bfloat16* __restrict__ Ah, const __nv_bfloat16* __restrict__ Al,
      const __nv_bfloat16* __restrict__ Bh, const __nv_bfloat16* __restrict__ Bl,
      const float* __restrict__ bias, float* __restrict__ C, int N, int K)
{
    __shared__ __nv_bfloat16 sm[4*TG_ARR];   // Ah | Al | Bh | Bl
    int tid = threadIdx.x, lane = tid & 31, wid = tid >> 5;
    int row0 = blockIdx.y * 128, col0 = blockIdx.x * 128;
    int wm = (wid & 3) * 32, wn = (wid >> 2) * 64;
    uint32_t sb = cvta_sm(sm);

    float acc[2][8][4] = {};

    for (int k0 = 0; k0 < K; k0 += 32) {
        // cooperative load: 4 arrays x 128 rows x 4 uint4 (32 bf16/row)
        #pragma unroll
        for (int arr = 0; arr < 4; arr++) {
            const __nv_bfloat16* src = (arr == 0) ? Ah : (arr == 1) ? Al : (arr == 2) ? Bh : Bl;
            int rbase = (arr < 2) ? row0 : col0;
            __nv_bfloat16* dst = sm + arr * TG_ARR;
            #pragma unroll
            for (int l = 0; l < 2; l++) {
                int i = tid + l * 256;
                int r = i >> 2, c8 = i & 3;
                uint4 v = *(const uint4*)(src + (size_t)(rbase + r) * K + k0 + c8 * 8);
                *(uint4*)(dst + r * TG_STRIDE + c8 * 8) = v;
            }
        }
        __syncthreads();

        #pragma unroll
        for (int kk = 0; kk < 32; kk += 16) {
            uint32_t ah[2][4], al[2][4];
            #pragma unroll
            for (int mb = 0; mb < 2; mb++) {
                int r = wm + mb * 16 + (lane & 15);
                int c = kk + (lane >> 4) * 8;
                uint32_t off = (uint32_t)(r * TG_STRIDE + c) * 2;
                ldm_x4(ah[mb], sb + 0 * (TG_ARR*2) + off);
                ldm_x4(al[mb], sb + 1 * (TG_ARR*2) + off);
            }
            #pragma unroll
            for (int nb = 0; nb < 4; nb++) {
                int r = wn + nb * 16 + ((lane >> 4) << 3) + (lane & 7);
                int c = kk + ((lane >> 3) & 1) * 8;
                uint32_t off = (uint32_t)(r * TG_STRIDE + c) * 2;
                uint32_t bh[4], bl[4];
                ldm_x4(bh, sb + 2 * (TG_ARR*2) + off);
                ldm_x4(bl, sb + 3 * (TG_ARR*2) + off);
                #pragma unroll
                for (int mb = 0; mb < 2; mb++) {
                    mma16816(acc[mb][2*nb+0], ah[mb], bh[0], bh[1]);
                    mma16816(acc[mb][2*nb+1], ah[mb], bh[2], bh[3]);
                    mma16816(acc[mb][2*nb+0], ah[mb], bl[0], bl[1]);
                    mma16816(acc[mb][2*nb+1], ah[mb], bl[2], bl[3]);
                    mma16816(acc[mb][2*nb+0], al[mb], bh[0], bh[1]);
                    mma16816(acc[mb][2*nb+1], al[mb], bh[2], bh[3]);
                }
            }
        }
        __syncthreads();
    }

    // epilogue: c fragment layout m16n8 -> (g,2tg),(g,2tg+1),(g+8,2tg),(g+8,2tg+1)
    int g = lane >> 2, tg = lane & 3;
    #pragma unroll
    for (int mb = 0; mb < 2; mb++) {
        #pragma unroll
        for (int n8 = 0; n8 < 8; n8++) {
            int row = row0 + wm + mb * 16 + g;
            int col = col0 + wn + n8 * 8 + 2 * tg;
            float b0 = bias ? bias[col]   : 0.f;
            float b1 = bias ? bias[col+1] : 0.f;
            float2 v0 = make_float2(acc[mb][n8][0] + b0, acc[mb][n8][1] + b1);
            float2 v1 = make_float2(acc[mb][n8][2] + b0, acc[mb][n8][3] + b1);
            *(float2*)(C + (size_t)row * N + col)       = v0;
            *(float2*)(C + (size_t)(row + 8) * N + col) = v1;
        }
    }
}

// ---------------- split / conversion kernels ----------------
__global__ void split_plain(const float* __restrict__ src,
                            __nv_bfloat16* __restrict__ hi, __nv_bfloat16* __restrict__ lo, int n)
{
    int i = blockIdx.x*256 + threadIdx.x;
    if (i >= n) return;
    float x = src[i];
    __nv_bfloat16 h = __float2bfloat16(x);
    hi[i] = h;
    lo[i] = __float2bfloat16(x - __bfloat162float(h));
}

__global__ void split_cat(const float* __restrict__ A0, const float* __restrict__ A1,
                          __nv_bfloat16* __restrict__ hi, __nv_bfloat16* __restrict__ lo)
{
    int i = blockIdx.x*256 + threadIdx.x;   // over NA*512
    int n = i >> 9, k = i & 511;
    float x = (k < 256) ? A0[n*256 + k] : A1[n*256 + k - 256];
    __nv_bfloat16 h = __float2bfloat16(x);
    hi[i] = h;
    lo[i] = __float2bfloat16(x - __bfloat162float(h));
}

__global__ void split_Wg(const float* __restrict__ Wih, const float* __restrict__ Whh,
                         __nv_bfloat16* __restrict__ hi, __nv_bfloat16* __restrict__ lo)
{
    int i = blockIdx.x*256 + threadIdx.x;   // over 1024*512
    int r = i >> 9, k = i & 511;
    float x = (k < 256) ? Wih[r*256 + k] : Whh[r*256 + k - 256];
    __nv_bfloat16 h = __float2bfloat16(x);
    hi[i] = h;
    lo[i] = __float2bfloat16(x - __bfloat162float(h));
}

// B[n,k] = W[k*256 + n]  (transpose 256x256)
__global__ void split_WT(const float* __restrict__ W,
                         __nv_bfloat16* __restrict__ hi, __nv_bfloat16* __restrict__ lo)
{
    int i = blockIdx.x*256 + threadIdx.x;   // over 256*256
    int n = i >> 8, k = i & 255;
    float x = W[k*256 + n];
    __nv_bfloat16 h = __float2bfloat16(x);
    hi[i] = h;
    lo[i] = __float2bfloat16(x - __bfloat162float(h));
}

__global__ void k_bsum(const float* __restrict__ bih, const float* __restrict__ bhh)
{
    int i = blockIdx.x*256 + threadIdx.x;
    if (i < 1024) g_bsum[i] = bih[i] + bhh[i];
}

__global__ void cat2k(const float* __restrict__ A0, const float* __restrict__ A1,
                      float* __restrict__ dst)
{
    int idx = blockIdx.x*256 + threadIdx.x;
    int n = idx >> 9, k = idx & 511;
    dst[idx] = (k < 256) ? A0[n*256 + k] : A1[n*256 + k - 256];
}

// ---------------- SIMT GEMM (policy head only) ----------------
template<int BM, int BN, int TM, int TN>
__global__ void __launch_bounds__(256, 2)
gemmT(const float* __restrict__ A, const float* __restrict__ B,
      const float* __restrict__ bias, float* __restrict__ C,
      int M, int N, int K, int transB)
{
    const int BK = 16;
    __shared__ float As[BK][BM+4];
    __shared__ float Bs[BK][BN+4];
    int tid = threadIdx.x;
    int tx = tid % (BN/TN);
    int ty = tid / (BN/TN);
    int row0 = blockIdx.y * BM, col0 = blockIdx.x * BN;
    float acc[TM][TN] = {};
    for (int k0 = 0; k0 < K; k0 += BK) {
        #pragma unroll
        for (int p = 0; p < (BM*BK)/1024; p++) {
            int lin = (p*256 + tid) * 4;
            int m = lin / BK, kk = lin % BK;
            float4 v = *(const float4*)&A[(size_t)(row0+m)*K + k0 + kk];
            As[kk+0][m] = v.x; As[kk+1][m] = v.y; As[kk+2][m] = v.z; As[kk+3][m] = v.w;
        }
        if (!transB) {
            #pragma unroll
            for (int p = 0; p < (BN*BK)/1024; p++) {
                int lin = (p*256 + tid) * 4;
                int kk = lin / BN, n = lin % BN;
                *(float4*)&Bs[kk][n] = *(const float4*)&B[(size_t)(k0+kk)*N + col0 + n];
            }
        } else {
            #pragma unroll
            for (int p = 0; p < (BN*BK)/1024; p++) {
                int lin = (p*256 + tid) * 4;
                int n = lin / BK, kk = lin % BK;
                float4 v = *(const float4*)&B[(size_t)(col0+n)*K + k0 + kk];
                Bs[kk+0][n] = v.x; Bs[kk+1][n] = v.y; Bs[kk+2][n] = v.z; Bs[kk+3][n] = v.w;
            }
        }
        __syncthreads();
        #pragma unroll
        for (int kk = 0; kk < BK; kk++) {
            float a[TM], bb[TN];
            #pragma unroll
            for (int i = 0; i < TM; i++) a[i] = As[kk][ty*TM+i];
            #pragma unroll
            for (int j = 0; j < TN; j++) bb[j] = Bs[kk][tx*TN+j];
            #pragma unroll
            for (int i = 0; i < TM; i++)
                #pragma unroll
                for (int j = 0; j < TN; j++)
                    acc[i][j] = fmaf(a[i], bb[j], acc[i][j]);
        }
        __syncthreads();
    }
    #pragma unroll
    for (int i = 0; i < TM; i++) {
        int m = row0 + ty*TM + i;
        #pragma unroll
        for (int j = 0; j < TN; j++) {
            int n = col0 + tx*TN + j;
            float v = acc[i][j];
            if (bias) v += bias[n];
            C[(size_t)m*N + n] = v;
        }
    }
}

// ---------------- LSTM pointwise ----------------
__global__ void lstm_pw(const float* __restrict__ gates, const float* __restrict__ c0,
                        float* __restrict__ h, float* __restrict__ c)
{
    int idx = blockIdx.x * blockDim.x + threadIdx.x;
    if (idx >= NA*HD) return;
    int n = idx / HD, k = idx % HD;
    const float* gr = gates + n * (4*HD);
    float ig = gr[k], fg = gr[HD+k], gg = gr[2*HD+k], og = gr[3*HD+k];
    float si = 1.f/(1.f+expf(-ig));
    float sf = 1.f/(1.f+expf(-fg));
    float so = 1.f/(1.f+expf(-og));
    float c2 = sf * c0[idx] + si * tanhf(gg);
    h[idx] = so * tanhf(c2);
    c[idx] = c2;
}

// ---------------- fake quant ----------------
__global__ void minmax1(const float* __restrict__ x, int n)
{
    __shared__ float smn[256], smx[256];
    float mn = 1e30f, mx = -1e30f;
    for (int i = blockIdx.x*256 + threadIdx.x; i < n; i += gridDim.x*256) {
        float v = x[i]; mn = fminf(mn, v); mx = fmaxf(mx, v);
    }
    smn[threadIdx.x] = mn; smx[threadIdx.x] = mx; __syncthreads();
    for (int s = 128; s > 0; s >>= 1) {
        if (threadIdx.x < s) {
            smn[threadIdx.x] = fminf(smn[threadIdx.x], smn[threadIdx.x+s]);
            smx[threadIdx.x] = fmaxf(smx[threadIdx.x], smx[threadIdx.x+s]);
        }
        __syncthreads();
    }
    if (threadIdx.x == 0) { g_pmin[blockIdx.x] = smn[0]; g_pmax[blockIdx.x] = smx[0]; }
}

__global__ void minmax2()
{
    __shared__ float smn[MMB], smx[MMB];
    int t = threadIdx.x;
    smn[t] = g_pmin[t]; smx[t] = g_pmax[t];
    __syncthreads();
    for (int s = MMB/2; s > 0; s >>= 1) {
        if (t < s) { smn[t] = fminf(smn[t], smn[t+s]); smx[t] = fmaxf(smx[t], smx[t+s]); }
        __syncthreads();
    }
    if (t == 0) {
        float mn = smn[0], mx = smx[0];
        if (mn == mx) { mn -= 0.01f; mx += 0.01f; }
        float scale = (mx - mn) / 255.f;
        g_qparam[0] = scale;
        g_qparam[1] = rintf(-mn / scale);
    }
}

__global__ void quant_loss(const float* __restrict__ x, float* __restrict__ q, int n)
{
    float scale = g_qparam[0], zp = g_qparam[1];
    double part = 0.0;
    for (int i = blockIdx.x*blockDim.x + threadIdx.x; i < n; i += gridDim.x*blockDim.x) {
        float t = x[i];
        float r = rintf(t/scale + zp);
        r = fminf(fmaxf(r, 0.f), 255.f);
        float d = (r - zp) * scale;
        q[i] = d;
        part += (double)log2f(510.f * fabsf(d) + 1.f);
    }
    __shared__ double sd[256];
    sd[threadIdx.x] = part; __syncthreads();
    for (int s = 128; s > 0; s >>= 1) { if (threadIdx.x < s) sd[threadIdx.x] += sd[threadIdx.x+s]; __syncthreads(); }
    if (threadIdx.x == 0) atomicAdd(&g_loss, sd[0]);
}

// ---------------- GAT attention (separable exact softmax) ----------------
__global__ void cicj(const float* __restrict__ ai, const float* __restrict__ aj, int H, int G)
{
    int warp = (blockIdx.x*blockDim.x + threadIdx.x) >> 5;
    int lane = threadIdx.x & 31;
    if (warp >= NA * H) return;
    int n = warp / H, h = warp % H;
    float si = 0.f, sj = 0.f;
    for (int g = lane; g < G; g += 32) {
        float v = g_hW[n*HG + h*G + g];
        si += v * ai[h*G + g];
        sj += v * aj[h*G + g];
    }
    for (int o = 16; o > 0; o >>= 1) {
        si += __shfl_down_sync(0xffffffffu, si, o);
        sj += __shfl_down_sync(0xffffffffu, sj, o);
    }
    if (lane == 0) { g_ci[h*NA + n] = si; g_cj[h*NA + n] = sj; }
}

__global__ void sortk()
{
    __shared__ float key[NA];
    __shared__ int   idx[NA];
    int h = blockIdx.x;
    for (int i = threadIdx.x; i < NA; i += 1024) { key[i] = g_cj[h*NA + i]; idx[i] = i; }
    __syncthreads();
    for (int k = 2; k <= NA; k <<= 1) {
        for (int j = k >> 1; j > 0; j >>= 1) {
            for (int t = threadIdx.x; t < NA; t += 1024) {
                int ixj = t ^ j;
                if (ixj > t) {
                    bool up = ((t & k) == 0);
                    float a = key[t], b = key[ixj];
                    bool sw = up ? (a > b) : (a < b);
                    if (sw) {
                        key[t] = b; key[ixj] = a;
                        int tmp = idx[t]; idx[t] = idx[ixj]; idx[ixj] = tmp;
                    }
                }
            }
            __syncthreads();
        }
    }
    float cm = key[NA-1];
    for (int i = threadIdx.x; i < NA; i += 1024) {
        g_sidx[h*NA + i] = idx[i];
        g_cjs [h*NA + i] = key[i];
        g_wA  [h*NA + i] = expf(key[i] - cm);
        g_wB  [h*NA + i] = expf(0.2f * (key[i] - cm));
    }
    if (threadIdx.x == 0) g_cmax[h] = cm;
}

__global__ void bsearchk(int H)
{
    int idx = blockIdx.x*256 + threadIdx.x;
    if (idx >= NA*H) return;
    int h = idx / NA, i = idx % NA;
    float t = -g_ci[h*NA + i];
    const float* keys = g_cjs + h*NA;
    int lo = 0, hi = NA;
    while (lo < hi) {
        int mid = (lo + hi) >> 1;
        if (keys[mid] <= t) lo = mid + 1; else hi = mid;
    }
    g_kcount[h*NA + i] = lo;
}

__global__ void permT(int G)
{
    __shared__ float tile[32][33];
    int r0 = blockIdx.x * 32, c0 = blockIdx.y * 32;
    int h = c0 / G;
    for (int rr = threadIdx.y; rr < 32; rr += 8) {
        int src = g_sidx[h*NA + r0 + rr];
        tile[rr][threadIdx.x] = g_hW[src*HG + c0 + threadIdx.x];
    }
    __syncthreads();
    for (int cc = threadIdx.y; cc < 32; cc += 8) {
        g_hWT[(size_t)(c0+cc)*NA + r0 + threadIdx.x] = tile[threadIdx.x][cc];
    }
}

__global__ void scank(int H, int G)
{
    __shared__ float wsum[32];
    int b = blockIdx.x;
    bool scalar = (b >= H*G);
    int c = scalar ? 0 : b;
    int h = scalar ? (b - H*G) : (c / G);
    int tid = threadIdx.x, lane = tid & 31, warp = tid >> 5;
    int t0 = tid * 4;

    float4 w4 = *(const float4*)&g_wB[h*NA + t0];
    float x0 = 1.f, x1 = 1.f, x2 = 1.f, x3 = 1.f;
    if (!scalar) {
        float4 xv = *(const float4*)&g_hWT[(size_t)c*NA + t0];
        x0 = xv.x; x1 = xv.y; x2 = xv.z; x3 = xv.w;
    }
    float v0 = w4.x*x0;
    float v1 = v0 + w4.y*x1;
    float v2 = v1 + w4.z*x2;
    float v3 = v2 + w4.w*x3;
    float tot = v3, s = tot;
    #pragma unroll
    for (int o = 1; o < 32; o <<= 1) { float u = __shfl_up_sync(0xffffffffu, s, o); if (lane >= o) s += u; }
    if (lane == 31) wsum[warp] = s;
    __syncthreads();
    if (warp == 0) {
        float y = wsum[lane];
        #pragma unroll
        for (int o = 1; o < 32; o <<= 1) { float u = __shfl_up_sync(0xffffffffu, y, o); if (lane >= o) y += u; }
        wsum[lane] = y;
    }
    __syncthreads();
    float off = (warp ? wsum[warp-1] : 0.f) + (s - tot);
    {
        float4 o4 = make_float4(off+v0, off+v1, off+v2, off+v3);
        if (scalar) *(float4*)&g_preB_s[h*NA + t0] = o4;
        else        *(float4*)&g_preB_v[(size_t)c*NA + t0] = o4;
    }
    __syncthreads();

    int rbase = NA - 4 - t0;
    float4 wa = *(const float4*)&g_wA[h*NA + rbase];
    float y0 = 1.f, y1 = 1.f, y2 = 1.f, y3 = 1.f;
    if (!scalar) {
        float4 xv = *(const float4*)&g_hWT[(size_t)c*NA + rbase];
        y0 = xv.x; y1 = xv.y; y2 = xv.z; y3 = xv.w;
    }
    float u0 = wa.w*y3;
    float u1 = u0 + wa.z*y2;
    float u2 = u1 + wa.y*y1;
    float u3 = u2 + wa.x*y0;
    float tot2 = u3, s2 = tot2;
    #pragma unroll
    for (int o = 1; o < 32; o <<= 1) { float u = __shfl_up_sync(0xffffffffu, s2, o); if (lane >= o) s2 += u; }
    if (lane == 31) wsum[warp] = s2;
    __syncthreads();
    if (warp == 0) {
        float y = wsum[lane];
        #pragma unroll
        for (int o = 1; o < 32; o <<= 1) { float u = __shfl_up_sync(0xffffffffu, y, o); if (lane >= o) y += u; }
        wsum[lane] = y;
    }
    __syncthreads();
    float off2 = (warp ? wsum[warp-1] : 0.f) + (s2 - tot2);
    {
        float4 o4 = make_float4(off2+u3, off2+u2, off2+u1, off2+u0);
        if (scalar) *(float4*)&g_sufA_s[h*NA + rbase] = o4;
        else        *(float4*)&g_sufA_v[(size_t)c*NA + rbase] = o4;
    }
}

__global__ void combine(const float* __restrict__ bias, float* __restrict__ out,
                        int H, int G, int do_elu)
{
    int idx = blockIdx.x*blockDim.x + threadIdx.x;
    if (idx >= NA*HG) return;
    int gi = idx % G;
    int h  = (idx / G) % H;
    int n  = idx / HG;
    int k  = g_kcount[h*NA + n];
    float r = expf(0.8f * (g_ci[h*NA + n] + g_cmax[h]));
    float A = (k < NA) ? g_sufA_s[h*NA + k]     : 0.f;
    float B = (k > 0)  ? g_preB_s[h*NA + k - 1] : 0.f;
    size_t vb = (size_t)(h*G + gi) * NA;
    float Av = (k < NA) ? g_sufA_v[vb + k]     : 0.f;
    float Bv = (k > 0)  ? g_preB_v[vb + k - 1] : 0.f;
    float val = (r*Av + Bv) / (r*A + B);
    val += bias[h*G + gi];
    if (do_elu) val = (val > 0.f) ? val : expm1f(val);
    out[idx] = val;
}

// ---------------- heads ----------------
__global__ void valuek(const float* __restrict__ h, const float* __restrict__ comm2,
                       const float* __restrict__ Wv, const float* __restrict__ bv,
                       float* __restrict__ val)
{
    int warp = (blockIdx.x*blockDim.x + threadIdx.x) >> 5;
    int lane = threadIdx.x & 31;
    if (warp >= NA) return;
    float s = 0.f;
    for (int k = lane; k < HD; k += 32)
        s += h[warp*HD + k] * Wv[k] + comm2[warp*HD + k] * Wv[HD + k];
    for (int o = 16; o > 0; o >>= 1) s += __shfl_down_sync(0xffffffffu, s, o);
    if (lane == 0) val[warp] = s + bv[0];
}

__global__ void logsm(const float* __restrict__ logits, float* __restrict__ out)
{
    int warp = (blockIdx.x*blockDim.x + threadIdx.x) >> 5;
    int lane = threadIdx.x & 31;
    if (warp >= NA) return;
    float x0 = logits[warp*ACT + lane];
    float x1 = logits[warp*ACT + 32 + lane];
    float m = fmaxf(x0, x1);
    for (int o = 16; o > 0; o >>= 1) m = fmaxf(m, __shfl_xor_sync(0xffffffffu, m, o));
    float s = expf(x0 - m) + expf(x1 - m);
    for (int o = 16; o > 0; o >>= 1) s += __shfl_xor_sync(0xffffffffu, s, o);
    float lse = m + logf(s);
    out[warp*ACT + lane]      = x0 - lse;
    out[warp*ACT + 32 + lane] = x1 - lse;
}

__global__ void k_writeloss(float* __restrict__ dst) { dst[0] = (float)g_loss; }

// ---------------- host ----------------
extern "C" void kernel_launch(void* const* d_in, const int* in_sizes, int n_in,
                              void* d_out, int out_size)
{
    const float* obs  = (const float*)d_in[0];
    const float* h0   = (const float*)d_in[1];
    const float* c0   = (const float*)d_in[2];
    const float* Wobs = (const float*)d_in[3];
    const float* bobs = (const float*)d_in[4];
    const float* Wih  = (const float*)d_in[5];
    const float* Whh  = (const float*)d_in[6];
    const float* bih  = (const float*)d_in[7];
    const float* bhh  = (const float*)d_in[8];
    const float* W1   = (const float*)d_in[9];
    const float* ai1  = (const float*)d_in[10];
    const float* aj1  = (const float*)d_in[11];
    const float* b1   = (const float*)d_in[12];
    const float* W2   = (const float*)d_in[13];
    const float* ai2  = (const float*)d_in[14];
    const float* aj2  = (const float*)d_in[15];
    const float* b2   = (const float*)d_in[16];
    const float* Wv   = (const float*)d_in[17];
    const float* bv   = (const float*)d_in[18];
    const float* Wa   = (const float*)d_in[19];
    const float* ba   = (const float*)d_in[20];

    float* out       = (float*)d_out;
    float* out_logp  = out;
    float* out_value = out + NA*ACT;
    float* out_h     = out_value + NA;
    float* out_c     = out_h + NA*HD;
    float* out_loss  = out_c + NA*HD;

    float *p_enc, *p_gates, *p_commq, *p_hW, *p_comm1, *p_comm2, *p_logits, *p_cat, *p_bsum;
    __nv_bfloat16 *p_Ah, *p_Al, *p_Bh, *p_Bl;
    cudaGetSymbolAddress((void**)&p_enc,    g_enc);
    cudaGetSymbolAddress((void**)&p_gates,  g_gates);
    cudaGetSymbolAddress((void**)&p_commq,  g_commq);
    cudaGetSymbolAddress((void**)&p_hW,     g_hW);
    cudaGetSymbolAddress((void**)&p_comm1,  g_comm1);
    cudaGetSymbolAddress((void**)&p_comm2,  g_comm2);
    cudaGetSymbolAddress((void**)&p_logits, g_logits);
    cudaGetSymbolAddress((void**)&p_cat,    g_cat);
    cudaGetSymbolAddress((void**)&p_bsum,   g_bsum);
    cudaGetSymbolAddress((void**)&p_Ah,     g_Ah);
    cudaGetSymbolAddress((void**)&p_Al,     g_Al);
    cudaGetSymbolAddress((void**)&p_Bh,     g_Bh);
    cudaGetSymbolAddress((void**)&p_Bl,     g_Bl);

    k_init<<<1, 1>>>();

    // 1. enc = obs @ Wobs + bobs  (tensor, split-bf16)
    split_plain<<<(NA*256)/256, 256>>>(obs, p_Ah, p_Al, NA*256);
    split_WT<<<(256*256)/256, 256>>>(Wobs, p_Bh, p_Bl);
    tgemm<<<dim3(2, 32), 256>>>(p_Ah, p_Al, p_Bh, p_Bl, bobs, p_enc, 256, 256);
    // 2. gates = [enc|h0] @ [Wih;Whh]^T + (bih+bhh)
    k_bsum<<<4, 256>>>(bih, bhh);
    split_cat<<<(NA*512)/256, 256>>>(p_enc, h0, p_Ah, p_Al);
    split_Wg<<<(1024*512)/256, 256>>>(Wih, Whh, p_Bh, p_Bl);
    tgemm<<<dim3(8, 32), 256>>>(p_Ah, p_Al, p_Bh, p_Bl, p_bsum, p_gates, 1024, 512);
    // 3. LSTM pointwise
    lstm_pw<<<(NA*HD)/256, 256>>>(p_gates, c0, out_h, out_c);
    // 4. fake quant #1
    minmax1<<<MMB, 256>>>(out_h, NA*HD);
    minmax2<<<1, MMB>>>();
    quant_loss<<<MMB, 256>>>(out_h, p_commq, NA*HD);
    // 5. GAT1 projection (tensor)
    split_plain<<<(NA*256)/256, 256>>>(p_commq, p_Ah, p_Al, NA*256);
    split_WT<<<(256*256)/256, 256>>>(W1, p_Bh, p_Bl);
    tgemm<<<dim3(2, 32), 256>>>(p_Ah, p_Al, p_Bh, p_Bl, nullptr, p_hW, 256, 256);
    // 6. GAT1 attention
    cicj<<<(NA*4*32)/256, 256>>>(ai1, aj1, 4, 64);
    sortk<<<4, 1024>>>();
    bsearchk<<<(NA*4)/256, 256>>>(4);
    permT<<<dim3(NA/32, HG/32), dim3(32,8)>>>(64);
    scank<<<4*64 + 4, 1024>>>(4, 64);
    combine<<<(NA*HG)/256, 256>>>(b1, p_comm1, 4, 64, 1);
    // 7. fake quant #2
    minmax1<<<MMB, 256>>>(p_comm1, NA*HD);
    minmax2<<<1, MMB>>>();
    quant_loss<<<MMB, 256>>>(p_comm1, p_commq, NA*HD);
    // 8. GAT2 projection (tensor)
    split_plain<<<(NA*256)/256, 256>>>(p_commq, p_Ah, p_Al, NA*256);
    split_WT<<<(256*256)/256, 256>>>(W2, p_Bh, p_Bl);
    tgemm<<<dim3(2, 32), 256>>>(p_Ah, p_Al, p_Bh, p_Bl, nullptr, p_hW, 256, 256);
    // 9. GAT2 attention
    cicj<<<(NA*1*32)/256, 256>>>(ai2, aj2, 1, 256);
    sortk<<<1, 1024>>>();
    bsearchk<<<(NA*1)/256, 256>>>(1);
    permT<<<dim3(NA/32, HG/32), dim3(32,8)>>>(256);
    scank<<<1*256 + 1, 1024>>>(1, 256);
    combine<<<(NA*HG)/256, 256>>>(b2, p_comm2, 1, 256, 0);
    // 10. value head
    valuek<<<(NA*32)/256, 256>>>(out_h, p_comm2, Wv, bv, out_value);
    // 11. policy head (merged): [h|comm2] @ Wa + ba (SIMT; tiny)
    cat2k<<<(NA*512)/256, 256>>>(out_h, p_comm2, p_cat);
    gemmT<64,64,4,4><<<dim3(1, NA/64), 256>>>(p_cat, Wa, ba, p_logits, NA, ACT, 2*HD, 0);
    logsm<<<(NA*32)/256, 256>>>(p_logits, out_logp);
    // 12. loss
    k_writeloss<<<1, 1>>>(out_loss);
}

// round 5
// speedup vs baseline: 3.2128x; 1.0067x over previous
#include <cuda_runtime.h>
#include <cuda_bf16.h>
#include <math.h>
#include <stdint.h>

#define NA   4096
#define HD   256
#define HG   256
#define ACT  64
#define MMB  1024

// ---------------- device scratch ----------------
__device__ float g_gates[NA*4*HD];
__device__ float g_hW[NA*HG];
__device__ float g_hWT[HG*NA];
__device__ float g_comm1[NA*HD];
__device__ float g_comm2[NA*HD];
__device__ float g_bsum[4*HD];
__device__ __nv_bfloat16 g_Ah[NA*512];      // gates A (ld 512) then GAT A (ld 256)
__device__ __nv_bfloat16 g_Al[NA*512];
__device__ __nv_bfloat16 g_A2h[NA*256];     // obs split
__device__ __nv_bfloat16 g_A2l[NA*256];
__device__ __nv_bfloat16 g_B0h[256*256], g_B0l[256*256];    // Wobs^T
__device__ __nv_bfloat16 g_Bgh[1024*512], g_Bgl[1024*512];  // [Wih;Whh]
__device__ __nv_bfloat16 g_B1h[256*256], g_B1l[256*256];    // W1^T
__device__ __nv_bfloat16 g_B2h[256*256], g_B2l[256*256];    // W2^T
__device__ float g_ci[4*NA];
__device__ float g_cj[4*NA];
__device__ float g_cmax[4];
__device__ int   g_kcount[4*NA];
__device__ int   g_sidx[4*NA];
__device__ float g_wA[4*NA];
__device__ float g_wB[4*NA];
__device__ float g_sufA_s[4*NA];
__device__ float g_preB_s[4*NA];
__device__ float g_sufA_v[HG*NA];
__device__ float g_preB_v[HG*NA];
__device__ float g_pmin[MMB];
__device__ float g_pmax[MMB];
__device__ float g_qparam[2];
__device__ double g_loss;

__global__ void k_init() { g_loss = 0.0; }

__device__ __forceinline__ void bf16split(float x, __nv_bfloat16* hi, __nv_bfloat16* lo) {
    __nv_bfloat16 h = __float2bfloat16(x);
    *hi = h;
    *lo = __float2bfloat16(x - __bfloat162float(h));
}

// ---------------- fused weight/input prep (one launch) ----------------
#define WP_S0 (NA*256)             // obs
#define WP_S1 (WP_S0 + NA*256)     // h0 -> g_Ah cols 256..511
#define WP_S2 (WP_S1 + 65536)      // Wobs^T
#define WP_S3 (WP_S2 + 524288)     // [Wih;Whh]
#define WP_S4 (WP_S3 + 65536)      // W1^T
#define WP_S5 (WP_S4 + 65536)      // W2^T
#define WP_S6 (WP_S5 + 1024)       // bsum
__global__ void wprep(const float* __restrict__ obs, const float* __restrict__ h0,
                      const float* __restrict__ Wobs,
                      const float* __restrict__ Wih, const float* __restrict__ Whh,
                      const float* __restrict__ W1, const float* __restrict__ W2,
                      const float* __restrict__ bih, const float* __restrict__ bhh)
{
    int idx = blockIdx.x*256 + threadIdx.x;
    if (idx < WP_S0) {
        bf16split(obs[idx], &g_A2h[idx], &g_A2l[idx]);
    } else if (idx < WP_S1) {
        int j = idx - WP_S0;
        int n = j >> 8, k = j & 255;
        int d = n*512 + 256 + k;
        bf16split(h0[j], &g_Ah[d], &g_Al[d]);
    } else if (idx < WP_S2) {
        int j = idx - WP_S1;
        int n = j >> 8, k = j & 255;
        bf16split(Wobs[k*256 + n], &g_B0h[j], &g_B0l[j]);
    } else if (idx < WP_S3) {
        int j = idx - WP_S2;
        int r = j >> 9, k = j & 511;
        float x = (k < 256) ? Wih[r*256 + k] : Whh[r*256 + k - 256];
        bf16split(x, &g_Bgh[j], &g_Bgl[j]);
    } else if (idx < WP_S4) {
        int j = idx - WP_S3;
        int n = j >> 8, k = j & 255;
        bf16split(W1[k*256 + n], &g_B1h[j], &g_B1l[j]);
    } else if (idx < WP_S5) {
        int j = idx - WP_S4;
        int n = j >> 8, k = j & 255;
        bf16split(W2[k*256 + n], &g_B2h[j], &g_B2l[j]);
    } else if (idx < WP_S6) {
        int j = idx - WP_S5;
        g_bsum[j] = bih[j] + bhh[j];
    }
}

// ---------------- mma.sync helpers ----------------
__device__ __forceinline__ uint32_t cvta_sm(const void* p) {
    uint32_t a;
    asm("{ .reg .u64 t; cvta.to.shared.u64 t, %1; cvt.u32.u64 %0, t; }" : "=r"(a) : "l"(p));
    return a;
}
__device__ __forceinline__ void ldm_x4(uint32_t (&d)[4], uint32_t addr) {
    asm volatile("ldmatrix.sync.aligned.m8n8.x4.shared.b16 {%0,%1,%2,%3}, [%4];"
        : "=r"(d[0]), "=r"(d[1]), "=r"(d[2]), "=r"(d[3]) : "r"(addr));
}
__device__ __forceinline__ void mma16816(float (&c)[4], const uint32_t (&a)[4],
                                         uint32_t b0, uint32_t b1) {
    asm volatile("mma.sync.aligned.m16n8k16.row.col.f32.bf16.bf16.f32 "
        "{%0,%1,%2,%3},{%4,%5,%6,%7},{%8,%9},{%0,%1,%2,%3};"
        : "+f"(c[0]), "+f"(c[1]), "+f"(c[2]), "+f"(c[3])
        : "r"(a[0]), "r"(a[1]), "r"(a[2]), "r"(a[3]), "r"(b0), "r"(b1));
}

// ---------------- split-bf16 tensor GEMM: D[M,N] = A[M,K]@B[N,K]^T (+bias) ----
// Optional fp32 output C (ld N) and/or bf16-split output Shi/Slo (ld ldS, col offset colS).
#define TG_STRIDE 40
#define TG_ARR    5120

__global__ void __launch_bounds__(256)
tgemm(const __nv_bfloat16* __restrict__ Ah, const __nv_bfloat16* __restrict__ Al,
      const __nv_bfloat16* __restrict__ Bh, const __nv_bfloat16* __restrict__ Bl,
      const float* __restrict__ bias, float* __restrict__ C,
      __nv_bfloat16* __restrict__ Shi, __nv_bfloat16* __restrict__ Slo,
      int ldS, int colS, int N, int K)
{
    __shared__ __nv_bfloat16 sm[4*TG_ARR];
    int tid = threadIdx.x, lane = tid & 31, wid = tid >> 5;
    int row0 = blockIdx.y * 128, col0 = blockIdx.x * 128;
    int wm = (wid & 3) * 32, wn = (wid >> 2) * 64;
    uint32_t sb = cvta_sm(sm);

    float acc[2][8][4] = {};

    for (int k0 = 0; k0 < K; k0 += 32) {
        #pragma unroll
        for (int arr = 0; arr < 4; arr++) {
            const __nv_bfloat16* src = (arr == 0) ? Ah : (arr == 1) ? Al : (arr == 2) ? Bh : Bl;
            int rbase = (arr < 2) ? row0 : col0;
            __nv_bfloat16* dst = sm + arr * TG_ARR;
            #pragma unroll
            for (int l = 0; l < 2; l++) {
                int i = tid + l * 256;
                int r = i >> 2, c8 = i & 3;
                uint4 v = *(const uint4*)(src + (size_t)(rbase + r) * K + k0 + c8 * 8);
                *(uint4*)(dst + r * TG_STRIDE + c8 * 8) = v;
            }
        }
        __syncthreads();

        #pragma unroll
        for (int kk = 0; kk < 32; kk += 16) {
            uint32_t ah[2][4], al[2][4];
            #pragma unroll
            for (int mb = 0; mb < 2; mb++) {
                int r = wm + mb * 16 + (lane & 15);
                int c = kk + (lane >> 4) * 8;
                uint32_t off = (uint32_t)(r * TG_STRIDE + c) * 2;
                ldm_x4(ah[mb], sb + 0 * (TG_ARR*2) + off);
                ldm_x4(al[mb], sb + 1 * (TG_ARR*2) + off);
            }
            #pragma unroll
            for (int nb = 0; nb < 4; nb++) {
                int r = wn + nb * 16 + ((lane >> 4) << 3) + (lane & 7);
                int c = kk + ((lane >> 3) & 1) * 8;
                uint32_t off = (uint32_t)(r * TG_STRIDE + c) * 2;
                uint32_t bh[4], bl[4];
                ldm_x4(bh, sb + 2 * (TG_ARR*2) + off);
                ldm_x4(bl, sb + 3 * (TG_ARR*2) + off);
                #pragma unroll
                for (int mb = 0; mb < 2; mb++) {
                    mma16816(acc[mb][2*nb+0], ah[mb], bh[0], bh[1]);
                    mma16816(acc[mb][2*nb+1], ah[mb], bh[2], bh[3]);
                    mma16816(acc[mb][2*nb+0], ah[mb], bl[0], bl[1]);
                    mma16816(acc[mb][2*nb+1], ah[mb], bl[2], bl[3]);
                    mma16816(acc[mb][2*nb+0], al[mb], bh[0], bh[1]);
                    mma16816(acc[mb][2*nb+1], al[mb], bh[2], bh[3]);
                }
            }
        }
        __syncthreads();
    }

    int g = lane >> 2, tg = lane & 3;
    #pragma unroll
    for (int mb = 0; mb < 2; mb++) {
        #pragma unroll
        for (int n8 = 0; n8 < 8; n8++) {
            int row = row0 + wm + mb * 16 + g;
            int col = col0 + wn + n8 * 8 + 2 * tg;
            float b0 = bias ? bias[col]   : 0.f;
            float b1 = bias ? bias[col+1] : 0.f;
            float v00 = acc[mb][n8][0] + b0, v01 = acc[mb][n8][1] + b1;
            float v10 = acc[mb][n8][2] + b0, v11 = acc[mb][n8][3] + b1;
            if (C) {
                *(float2*)(C + (size_t)row * N + col)       = make_float2(v00, v01);
                *(float2*)(C + (size_t)(row + 8) * N + col) = make_float2(v10, v11);
            }
            if (Shi) {
                size_t d0 = (size_t)row * ldS + colS + col;
                size_t d1 = (size_t)(row + 8) * ldS + colS + col;
                bf16split(v00, &Shi[d0],   &Slo[d0]);
                bf16split(v01, &Shi[d0+1], &Slo[d0+1]);
                bf16split(v10, &Shi[d1],   &Slo[d1]);
                bf16split(v11, &Shi[d1+1], &Slo[d1+1]);
            }
        }
    }
}

// ---------------- LSTM pointwise + fused min/max partials ----------------
__global__ void lstm_mm(const float* __restrict__ gates, const float* __restrict__ c0,
                        float* __restrict__ h, float* __restrict__ c)
{
    float mn = 1e30f, mx = -1e30f;
    for (int idx = blockIdx.x*256 + threadIdx.x; idx < NA*HD; idx += MMB*256) {
        int n = idx / HD, k = idx % HD;
        const float* gr = gates + n * (4*HD);
        float ig = gr[k], fg = gr[HD+k], gg = gr[2*HD+k], og = gr[3*HD+k];
        float si = 1.f/(1.f+expf(-ig));
        float sf = 1.f/(1.f+expf(-fg));
        float so = 1.f/(1.f+expf(-og));
        float c2 = sf * c0[idx] + si * tanhf(gg);
        float hv = so * tanhf(c2);
        h[idx] = hv;
        c[idx] = c2;
        mn = fminf(mn, hv); mx = fmaxf(mx, hv);
    }
    __shared__ float smn[256], smx[256];
    smn[threadIdx.x] = mn; smx[threadIdx.x] = mx; __syncthreads();
    for (int s = 128; s > 0; s >>= 1) {
        if (threadIdx.x < s) {
            smn[threadIdx.x] = fminf(smn[threadIdx.x], smn[threadIdx.x+s]);
            smx[threadIdx.x] = fmaxf(smx[threadIdx.x], smx[threadIdx.x+s]);
        }
        __syncthreads();
    }
    if (threadIdx.x == 0) { g_pmin[blockIdx.x] = smn[0]; g_pmax[blockIdx.x] = smx[0]; }
}

__global__ void minmax2()
{
    __shared__ float smn[MMB], smx[MMB];
    int t = threadIdx.x;
    smn[t] = g_pmin[t]; smx[t] = g_pmax[t];
    __syncthreads();
    for (int s = MMB/2; s > 0; s >>= 1) {
        if (t < s) { smn[t] = fminf(smn[t], smn[t+s]); smx[t] = fmaxf(smx[t], smx[t+s]); }
        __syncthreads();
    }
    if (t == 0) {
        float mn = smn[0], mx = smx[0];
        if (mn == mx) { mn -= 0.01f; mx += 0.01f; }
        float scale = (mx - mn) / 255.f;
        g_qparam[0] = scale;
        g_qparam[1] = rintf(-mn / scale);
    }
}

// fake-quant: writes bf16 hi/lo splits of dequantized value + loss
__global__ void quant_split(const float* __restrict__ x,
                            __nv_bfloat16* __restrict__ hi, __nv_bfloat16* __restrict__ lo)
{
    float scale = g_qparam[0], zp = g_qparam[1];
    double part = 0.0;
    for (int i = blockIdx.x*256 + threadIdx.x; i < NA*HD; i += MMB*256) {
        float t = x[i];
        float r = rintf(t/scale + zp);
        r = fminf(fmaxf(r, 0.f), 255.f);
        float d = (r - zp) * scale;
        bf16split(d, &hi[i], &lo[i]);
        part += (double)log2f(510.f * fabsf(d) + 1.f);
    }
    __shared__ double sd[256];
    sd[threadIdx.x] = part; __syncthreads();
    for (int s = 128; s > 0; s >>= 1) { if (threadIdx.x < s) sd[threadIdx.x] += sd[threadIdx.x+s]; __syncthreads(); }
    if (threadIdx.x == 0) atomicAdd(&g_loss, sd[0]);
}

// ---------------- GAT attention ----------------
__global__ void cicj(const float* __restrict__ ai, const float* __restrict__ aj, int H, int G)
{
    int warp = (blockIdx.x*blockDim.x + threadIdx.x) >> 5;
    int lane = threadIdx.x & 31;
    if (warp >= NA * H) return;
    int n = warp / H, h = warp % H;
    float si = 0.f, sj = 0.f;
    for (int g = lane; g < G; g += 32) {
        float v = g_hW[n*HG + h*G + g];
        si += v * ai[h*G + g];
        sj += v * aj[h*G + g];
    }
    for (int o = 16; o > 0; o >>= 1) {
        si += __shfl_down_sync(0xffffffffu, si, o);
        sj += __shfl_down_sync(0xffffffffu, sj, o);
    }
    if (lane == 0) { g_ci[h*NA + n] = si; g_cj[h*NA + n] = sj; }
}

// bitonic sort + weights + cmax + fused per-query binary search
__global__ void sortk()
{
    __shared__ float key[NA];
    __shared__ int   idx[NA];
    int h = blockIdx.x;
    for (int i = threadIdx.x; i < NA; i += 1024) { key[i] = g_cj[h*NA + i]; idx[i] = i; }
    __syncthreads();
    for (int k = 2; k <= NA; k <<= 1) {
        for (int j = k >> 1; j > 0; j >>= 1) {
            for (int t = threadIdx.x; t < NA; t += 1024) {
                int ixj = t ^ j;
                if (ixj > t) {
                    bool up = ((t & k) == 0);
                    float a = key[t], b = key[ixj];
                    bool sw = up ? (a > b) : (a < b);
                    if (sw) {
                        key[t] = b; key[ixj] = a;
                        int tmp = idx[t]; idx[t] = idx[ixj]; idx[ixj] = tmp;
                    }
                }
            }
            __syncthreads();
        }
    }
    float cm = key[NA-1];
    for (int i = threadIdx.x; i < NA; i += 1024) {
        g_sidx[h*NA + i] = idx[i];
        g_wA  [h*NA + i] = expf(key[i] - cm);
        g_wB  [h*NA + i] = expf(0.2f * (key[i] - cm));
        // fused binary search: k_i = #{ cj <= -ci }
        float t = -g_ci[h*NA + i];
        int lo = 0, hi = NA;
        while (lo < hi) {
            int mid = (lo + hi) >> 1;
            if (key[mid] <= t) lo = mid + 1; else hi = mid;
        }
        g_kcount[h*NA + i] = lo;
    }
    if (threadIdx.x == 0) g_cmax[h] = cm;
}

__global__ void permT(int G)
{
    __shared__ float tile[32][33];
    int r0 = blockIdx.x * 32, c0 = blockIdx.y * 32;
    int h = c0 / G;
    for (int rr = threadIdx.y; rr < 32; rr += 8) {
        int src = g_sidx[h*NA + r0 + rr];
        tile[rr][threadIdx.x] = g_hW[src*HG + c0 + threadIdx.x];
    }
    __syncthreads();
    for (int cc = threadIdx.y; cc < 32; cc += 8) {
        g_hWT[(size_t)(c0+cc)*NA + r0 + threadIdx.x] = tile[threadIdx.x][cc];
    }
}

__global__ void scank(int H, int G)
{
    __shared__ float wsum[32];
    int b = blockIdx.x;
    bool scalar = (b >= H*G);
    int c = scalar ? 0 : b;
    int h = scalar ? (b - H*G) : (c / G);
    int tid = threadIdx.x, lane = tid & 31, warp = tid >> 5;
    int t0 = tid * 4;

    float4 w4 = *(const float4*)&g_wB[h*NA + t0];
    float x0 = 1.f, x1 = 1.f, x2 = 1.f, x3 = 1.f;
    if (!scalar) {
        float4 xv = *(const float4*)&g_hWT[(size_t)c*NA + t0];
        x0 = xv.x; x1 = xv.y; x2 = xv.z; x3 = xv.w;
    }
    float v0 = w4.x*x0;
    float v1 = v0 + w4.y*x1;
    float v2 = v1 + w4.z*x2;
    float v3 = v2 + w4.w*x3;
    float tot = v3, s = tot;
    #pragma unroll
    for (int o = 1; o < 32; o <<= 1) { float u = __shfl_up_sync(0xffffffffu, s, o); if (lane >= o) s += u; }
    if (lane == 31) wsum[warp] = s;
    __syncthreads();
    if (warp == 0) {
        float y = wsum[lane];
        #pragma unroll
        for (int o = 1; o < 32; o <<= 1) { float u = __shfl_up_sync(0xffffffffu, y, o); if (lane >= o) y += u; }
        wsum[lane] = y;
    }
    __syncthreads();
    float off = (warp ? wsum[warp-1] : 0.f) + (s - tot);
    {
        float4 o4 = make_float4(off+v0, off+v1, off+v2, off+v3);
        if (scalar) *(float4*)&g_preB_s[h*NA + t0] = o4;
        else        *(float4*)&g_preB_v[(size_t)c*NA + t0] = o4;
    }
    __syncthreads();

    int rbase = NA - 4 - t0;
    float4 wa = *(const float4*)&g_wA[h*NA + rbase];
    float y0 = 1.f, y1 = 1.f, y2 = 1.f, y3 = 1.f;
    if (!scalar) {
        float4 xv = *(const float4*)&g_hWT[(size_t)c*NA + rbase];
        y0 = xv.x; y1 = xv.y; y2 = xv.z; y3 = xv.w;
    }
    float u0 = wa.w*y3;
    float u1 = u0 + wa.z*y2;
    float u2 = u1 + wa.y*y1;
    float u3 = u2 + wa.x*y0;
    float tot2 = u3, s2 = tot2;
    #pragma unroll
    for (int o = 1; o < 32; o <<= 1) { float u = __shfl_up_sync(0xffffffffu, s2, o); if (lane >= o) s2 += u; }
    if (lane == 31) wsum[warp] = s2;
    __syncthreads();
    if (warp == 0) {
        float y = wsum[lane];
        #pragma unroll
        for (int o = 1; o < 32; o <<= 1) { float u = __shfl_up_sync(0xffffffffu, y, o); if (lane >= o) y += u; }
        wsum[lane] = y;
    }
    __syncthreads();
    float off2 = (warp ? wsum[warp-1] : 0.f) + (s2 - tot2);
    {
        float4 o4 = make_float4(off2+u3, off2+u2, off2+u1, off2+u0);
        if (scalar) *(float4*)&g_sufA_s[h*NA + rbase] = o4;
        else        *(float4*)&g_sufA_v[(size_t)c*NA + rbase] = o4;
    }
}

// combine + optional elu + optional fused min/max partials
__global__ void combine(const float* __restrict__ bias, float* __restrict__ out,
                        int H, int G, int do_elu, int do_mm)
{
    float mn = 1e30f, mx = -1e30f;
    for (int idx = blockIdx.x*256 + threadIdx.x; idx < NA*HG; idx += MMB*256) {
        int gi = idx % G;
        int h  = (idx / G) % H;
        int n  = idx / HG;
        int k  = g_kcount[h*NA + n];
        float r = expf(0.8f * (g_ci[h*NA + n] + g_cmax[h]));
        float A = (k < NA) ? g_sufA_s[h*NA + k]     : 0.f;
        float B = (k > 0)  ? g_preB_s[h*NA + k - 1] : 0.f;
        size_t vb = (size_t)(h*G + gi) * NA;
        float Av = (k < NA) ? g_sufA_v[vb + k]     : 0.f;
        float Bv = (k > 0)  ? g_preB_v[vb + k - 1] : 0.f;
        float val = (r*Av + Bv) / (r*A + B);
        val += bias[h*G + gi];
        if (do_elu) val = (val > 0.f) ? val : expm1f(val);
        out[idx] = val;
        mn = fminf(mn, val); mx = fmaxf(mx, val);
    }
    if (do_mm) {
        __shared__ float smn[256], smx[256];
        smn[threadIdx.x] = mn; smx[threadIdx.x] = mx; __syncthreads();
        for (int s = 128; s > 0; s >>= 1) {
            if (threadIdx.x < s) {
                smn[threadIdx.x] = fminf(smn[threadIdx.x], smn[threadIdx.x+s]);
                smx[threadIdx.x] = fmaxf(smx[threadIdx.x], smx[threadIdx.x+s]);
            }
            __syncthreads();
        }
        if (threadIdx.x == 0) { g_pmin[blockIdx.x] = smn[0]; g_pmax[blockIdx.x] = smx[0]; }
    }
}

// ---------------- fused policy + value head ----------------
// logits = [h|comm2] @ Wa + ba -> log_softmax -> out_logp; value = [h|comm2]@Wv + bv
__global__ void __launch_bounds__(256)
policyk(const float* __restrict__ A0, const float* __restrict__ A1,
        const float* __restrict__ Wa, const float* __restrict__ ba,
        const float* __restrict__ Wv, const float* __restrict__ bv,
        float* __restrict__ out_logp, float* __restrict__ out_value)
{
    __shared__ float As[16][68];
    __shared__ float Bs[16][68];
    __shared__ float Ss[64][65];
    int tid = threadIdx.x;
    int tx = tid % 16, ty = tid / 16;
    int row0 = blockIdx.x * 64;
    float acc[4][4] = {};
    float vacc = 0.f;

    for (int k0 = 0; k0 < 512; k0 += 16) {
        const float* Asrc = (k0 < 256) ? A0 : A1;
        int kb = (k0 < 256) ? k0 : k0 - 256;
        {
            int lin = tid * 4;
            int m = lin >> 4, kk = lin & 15;
            float4 v = *(const float4*)&Asrc[(size_t)(row0+m)*256 + kb + kk];
            As[kk+0][m] = v.x; As[kk+1][m] = v.y; As[kk+2][m] = v.z; As[kk+3][m] = v.w;
        }
        {
            int lin = tid * 4;
            int kk = lin >> 6, n = lin & 63;
            *(float4*)&Bs[kk][n] = *(const float4*)&Wa[(size_t)(k0+kk)*64 + n];
        }
        __syncthreads();
        #pragma unroll
        for (int kk = 0; kk < 16; kk++) {
            float a[4], bb[4];
            #pragma unroll
            for (int i = 0; i < 4; i++) a[i] = As[kk][ty*4+i];
            #pragma unroll
            for (int j = 0; j < 4; j++) bb[j] = Bs[kk][tx*4+j];
            #pragma unroll
            for (int i = 0; i < 4; i++)
                #pragma unroll
                for (int j = 0; j < 4; j++)
                    acc[i][j] = fmaf(a[i], bb[j], acc[i][j]);
        }
        // value-head partial: threads 0..63 each own one row
        if (tid < 64) {
            #pragma unroll
            for (int kk = 0; kk < 16; kk++)
                vacc = fmaf(As[kk][tid], Wv[k0+kk], vacc);
        }
        __syncthreads();
    }
    if (tid < 64) out_value[row0 + tid] = vacc + bv[0];

    #pragma unroll
    for (int i = 0; i < 4; i++)
        #pragma unroll
        for (int j = 0; j < 4; j++)
            Ss[ty*4+i][tx*4+j] = acc[i][j] + ba[tx*4+j];
    __syncthreads();

    int row = tid >> 2, quad = tid & 3;
    float m = -1e30f;
    #pragma unroll
    for (int c = 0; c < 16; c++) m = fmaxf(m, Ss[row][quad*16 + c]);
    m = fmaxf(m, __shfl_xor_sync(0xffffffffu, m, 1));
    m = fmaxf(m, __shfl_xor_sync(0xffffffffu, m, 2));
    float s = 0.f;
    #pragma unroll
    for (int c = 0; c < 16; c++) s += expf(Ss[row][quad*16 + c] - m);
    s += __shfl_xor_sync(0xffffffffu, s, 1);
    s += __shfl_xor_sync(0xffffffffu, s, 2);
    float lse = m + logf(s);
    #pragma unroll
    for (int c = 0; c < 16; c++)
        out_logp[(size_t)(row0+row)*64 + quad*16 + c] = Ss[row][quad*16 + c] - lse;
}

__global__ void k_writeloss(float* __restrict__ dst) { dst[0] = (float)g_loss; }

// ---------------- host ----------------
extern "C" void kernel_launch(void* const* d_in, const int* in_sizes, int n_in,
                              void* d_out, int out_size)
{
    const float* obs  = (const float*)d_in[0];
    const float* h0   = (const float*)d_in[1];
    const float* c0   = (const float*)d_in[2];
    const float* Wobs = (const float*)d_in[3];
    const float* bobs = (const float*)d_in[4];
    const float* Wih  = (const float*)d_in[5];
    const float* Whh  = (const float*)d_in[6];
    const float* bih  = (const float*)d_in[7];
    const float* bhh  = (const float*)d_in[8];
    const float* W1   = (const float*)d_in[9];
    const float* ai1  = (const float*)d_in[10];
    const float* aj1  = (const float*)d_in[11];
    const float* b1   = (const float*)d_in[12];
    const float* W2   = (const float*)d_in[13];
    const float* ai2  = (const float*)d_in[14];
    const float* aj2  = (const float*)d_in[15];
    const float* b2   = (const float*)d_in[16];
    const float* Wv   = (const float*)d_in[17];
    const float* bv   = (const float*)d_in[18];
    const float* Wa   = (const float*)d_in[19];
    const float* ba   = (const float*)d_in[20];

    float* out       = (float*)d_out;
    float* out_logp  = out;
    float* out_value = out + NA*ACT;
    float* out_h     = out_value + NA;
    float* out_c     = out_h + NA*HD;
    float* out_loss  = out_c + NA*HD;

    float *p_gates, *p_hW, *p_comm1, *p_comm2, *p_bsum;
    __nv_bfloat16 *p_Ah, *p_Al, *p_A2h, *p_A2l;
    __nv_bfloat16 *p_B0h, *p_B0l, *p_Bgh, *p_Bgl, *p_B1h, *p_B1l, *p_B2h, *p_B2l;
    cudaGetSymbolAddress((void**)&p_gates,  g_gates);
    cudaGetSymbolAddress((void**)&p_hW,     g_hW);
    cudaGetSymbolAddress((void**)&p_comm1,  g_comm1);
    cudaGetSymbolAddress((void**)&p_comm2,  g_comm2);
    cudaGetSymbolAddress((void**)&p_bsum,   g_bsum);
    cudaGetSymbolAddress((void**)&p_Ah,     g_Ah);
    cudaGetSymbolAddress((void**)&p_Al,     g_Al);
    cudaGetSymbolAddress((void**)&p_A2h,    g_A2h);
    cudaGetSymbolAddress((void**)&p_A2l,    g_A2l);
    cudaGetSymbolAddress((void**)&p_B0h,    g_B0h);
    cudaGetSymbolAddress((void**)&p_B0l,    g_B0l);
    cudaGetSymbolAddress((void**)&p_Bgh,    g_Bgh);
    cudaGetSymbolAddress((void**)&p_Bgl,    g_Bgl);
    cudaGetSymbolAddress((void**)&p_B1h,    g_B1h);
    cudaGetSymbolAddress((void**)&p_B1l,    g_B1l);
    cudaGetSymbolAddress((void**)&p_B2h,    g_B2h);
    cudaGetSymbolAddress((void**)&p_B2l,    g_B2l);

    k_init<<<1, 1>>>();
    // all input-constant prep in one launch
    wprep<<<WP_S6/256, 256>>>(obs, h0, Wobs, Wih, Whh, W1, W2, bih, bhh);
    // enc GEMM -> writes split-bf16 gates-A operand (cols 0..255, ld 512)
    tgemm<<<dim3(2, 32), 256>>>(p_A2h, p_A2l, p_B0h, p_B0l, bobs,
                                nullptr, p_Ah, p_Al, 512, 0, 256, 256);
    // gates GEMM
    tgemm<<<dim3(8, 32), 256>>>(p_Ah, p_Al, p_Bgh, p_Bgl, p_bsum,
                                p_gates, nullptr, nullptr, 0, 0, 1024, 512);
    // LSTM + fused min/max
    lstm_mm<<<MMB, 256>>>(p_gates, c0, out_h, out_c);
    minmax2<<<1, MMB>>>();
    quant_split<<<MMB, 256>>>(out_h, p_Ah, p_Al);   // ld 256 reuse
    // GAT1 projection
    tgemm<<<dim3(2, 32), 256>>>(p_Ah, p_Al, p_B1h, p_B1l, nullptr,
                                p_hW, nullptr, nullptr, 0, 0, 256, 256);
    // GAT1 attention
    cicj<<<(NA*4*32)/256, 256>>>(ai1, aj1, 4, 64);
    sortk<<<4, 1024>>>();
    permT<<<dim3(NA/32, HG/32), dim3(32,8)>>>(64);
    scank<<<4*64 + 4, 1024>>>(4, 64);
    combine<<<MMB, 256>>>(b1, p_comm1, 4, 64, 1, 1);
    minmax2<<<1, MMB>>>();
    quant_split<<<MMB, 256>>>(p_comm1, p_Ah, p_Al);
    // GAT2 projection
    tgemm<<<dim3(2, 32), 256>>>(p_Ah, p_Al, p_B2h, p_B2l, nullptr,
                                p_hW, nullptr, nullptr, 0, 0, 256, 256);
    // GAT2 attention
    cicj<<<(NA*1*32)/256, 256>>>(ai2, aj2, 1, 256);
    sortk<<<1, 1024>>>();
    permT<<<dim3(NA/32, HG/32), dim3(32,8)>>>(256);
    scank<<<1*256 + 1, 1024>>>(1, 256);
    combine<<<MMB, 256>>>(b2, p_comm2, 1, 256, 0, 0);
    // fused policy + value heads
    policyk<<<NA/64, 256>>>(out_h, p_comm2, Wa, ba, Wv, bv, out_logp, out_value);
    // loss
    k_writeloss<<<1, 1>>>(out_loss);
}

// round 6
// speedup vs baseline: 3.4548x; 1.0753x over previous
#include <cuda_runtime.h>
#include <cuda_bf16.h>
#include <math.h>
#include <stdint.h>

#define NA   4096
#define HD   256
#define HG   256
#define ACT  64
#define MMB  1024

// ---------------- device scratch ----------------
__device__ float g_gates[NA*4*HD];
__device__ float g_hW[NA*HG];
__device__ float g_hWT[HG*NA];
__device__ float g_comm1[NA*HD];
__device__ float g_comm2[NA*HD];
__device__ float g_bsum[4*HD];
__device__ __nv_bfloat16 g_Ah[NA*512];
__device__ __nv_bfloat16 g_Al[NA*512];
__device__ __nv_bfloat16 g_A2h[NA*256];
__device__ __nv_bfloat16 g_A2l[NA*256];
__device__ __nv_bfloat16 g_B0h[256*256], g_B0l[256*256];
__device__ __nv_bfloat16 g_Bgh[1024*512], g_Bgl[1024*512];
__device__ __nv_bfloat16 g_B1h[256*256], g_B1l[256*256];
__device__ __nv_bfloat16 g_B2h[256*256], g_B2l[256*256];
__device__ float g_ci[4*NA];
__device__ float g_cj[4*NA];
__device__ float g_cmax[4];
__device__ int   g_kcount[4*NA];
__device__ int   g_sidx[4*NA];
__device__ float g_wA[4*NA];
__device__ float g_wB[4*NA];
__device__ float g_sufA_s[4*NA];
__device__ float g_preB_s[4*NA];
__device__ float g_sufA_v[HG*NA];
__device__ float g_preB_v[HG*NA];
__device__ float g_pmin[MMB];
__device__ float g_pmax[MMB];
__device__ double g_loss;

__device__ __forceinline__ void bf16split(float x, __nv_bfloat16* hi, __nv_bfloat16* lo) {
    __nv_bfloat16 h = __float2bfloat16(x);
    *hi = h;
    *lo = __float2bfloat16(x - __bfloat162float(h));
}

// ---------------- fused weight/input prep (one launch; also zeroes loss) ------
#define WP_S0 (NA*256)
#define WP_S1 (WP_S0 + NA*256)
#define WP_S2 (WP_S1 + 65536)
#define WP_S3 (WP_S2 + 524288)
#define WP_S4 (WP_S3 + 65536)
#define WP_S5 (WP_S4 + 65536)
#define WP_S6 (WP_S5 + 1024)
__global__ void wprep(const float* __restrict__ obs, const float* __restrict__ h0,
                      const float* __restrict__ Wobs,
                      const float* __restrict__ Wih, const float* __restrict__ Whh,
                      const float* __restrict__ W1, const float* __restrict__ W2,
                      const float* __restrict__ bih, const float* __restrict__ bhh)
{
    int idx = blockIdx.x*256 + threadIdx.x;
    if (idx == 0) g_loss = 0.0;
    if (idx < WP_S0) {
        bf16split(obs[idx], &g_A2h[idx], &g_A2l[idx]);
    } else if (idx < WP_S1) {
        int j = idx - WP_S0;
        int n = j >> 8, k = j & 255;
        int d = n*512 + 256 + k;
        bf16split(h0[j], &g_Ah[d], &g_Al[d]);
    } else if (idx < WP_S2) {
        int j = idx - WP_S1;
        int n = j >> 8, k = j & 255;
        bf16split(Wobs[k*256 + n], &g_B0h[j], &g_B0l[j]);
    } else if (idx < WP_S3) {
        int j = idx - WP_S2;
        int r = j >> 9, k = j & 511;
        float x = (k < 256) ? Wih[r*256 + k] : Whh[r*256 + k - 256];
        bf16split(x, &g_Bgh[j], &g_Bgl[j]);
    } else if (idx < WP_S4) {
        int j = idx - WP_S3;
        int n = j >> 8, k = j & 255;
        bf16split(W1[k*256 + n], &g_B1h[j], &g_B1l[j]);
    } else if (idx < WP_S5) {
        int j = idx - WP_S4;
        int n = j >> 8, k = j & 255;
        bf16split(W2[k*256 + n], &g_B2h[j], &g_B2l[j]);
    } else if (idx < WP_S6) {
        int j = idx - WP_S5;
        g_bsum[j] = bih[j] + bhh[j];
    }
}

// ---------------- mma.sync helpers ----------------
__device__ __forceinline__ uint32_t cvta_sm(const void* p) {
    uint32_t a;
    asm("{ .reg .u64 t; cvta.to.shared.u64 t, %1; cvt.u32.u64 %0, t; }" : "=r"(a) : "l"(p));
    return a;
}
__device__ __forceinline__ void ldm_x4(uint32_t (&d)[4], uint32_t addr) {
    asm volatile("ldmatrix.sync.aligned.m8n8.x4.shared.b16 {%0,%1,%2,%3}, [%4];"
        : "=r"(d[0]), "=r"(d[1]), "=r"(d[2]), "=r"(d[3]) : "r"(addr));
}
__device__ __forceinline__ void mma16816(float (&c)[4], const uint32_t (&a)[4],
                                         uint32_t b0, uint32_t b1) {
    asm volatile("mma.sync.aligned.m16n8k16.row.col.f32.bf16.bf16.f32 "
        "{%0,%1,%2,%3},{%4,%5,%6,%7},{%8,%9},{%0,%1,%2,%3};"
        : "+f"(c[0]), "+f"(c[1]), "+f"(c[2]), "+f"(c[3])
        : "r"(a[0]), "r"(a[1]), "r"(a[2]), "r"(a[3]), "r"(b0), "r"(b1));
}

// ---------------- split-bf16 tensor GEMM, cp.async 2-stage pipeline ----------
// D[M,N] = A[M,K]@B[N,K]^T (+bias). Optional fp32 out C and/or split out Shi/Slo.
#define TG_STRIDE 40

template<int BM>
__global__ void __launch_bounds__(256, BM == 64 ? 2 : 1)
tgemm(const __nv_bfloat16* __restrict__ Ah, const __nv_bfloat16* __restrict__ Al,
      const __nv_bfloat16* __restrict__ Bh, const __nv_bfloat16* __restrict__ Bl,
      const float* __restrict__ bias, float* __restrict__ C,
      __nv_bfloat16* __restrict__ Shi, __nv_bfloat16* __restrict__ Slo,
      int ldS, int N, int K)
{
    constexpr int A_ELE = BM * TG_STRIDE;        // bf16 per A array per stage
    constexpr int B_ELE = 128 * TG_STRIDE;
    constexpr int STAGE = 2*A_ELE + 2*B_ELE;
    constexpr int NWM  = BM / 32;                // warps along M
    constexpr int WN   = 128 / (8 / NWM);        // 64 (BM=128) or 32 (BM=64)
    constexpr int NB16 = WN / 16;
    constexpr int NB   = WN / 8;
    constexpr int A_U4 = BM * 4;
    constexpr int B_U4 = 512;
    constexpr int TOT_U4 = 2*A_U4 + 2*B_U4;

    extern __shared__ __nv_bfloat16 sm[];
    int tid = threadIdx.x, lane = tid & 31, wid = tid >> 5;
    int col0 = blockIdx.x * 128, row0 = blockIdx.y * BM;
    int wm = (wid % NWM) * 32, wn = (wid / NWM) * WN;
    uint32_t sb = cvta_sm(sm);

    float acc[2][NB][4] = {};

    auto issue = [&](int stage, int k0) {
        uint32_t stb = sb + (uint32_t)stage * STAGE * 2;
        #pragma unroll
        for (int l = 0; l < TOT_U4/256; l++) {
            int i = tid + l * 256;
            const __nv_bfloat16* src;
            int r, c8;
            uint32_t soff;
            if (i < 2*A_U4) {
                int a = i / A_U4, j = i % A_U4;
                r = j >> 2; c8 = j & 3;
                src = (a ? Al : Ah) + (size_t)(row0 + r) * K;
                soff = (uint32_t)a * A_ELE;
            } else {
                int i2 = i - 2*A_U4;
                int a = i2 / B_U4, j = i2 % B_U4;
                r = j >> 2; c8 = j & 3;
                src = (a ? Bl : Bh) + (size_t)(col0 + r) * K;
                soff = 2*A_ELE + (uint32_t)a * B_ELE;
            }
            uint32_t dst = stb + (soff + r * TG_STRIDE + c8 * 8) * 2;
            const __nv_bfloat16* g = src + k0 + c8 * 8;
            asm volatile("cp.async.cg.shared.global [%0], [%1], 16;" :: "r"(dst), "l"(g));
        }
        asm volatile("cp.async.commit_group;" ::: "memory");
    };

    auto compute = [&](int stage) {
        uint32_t stb = sb + (uint32_t)stage * STAGE * 2;
        uint32_t bA_h = stb, bA_l = stb + A_ELE*2;
        uint32_t bB_h = stb + 2*A_ELE*2, bB_l = stb + (2*A_ELE + B_ELE)*2;
        #pragma unroll
        for (int kk = 0; kk < 32; kk += 16) {
            uint32_t ah[2][4], al[2][4];
            #pragma unroll
            for (int mb = 0; mb < 2; mb++) {
                int r = wm + mb * 16 + (lane & 15);
                int c = kk + (lane >> 4) * 8;
                uint32_t off = (uint32_t)(r * TG_STRIDE + c) * 2;
                ldm_x4(ah[mb], bA_h + off);
                ldm_x4(al[mb], bA_l + off);
            }
            #pragma unroll
            for (int nb = 0; nb < NB16; nb++) {
                int r = wn + nb * 16 + ((lane >> 4) << 3) + (lane & 7);
                int c = kk + ((lane >> 3) & 1) * 8;
                uint32_t off = (uint32_t)(r * TG_STRIDE + c) * 2;
                uint32_t bh[4], bl[4];
                ldm_x4(bh, bB_h + off);
                ldm_x4(bl, bB_l + off);
                #pragma unroll
                for (int mb = 0; mb < 2; mb++) {
                    mma16816(acc[mb][2*nb+0], ah[mb], bh[0], bh[1]);
                    mma16816(acc[mb][2*nb+1], ah[mb], bh[2], bh[3]);
                    mma16816(acc[mb][2*nb+0], ah[mb], bl[0], bl[1]);
                    mma16816(acc[mb][2*nb+1], ah[mb], bl[2], bl[3]);
                    mma16816(acc[mb][2*nb+0], al[mb], bh[0], bh[1]);
                    mma16816(acc[mb][2*nb+1], al[mb], bh[2], bh[3]);
                }
            }
        }
    };

    int nch = K >> 5;
    issue(0, 0);
    for (int ck = 0; ck < nch; ck++) {
        if (ck + 1 < nch) {
            issue((ck + 1) & 1, (ck + 1) << 5);
            asm volatile("cp.async.wait_group 1;" ::: "memory");
        } else {
            asm volatile("cp.async.wait_group 0;" ::: "memory");
        }
        __syncthreads();
        compute(ck & 1);
        __syncthreads();
    }

    int g = lane >> 2, tg = lane & 3;
    #pragma unroll
    for (int mb = 0; mb < 2; mb++) {
        #pragma unroll
        for (int n8 = 0; n8 < NB; n8++) {
            int row = row0 + wm + mb * 16 + g;
            int col = col0 + wn + n8 * 8 + 2 * tg;
            float b0 = bias ? bias[col]   : 0.f;
            float b1 = bias ? bias[col+1] : 0.f;
            float v00 = acc[mb][n8][0] + b0, v01 = acc[mb][n8][1] + b1;
            float v10 = acc[mb][n8][2] + b0, v11 = acc[mb][n8][3] + b1;
            if (C) {
                *(float2*)(C + (size_t)row * N + col)       = make_float2(v00, v01);
                *(float2*)(C + (size_t)(row + 8) * N + col) = make_float2(v10, v11);
            }
            if (Shi) {
                size_t d0 = (size_t)row * ldS + col;
                size_t d1 = (size_t)(row + 8) * ldS + col;
                bf16split(v00, &Shi[d0],   &Slo[d0]);
                bf16split(v01, &Shi[d0+1], &Slo[d0+1]);
                bf16split(v10, &Shi[d1],   &Slo[d1]);
                bf16split(v11, &Shi[d1+1], &Slo[d1+1]);
            }
        }
    }
}

// ---------------- LSTM pointwise + fused min/max partials ----------------
__global__ void lstm_mm(const float* __restrict__ gates, const float* __restrict__ c0,
                        float* __restrict__ h, float* __restrict__ c)
{
    float mn = 1e30f, mx = -1e30f;
    for (int idx = blockIdx.x*256 + threadIdx.x; idx < NA*HD; idx += MMB*256) {
        int n = idx / HD, k = idx % HD;
        const float* gr = gates + n * (4*HD);
        float ig = gr[k], fg = gr[HD+k], gg = gr[2*HD+k], og = gr[3*HD+k];
        float si = 1.f/(1.f+expf(-ig));
        float sf = 1.f/(1.f+expf(-fg));
        float so = 1.f/(1.f+expf(-og));
        float c2 = sf * c0[idx] + si * tanhf(gg);
        float hv = so * tanhf(c2);
        h[idx] = hv;
        c[idx] = c2;
        mn = fminf(mn, hv); mx = fmaxf(mx, hv);
    }
    __shared__ float smn[256], smx[256];
    smn[threadIdx.x] = mn; smx[threadIdx.x] = mx; __syncthreads();
    for (int s = 128; s > 0; s >>= 1) {
        if (threadIdx.x < s) {
            smn[threadIdx.x] = fminf(smn[threadIdx.x], smn[threadIdx.x+s]);
            smx[threadIdx.x] = fmaxf(smx[threadIdx.x], smx[threadIdx.x+s]);
        }
        __syncthreads();
    }
    if (threadIdx.x == 0) { g_pmin[blockIdx.x] = smn[0]; g_pmax[blockIdx.x] = smx[0]; }
}

// fake-quant: each block reduces partials itself (no separate minmax2 launch),
// then writes bf16 hi/lo splits + loss.
__global__ void quant_split(const float* __restrict__ x,
                            __nv_bfloat16* __restrict__ hi, __nv_bfloat16* __restrict__ lo,
                            int npart)
{
    __shared__ float smn[256], smx[256];
    __shared__ float sparam[2];
    float mn = 1e30f, mx = -1e30f;
    for (int i = threadIdx.x; i < npart; i += 256) {
        mn = fminf(mn, g_pmin[i]); mx = fmaxf(mx, g_pmax[i]);
    }
    smn[threadIdx.x] = mn; smx[threadIdx.x] = mx; __syncthreads();
    for (int s = 128; s > 0; s >>= 1) {
        if (threadIdx.x < s) {
            smn[threadIdx.x] = fminf(smn[threadIdx.x], smn[threadIdx.x+s]);
            smx[threadIdx.x] = fmaxf(smx[threadIdx.x], smx[threadIdx.x+s]);
        }
        __syncthreads();
    }
    if (threadIdx.x == 0) {
        float a = smn[0], b = smx[0];
        if (a == b) { a -= 0.01f; b += 0.01f; }
        float scale = (b - a) / 255.f;
        sparam[0] = scale;
        sparam[1] = rintf(-a / scale);
    }
    __syncthreads();
    float scale = sparam[0], zp = sparam[1];

    double part = 0.0;
    for (int i = blockIdx.x*256 + threadIdx.x; i < NA*HD; i += MMB*256) {
        float t = x[i];
        float r = rintf(t/scale + zp);
        r = fminf(fmaxf(r, 0.f), 255.f);
        float d = (r - zp) * scale;
        bf16split(d, &hi[i], &lo[i]);
        part += (double)log2f(510.f * fabsf(d) + 1.f);
    }
    __shared__ double sd[256];
    sd[threadIdx.x] = part; __syncthreads();
    for (int s = 128; s > 0; s >>= 1) { if (threadIdx.x < s) sd[threadIdx.x] += sd[threadIdx.x+s]; __syncthreads(); }
    if (threadIdx.x == 0) atomicAdd(&g_loss, sd[0]);
}

// ---------------- GAT attention ----------------
__global__ void cicj(const float* __restrict__ ai, const float* __restrict__ aj, int H, int G)
{
    int warp = (blockIdx.x*blockDim.x + threadIdx.x) >> 5;
    int lane = threadIdx.x & 31;
    if (warp >= NA * H) return;
    int n = warp / H, h = warp % H;
    float si = 0.f, sj = 0.f;
    for (int g = lane; g < G; g += 32) {
        float v = g_hW[n*HG + h*G + g];
        si += v * ai[h*G + g];
        sj += v * aj[h*G + g];
    }
    for (int o = 16; o > 0; o >>= 1) {
        si += __shfl_down_sync(0xffffffffu, si, o);
        sj += __shfl_down_sync(0xffffffffu, sj, o);
    }
    if (lane == 0) { g_ci[h*NA + n] = si; g_cj[h*NA + n] = sj; }
}

__global__ void sortk()
{
    __shared__ float key[NA];
    __shared__ int   idx[NA];
    int h = blockIdx.x;
    for (int i = threadIdx.x; i < NA; i += 1024) { key[i] = g_cj[h*NA + i]; idx[i] = i; }
    __syncthreads();
    for (int k = 2; k <= NA; k <<= 1) {
        for (int j = k >> 1; j > 0; j >>= 1) {
            for (int t = threadIdx.x; t < NA; t += 1024) {
                int ixj = t ^ j;
                if (ixj > t) {
                    bool up = ((t & k) == 0);
                    float a = key[t], b = key[ixj];
                    bool sw = up ? (a > b) : (a < b);
                    if (sw) {
                        key[t] = b; key[ixj] = a;
                        int tmp = idx[t]; idx[t] = idx[ixj]; idx[ixj] = tmp;
                    }
                }
            }
            __syncthreads();
        }
    }
    float cm = key[NA-1];
    for (int i = threadIdx.x; i < NA; i += 1024) {
        g_sidx[h*NA + i] = idx[i];
        g_wA  [h*NA + i] = expf(key[i] - cm);
        g_wB  [h*NA + i] = expf(0.2f * (key[i] - cm));
        float t = -g_ci[h*NA + i];
        int lo = 0, hi = NA;
        while (lo < hi) {
            int mid = (lo + hi) >> 1;
            if (key[mid] <= t) lo = mid + 1; else hi = mid;
        }
        g_kcount[h*NA + i] = lo;
    }
    if (threadIdx.x == 0) g_cmax[h] = cm;
}

__global__ void permT(int G)
{
    __shared__ float tile[32][33];
    int r0 = blockIdx.x * 32, c0 = blockIdx.y * 32;
    int h = c0 / G;
    for (int rr = threadIdx.y; rr < 32; rr += 8) {
        int src = g_sidx[h*NA + r0 + rr];
        tile[rr][threadIdx.x] = g_hW[src*HG + c0 + threadIdx.x];
    }
    __syncthreads();
    for (int cc = threadIdx.y; cc < 32; cc += 8) {
        g_hWT[(size_t)(c0+cc)*NA + r0 + threadIdx.x] = tile[threadIdx.x][cc];
    }
}

__global__ void scank(int H, int G)
{
    __shared__ float wsum[32];
    int b = blockIdx.x;
    bool scalar = (b >= H*G);
    int c = scalar ? 0 : b;
    int h = scalar ? (b - H*G) : (c / G);
    int tid = threadIdx.x, lane = tid & 31, warp = tid >> 5;
    int t0 = tid * 4;

    float4 w4 = *(const float4*)&g_wB[h*NA + t0];
    float x0 = 1.f, x1 = 1.f, x2 = 1.f, x3 = 1.f;
    if (!scalar) {
        float4 xv = *(const float4*)&g_hWT[(size_t)c*NA + t0];
        x0 = xv.x; x1 = xv.y; x2 = xv.z; x3 = xv.w;
    }
    float v0 = w4.x*x0;
    float v1 = v0 + w4.y*x1;
    float v2 = v1 + w4.z*x2;
    float v3 = v2 + w4.w*x3;
    float tot = v3, s = tot;
    #pragma unroll
    for (int o = 1; o < 32; o <<= 1) { float u = __shfl_up_sync(0xffffffffu, s, o); if (lane >= o) s += u; }
    if (lane == 31) wsum[warp] = s;
    __syncthreads();
    if (warp == 0) {
        float y = wsum[lane];
        #pragma unroll
        for (int o = 1; o < 32; o <<= 1) { float u = __shfl_up_sync(0xffffffffu, y, o); if (lane >= o) y += u; }
        wsum[lane] = y;
    }
    __syncthreads();
    float off = (warp ? wsum[warp-1] : 0.f) + (s - tot);
    {
        float4 o4 = make_float4(off+v0, off+v1, off+v2, off+v3);
        if (scalar) *(float4*)&g_preB_s[h*NA + t0] = o4;
        else        *(float4*)&g_preB_v[(size_t)c*NA + t0] = o4;
    }
    __syncthreads();

    int rbase = NA - 4 - t0;
    float4 wa = *(const float4*)&g_wA[h*NA + rbase];
    float y0 = 1.f, y1 = 1.f, y2 = 1.f, y3 = 1.f;
    if (!scalar) {
        float4 xv = *(const float4*)&g_hWT[(size_t)c*NA + rbase];
        y0 = xv.x; y1 = xv.y; y2 = xv.z; y3 = xv.w;
    }
    float u0 = wa.w*y3;
    float u1 = u0 + wa.z*y2;
    float u2 = u1 + wa.y*y1;
    float u3 = u2 + wa.x*y0;
    float tot2 = u3, s2 = tot2;
    #pragma unroll
    for (int o = 1; o < 32; o <<= 1) { float u = __shfl_up_sync(0xffffffffu, s2, o); if (lane >= o) s2 += u; }
    if (lane == 31) wsum[warp] = s2;
    __syncthreads();
    if (warp == 0) {
        float y = wsum[lane];
        #pragma unroll
        for (int o = 1; o < 32; o <<= 1) { float u = __shfl_up_sync(0xffffffffu, y, o); if (lane >= o) y += u; }
        wsum[lane] = y;
    }
    __syncthreads();
    float off2 = (warp ? wsum[warp-1] : 0.f) + (s2 - tot2);
    {
        float4 o4 = make_float4(off2+u3, off2+u2, off2+u1, off2+u0);
        if (scalar) *(float4*)&g_sufA_s[h*NA + rbase] = o4;
        else        *(float4*)&g_sufA_v[(size_t)c*NA + rbase] = o4;
    }
}

// ---------------- combine v2: tiled, cache-friendly gathers, coalesced writes -
// grid: (HG/16 gi-blocks, NA/512 n-blocks), 256 threads.
__global__ void __launch_bounds__(256)
combine2(const float* __restrict__ bias, float* __restrict__ out,
         int G, int do_elu, int do_mm)
{
    __shared__ float s_r[512], s_invd[512];
    __shared__ int   s_k[512];
    __shared__ float tile[512][17];
    int gi0 = blockIdx.x * 16;
    int n0  = blockIdx.y * 512;
    int h = gi0 / G;
    int tid = threadIdx.x;
    float cm = g_cmax[h];

    for (int nl = tid; nl < 512; nl += 256) {
        int n = n0 + nl;
        int k = g_kcount[h*NA + n];
        float r = expf(0.8f * (g_ci[h*NA + n] + cm));
        float A = (k < NA) ? g_sufA_s[h*NA + k]     : 0.f;
        float B = (k > 0)  ? g_preB_s[h*NA + k - 1] : 0.f;
        s_k[nl] = k; s_r[nl] = r; s_invd[nl] = 1.f / (r*A + B);
    }
    __syncthreads();

    float mn = 1e30f, mx = -1e30f;
    #pragma unroll 1
    for (int c = 0; c < 16; c++) {
        int gi = gi0 + c;
        float bv = bias[gi];
        const float* Sv = g_sufA_v + (size_t)gi * NA;
        const float* Pv = g_preB_v + (size_t)gi * NA;
        for (int nl = tid; nl < 512; nl += 256) {
            int k = s_k[nl];
            float Av = (k < NA) ? Sv[k]     : 0.f;
            float Bv = (k > 0)  ? Pv[k - 1] : 0.f;
            float val = (s_r[nl]*Av + Bv) * s_invd[nl] + bv;
            if (do_elu) val = (val > 0.f) ? val : expm1f(val);
            tile[nl][c] = val;
            mn = fminf(mn, val); mx = fmaxf(mx, val);
        }
    }
    __syncthreads();
    for (int i = tid; i < 512*16; i += 256) {
        int nl = i >> 4, c = i & 15;
        out[(size_t)(n0 + nl) * HG + gi0 + c] = tile[nl][c];
    }
    if (do_mm) {
        __shared__ float smn[256], smx[256];
        smn[tid] = mn; smx[tid] = mx; __syncthreads();
        for (int s = 128; s > 0; s >>= 1) {
            if (tid < s) {
                smn[tid] = fminf(smn[tid], smn[tid+s]);
                smx[tid] = fmaxf(smx[tid], smx[tid+s]);
            }
            __syncthreads();
        }
        if (tid == 0) {
            int bid = blockIdx.y * 16 + blockIdx.x;
            g_pmin[bid] = smn[0]; g_pmax[bid] = smx[0];
        }
    }
}

// ---------------- fused policy + value head (+ loss write) ----------------
__global__ void __launch_bounds__(256)
policyk(const float* __restrict__ A0, const float* __restrict__ A1,
        const float* __restrict__ Wa, const float* __restrict__ ba,
        const float* __restrict__ Wv, const float* __restrict__ bv,
        float* __restrict__ out_logp, float* __restrict__ out_value,
        float* __restrict__ out_loss)
{
    if (blockIdx.x == 0 && threadIdx.x == 0) out_loss[0] = (float)g_loss;
    __shared__ float As[16][68];
    __shared__ float Bs[16][68];
    __shared__ float Ss[64][65];
    int tid = threadIdx.x;
    int tx = tid % 16, ty = tid / 16;
    int row0 = blockIdx.x * 64;
    float acc[4][4] = {};
    float vacc = 0.f;

    for (int k0 = 0; k0 < 512; k0 += 16) {
        const float* Asrc = (k0 < 256) ? A0 : A1;
        int kb = (k0 < 256) ? k0 : k0 - 256;
        {
            int lin = tid * 4;
            int m = lin >> 4, kk = lin & 15;
            float4 v = *(const float4*)&Asrc[(size_t)(row0+m)*256 + kb + kk];
            As[kk+0][m] = v.x; As[kk+1][m] = v.y; As[kk+2][m] = v.z; As[kk+3][m] = v.w;
        }
        {
            int lin = tid * 4;
            int kk = lin >> 6, n = lin & 63;
            *(float4*)&Bs[kk][n] = *(const float4*)&Wa[(size_t)(k0+kk)*64 + n];
        }
        __syncthreads();
        #pragma unroll
        for (int kk = 0; kk < 16; kk++) {
            float a[4], bb[4];
            #pragma unroll
            for (int i = 0; i < 4; i++) a[i] = As[kk][ty*4+i];
            #pragma unroll
            for (int j = 0; j < 4; j++) bb[j] = Bs[kk][tx*4+j];
            #pragma unroll
            for (int i = 0; i < 4; i++)
                #pragma unroll
                for (int j = 0; j < 4; j++)
                    acc[i][j] = fmaf(a[i], bb[j], acc[i][j]);
        }
        if (tid < 64) {
            #pragma unroll
            for (int kk = 0; kk < 16; kk++)
                vacc = fmaf(As[kk][tid], Wv[k0+kk], vacc);
        }
        __syncthreads();
    }
    if (tid < 64) out_value[row0 + tid] = vacc + bv[0];

    #pragma unroll
    for (int i = 0; i < 4; i++)
        #pragma unroll
        for (int j = 0; j < 4; j++)
            Ss[ty*4+i][tx*4+j] = acc[i][j] + ba[tx*4+j];
    __syncthreads();

    int row = tid >> 2, quad = tid & 3;
    float m = -1e30f;
    #pragma unroll
    for (int c = 0; c < 16; c++) m = fmaxf(m, Ss[row][quad*16 + c]);
    m = fmaxf(m, __shfl_xor_sync(0xffffffffu, m, 1));
    m = fmaxf(m, __shfl_xor_sync(0xffffffffu, m, 2));
    float s = 0.f;
    #pragma unroll
    for (int c = 0; c < 16; c++) s += expf(Ss[row][quad*16 + c] - m);
    s += __shfl_xor_sync(0xffffffffu, s, 1);
    s += __shfl_xor_sync(0xffffffffu, s, 2);
    float lse = m + logf(s);
    #pragma unroll
    for (int c = 0; c < 16; c++)
        out_logp[(size_t)(row0+row)*64 + quad*16 + c] = Ss[row][quad*16 + c] - lse;
}

// ---------------- host ----------------
extern "C" void kernel_launch(void* const* d_in, const int* in_sizes, int n_in,
                              void* d_out, int out_size)
{
    const float* obs  = (const float*)d_in[0];
    const float* h0   = (const float*)d_in[1];
    const float* c0   = (const float*)d_in[2];
    const float* Wobs = (const float*)d_in[3];
    const float* bobs = (const float*)d_in[4];
    const float* Wih  = (const float*)d_in[5];
    const float* Whh  = (const float*)d_in[6];
    const float* bih  = (const float*)d_in[7];
    const float* bhh  = (const float*)d_in[8];
    const float* W1   = (const float*)d_in[9];
    const float* ai1  = (const float*)d_in[10];
    const float* aj1  = (const float*)d_in[11];
    const float* b1   = (const float*)d_in[12];
    const float* W2   = (const float*)d_in[13];
    const float* ai2  = (const float*)d_in[14];
    const float* aj2  = (const float*)d_in[15];
    const float* b2   = (const float*)d_in[16];
    const float* Wv   = (const float*)d_in[17];
    const float* bv   = (const float*)d_in[18];
    const float* Wa   = (const float*)d_in[19];
    const float* ba   = (const float*)d_in[20];

    float* out       = (float*)d_out;
    float* out_logp  = out;
    float* out_value = out + NA*ACT;
    float* out_h     = out_value + NA;
    float* out_c     = out_h + NA*HD;
    float* out_loss  = out_c + NA*HD;

    float *p_gates, *p_hW, *p_comm1, *p_comm2, *p_bsum;
    __nv_bfloat16 *p_Ah, *p_Al, *p_A2h, *p_A2l;
    __nv_bfloat16 *p_B0h, *p_B0l, *p_Bgh, *p_Bgl, *p_B1h, *p_B1l, *p_B2h, *p_B2l;
    cudaGetSymbolAddress((void**)&p_gates,  g_gates);
    cudaGetSymbolAddress((void**)&p_hW,     g_hW);
    cudaGetSymbolAddress((void**)&p_comm1,  g_comm1);
    cudaGetSymbolAddress((void**)&p_comm2,  g_comm2);
    cudaGetSymbolAddress((void**)&p_bsum,   g_bsum);
    cudaGetSymbolAddress((void**)&p_Ah,     g_Ah);
    cudaGetSymbolAddress((void**)&p_Al,     g_Al);
    cudaGetSymbolAddress((void**)&p_A2h,    g_A2h);
    cudaGetSymbolAddress((void**)&p_A2l,    g_A2l);
    cudaGetSymbolAddress((void**)&p_B0h,    g_B0h);
    cudaGetSymbolAddress((void**)&p_B0l,    g_B0l);
    cudaGetSymbolAddress((void**)&p_Bgh,    g_Bgh);
    cudaGetSymbolAddress((void**)&p_Bgl,    g_Bgl);
    cudaGetSymbolAddress((void**)&p_B1h,    g_B1h);
    cudaGetSymbolAddress((void**)&p_B1l,    g_B1l);
    cudaGetSymbolAddress((void**)&p_B2h,    g_B2h);
    cudaGetSymbolAddress((void**)&p_B2l,    g_B2l);

    // opt-in smem for pipelined GEMM (idempotent)
    const int SM128 = (2*(2*128*TG_STRIDE + 2*128*TG_STRIDE)) * 2; // 81920 B
    const int SM64  = (2*(2*64*TG_STRIDE  + 2*128*TG_STRIDE)) * 2; // 61440 B
    cudaFuncSetAttribute((const void*)tgemm<128>, cudaFuncAttributeMaxDynamicSharedMemorySize, SM128);
    cudaFuncSetAttribute((const void*)tgemm<64>,  cudaFuncAttributeMaxDynamicSharedMemorySize, SM64);

    // prep (also zeroes loss)
    wprep<<<(WP_S6 + 255)/256, 256>>>(obs, h0, Wobs, Wih, Whh, W1, W2, bih, bhh);
    // enc GEMM -> split-bf16 into gates A operand (cols 0..255 of ld-512)
    tgemm<64><<<dim3(2, 64), 256, SM64>>>(p_A2h, p_A2l, p_B0h, p_B0l, bobs,
                                          nullptr, p_Ah, p_Al, 512, 256, 256);
    // gates GEMM
    tgemm<128><<<dim3(8, 32), 256, SM128>>>(p_Ah, p_Al, p_Bgh, p_Bgl, p_bsum,
                                            p_gates, nullptr, nullptr, 0, 1024, 512);
    // LSTM + min/max partials
    lstm_mm<<<MMB, 256>>>(p_gates, c0, out_h, out_c);
    quant_split<<<MMB, 256>>>(out_h, p_Ah, p_Al, MMB);
    // GAT1 projection
    tgemm<64><<<dim3(2, 64), 256, SM64>>>(p_Ah, p_Al, p_B1h, p_B1l, nullptr,
                                          p_hW, nullptr, nullptr, 0, 256, 256);
    // GAT1 attention
    cicj<<<(NA*4*32)/256, 256>>>(ai1, aj1, 4, 64);
    sortk<<<4, 1024>>>();
    permT<<<dim3(NA/32, HG/32), dim3(32,8)>>>(64);
    scank<<<4*64 + 4, 1024>>>(4, 64);
    combine2<<<dim3(16, 8), 256>>>(b1, p_comm1, 64, 1, 1);
    quant_split<<<MMB, 256>>>(p_comm1, p_Ah, p_Al, 128);
    // GAT2 projection
    tgemm<64><<<dim3(2, 64), 256, SM64>>>(p_Ah, p_Al, p_B2h, p_B2l, nullptr,
                                          p_hW, nullptr, nullptr, 0, 256, 256);
    // GAT2 attention
    cicj<<<(NA*1*32)/256, 256>>>(ai2, aj2, 1, 256);
    sortk<<<1, 1024>>>();
    permT<<<dim3(NA/32, HG/32), dim3(32,8)>>>(256);
    scank<<<1*256 + 1, 1024>>>(1, 256);
    combine2<<<dim3(16, 8), 256>>>(b2, p_comm2, 256, 0, 0);
    // fused policy + value heads + loss write
    policyk<<<NA/64, 256>>>(out_h, p_comm2, Wa, ba, Wv, bv, out_logp, out_value, out_loss);
}

// round 7
// speedup vs baseline: 3.8948x; 1.1274x over previous
#include <cuda_runtime.h>
#include <cuda_bf16.h>
#include <math.h>
#include <stdint.h>

#define NA   4096
#define HD   256
#define HG   256
#define ACT  64
#define MMB  1024

// ---------------- device scratch ----------------
__device__ float g_gates[NA*4*HD];
__device__ float g_hWT[HG*NA];
__device__ float g_comm1[NA*HD];
__device__ float g_comm2[NA*HD];
__device__ float g_bsum[4*HD];
__device__ __nv_bfloat16 g_Ah[NA*512];
__device__ __nv_bfloat16 g_Al[NA*512];
__device__ __nv_bfloat16 g_A2h[NA*256];
__device__ __nv_bfloat16 g_A2l[NA*256];
__device__ __nv_bfloat16 g_B0h[256*256], g_B0l[256*256];
__device__ __nv_bfloat16 g_Bgh[1024*512], g_Bgl[1024*512];
__device__ __nv_bfloat16 g_B1h[256*256], g_B1l[256*256];
__device__ __nv_bfloat16 g_B2h[256*256], g_B2l[256*256];
__device__ float g_ci[4*NA];
__device__ float g_cj[4*NA];
__device__ float g_cmax[4];
__device__ int   g_kcount[4*NA];
__device__ int   g_sidx[4*NA];
__device__ float g_wA[4*NA];
__device__ float g_wB[4*NA];
__device__ float g_sufA_s[4*NA];
__device__ float g_preB_s[4*NA];
__device__ float g_sufA_v[HG*NA];
__device__ float g_preB_v[HG*NA];
__device__ float g_pmin[MMB];
__device__ float g_pmax[MMB];
__device__ double g_loss;

__device__ __forceinline__ void bf16split(float x, __nv_bfloat16* hi, __nv_bfloat16* lo) {
    __nv_bfloat16 h = __float2bfloat16(x);
    *hi = h;
    *lo = __float2bfloat16(x - __bfloat162float(h));
}

// ---------------- fused weight/input prep (one launch; also zeroes loss) ------
#define WP_S0 (NA*256)
#define WP_S1 (WP_S0 + NA*256)
#define WP_S2 (WP_S1 + 65536)
#define WP_S3 (WP_S2 + 524288)
#define WP_S4 (WP_S3 + 65536)
#define WP_S5 (WP_S4 + 65536)
#define WP_S6 (WP_S5 + 1024)
__global__ void wprep(const float* __restrict__ obs, const float* __restrict__ h0,
                      const float* __restrict__ Wobs,
                      const float* __restrict__ Wih, const float* __restrict__ Whh,
                      const float* __restrict__ W1, const float* __restrict__ W2,
                      const float* __restrict__ bih, const float* __restrict__ bhh)
{
    int idx = blockIdx.x*256 + threadIdx.x;
    if (idx == 0) g_loss = 0.0;
    if (idx < WP_S0) {
        bf16split(obs[idx], &g_A2h[idx], &g_A2l[idx]);
    } else if (idx < WP_S1) {
        int j = idx - WP_S0;
        int n = j >> 8, k = j & 255;
        int d = n*512 + 256 + k;
        bf16split(h0[j], &g_Ah[d], &g_Al[d]);
    } else if (idx < WP_S2) {
        int j = idx - WP_S1;
        int n = j >> 8, k = j & 255;
        bf16split(Wobs[k*256 + n], &g_B0h[j], &g_B0l[j]);
    } else if (idx < WP_S3) {
        int j = idx - WP_S2;
        int r = j >> 9, k = j & 511;
        float x = (k < 256) ? Wih[r*256 + k] : Whh[r*256 + k - 256];
        bf16split(x, &g_Bgh[j], &g_Bgl[j]);
    } else if (idx < WP_S4) {
        int j = idx - WP_S3;
        int n = j >> 8, k = j & 255;
        bf16split(W1[k*256 + n], &g_B1h[j], &g_B1l[j]);
    } else if (idx < WP_S5) {
        int j = idx - WP_S4;
        int n = j >> 8, k = j & 255;
        bf16split(W2[k*256 + n], &g_B2h[j], &g_B2l[j]);
    } else if (idx < WP_S6) {
        int j = idx - WP_S5;
        g_bsum[j] = bih[j] + bhh[j];
    }
}

// ---------------- mma.sync helpers ----------------
__device__ __forceinline__ uint32_t cvta_sm(const void* p) {
    uint32_t a;
    asm("{ .reg .u64 t; cvta.to.shared.u64 t, %1; cvt.u32.u64 %0, t; }" : "=r"(a) : "l"(p));
    return a;
}
__device__ __forceinline__ void ldm_x4(uint32_t (&d)[4], uint32_t addr) {
    asm volatile("ldmatrix.sync.aligned.m8n8.x4.shared.b16 {%0,%1,%2,%3}, [%4];"
        : "=r"(d[0]), "=r"(d[1]), "=r"(d[2]), "=r"(d[3]) : "r"(addr));
}
__device__ __forceinline__ void mma16816(float (&c)[4], const uint32_t (&a)[4],
                                         uint32_t b0, uint32_t b1) {
    asm volatile("mma.sync.aligned.m16n8k16.row.col.f32.bf16.bf16.f32 "
        "{%0,%1,%2,%3},{%4,%5,%6,%7},{%8,%9},{%0,%1,%2,%3};"
        : "+f"(c[0]), "+f"(c[1]), "+f"(c[2]), "+f"(c[3])
        : "r"(a[0]), "r"(a[1]), "r"(a[2]), "r"(a[3]), "r"(b0), "r"(b1));
}

// ---------------- split-bf16 tensor GEMM, cp.async 2-stage pipeline ----------
// D[M,N] = A[M,K]@B[N,K]^T (+bias). Outputs (each optional):
//   C      : fp32 row-major
//   Shi/Slo: bf16 hi/lo split, ld ldS
//   hwT    : fp32 transposed (hwT[col*NA+row])
//   aivec  : fused ci/cj reduction (atomicAdd into g_ci/g_cj), head size Gh
#define TG_STRIDE 40

template<int BM>
__global__ void __launch_bounds__(256, BM == 64 ? 2 : 1)
tgemm(const __nv_bfloat16* __restrict__ Ah, const __nv_bfloat16* __restrict__ Al,
      const __nv_bfloat16* __restrict__ Bh, const __nv_bfloat16* __restrict__ Bl,
      const float* __restrict__ bias, float* __restrict__ C,
      __nv_bfloat16* __restrict__ Shi, __nv_bfloat16* __restrict__ Slo, int ldS,
      float* __restrict__ hwT, const float* __restrict__ aivec,
      const float* __restrict__ ajvec, int Gh,
      int N, int K)
{
    constexpr int A_ELE = BM * TG_STRIDE;
    constexpr int B_ELE = 128 * TG_STRIDE;
    constexpr int STAGE = 2*A_ELE + 2*B_ELE;
    constexpr int NWM  = BM / 32;
    constexpr int WN   = 128 / (8 / NWM);
    constexpr int NB16 = WN / 16;
    constexpr int NB   = WN / 8;
    constexpr int A_U4 = BM * 4;
    constexpr int B_U4 = 512;
    constexpr int TOT_U4 = 2*A_U4 + 2*B_U4;

    extern __shared__ __nv_bfloat16 sm[];
    int tid = threadIdx.x, lane = tid & 31, wid = tid >> 5;
    int col0 = blockIdx.x * 128, row0 = blockIdx.y * BM;
    int wm = (wid % NWM) * 32, wn = (wid / NWM) * WN;
    uint32_t sb = cvta_sm(sm);

    float acc[2][NB][4] = {};

    auto issue = [&](int stage, int k0) {
        uint32_t stb = sb + (uint32_t)stage * STAGE * 2;
        #pragma unroll
        for (int l = 0; l < TOT_U4/256; l++) {
            int i = tid + l * 256;
            const __nv_bfloat16* src;
            int r, c8;
            uint32_t soff;
            if (i < 2*A_U4) {
                int a = i / A_U4, j = i % A_U4;
                r = j >> 2; c8 = j & 3;
                src = (a ? Al : Ah) + (size_t)(row0 + r) * K;
                soff = (uint32_t)a * A_ELE;
            } else {
                int i2 = i - 2*A_U4;
                int a = i2 / B_U4, j = i2 % B_U4;
                r = j >> 2; c8 = j & 3;
                src = (a ? Bl : Bh) + (size_t)(col0 + r) * K;
                soff = 2*A_ELE + (uint32_t)a * B_ELE;
            }
            uint32_t dst = stb + (soff + r * TG_STRIDE + c8 * 8) * 2;
            const __nv_bfloat16* g = src + k0 + c8 * 8;
            asm volatile("cp.async.cg.shared.global [%0], [%1], 16;" :: "r"(dst), "l"(g));
        }
        asm volatile("cp.async.commit_group;" ::: "memory");
    };

    auto compute = [&](int stage) {
        uint32_t stb = sb + (uint32_t)stage * STAGE * 2;
        uint32_t bA_h = stb, bA_l = stb + A_ELE*2;
        uint32_t bB_h = stb + 2*A_ELE*2, bB_l = stb + (2*A_ELE + B_ELE)*2;
        #pragma unroll
        for (int kk = 0; kk < 32; kk += 16) {
            uint32_t ah[2][4], al[2][4];
            #pragma unroll
            for (int mb = 0; mb < 2; mb++) {
                int r = wm + mb * 16 + (lane & 15);
                int c = kk + (lane >> 4) * 8;
                uint32_t off = (uint32_t)(r * TG_STRIDE + c) * 2;
                ldm_x4(ah[mb], bA_h + off);
                ldm_x4(al[mb], bA_l + off);
            }
            #pragma unroll
            for (int nb = 0; nb < NB16; nb++) {
                int r = wn + nb * 16 + ((lane >> 4) << 3) + (lane & 7);
                int c = kk + ((lane >> 3) & 1) * 8;
                uint32_t off = (uint32_t)(r * TG_STRIDE + c) * 2;
                uint32_t bh[4], bl[4];
                ldm_x4(bh, bB_h + off);
                ldm_x4(bl, bB_l + off);
                #pragma unroll
                for (int mb = 0; mb < 2; mb++) {
                    mma16816(acc[mb][2*nb+0], ah[mb], bh[0], bh[1]);
                    mma16816(acc[mb][2*nb+1], ah[mb], bh[2], bh[3]);
                    mma16816(acc[mb][2*nb+0], ah[mb], bl[0], bl[1]);
                    mma16816(acc[mb][2*nb+1], ah[mb], bl[2], bl[3]);
                    mma16816(acc[mb][2*nb+0], al[mb], bh[0], bh[1]);
                    mma16816(acc[mb][2*nb+1], al[mb], bh[2], bh[3]);
                }
            }
        }
    };

    int nch = K >> 5;
    issue(0, 0);
    for (int ck = 0; ck < nch; ck++) {
        if (ck + 1 < nch) {
            issue((ck + 1) & 1, (ck + 1) << 5);
            asm volatile("cp.async.wait_group 1;" ::: "memory");
        } else {
            asm volatile("cp.async.wait_group 0;" ::: "memory");
        }
        __syncthreads();
        compute(ck & 1);
        __syncthreads();
    }

    int g = lane >> 2, tg = lane & 3;
    float cia[2][2] = {}, cja[2][2] = {};
    #pragma unroll
    for (int mb = 0; mb < 2; mb++) {
        #pragma unroll
        for (int n8 = 0; n8 < NB; n8++) {
            int row = row0 + wm + mb * 16 + g;
            int col = col0 + wn + n8 * 8 + 2 * tg;
            float b0 = bias ? bias[col]   : 0.f;
            float b1 = bias ? bias[col+1] : 0.f;
            float v00 = acc[mb][n8][0] + b0, v01 = acc[mb][n8][1] + b1;
            float v10 = acc[mb][n8][2] + b0, v11 = acc[mb][n8][3] + b1;
            if (C) {
                *(float2*)(C + (size_t)row * N + col)       = make_float2(v00, v01);
                *(float2*)(C + (size_t)(row + 8) * N + col) = make_float2(v10, v11);
            }
            if (Shi) {
                size_t d0 = (size_t)row * ldS + col;
                size_t d1 = (size_t)(row + 8) * ldS + col;
                bf16split(v00, &Shi[d0],   &Slo[d0]);
                bf16split(v01, &Shi[d0+1], &Slo[d0+1]);
                bf16split(v10, &Shi[d1],   &Slo[d1]);
                bf16split(v11, &Shi[d1+1], &Slo[d1+1]);
            }
            if (hwT) {
                hwT[(size_t)col*NA + row]         = v00;
                hwT[(size_t)(col+1)*NA + row]     = v01;
                hwT[(size_t)col*NA + row + 8]     = v10;
                hwT[(size_t)(col+1)*NA + row + 8] = v11;
            }
            if (aivec) {
                float a0 = aivec[col], a1 = aivec[col+1];
                float j0 = ajvec[col], j1 = ajvec[col+1];
                cia[mb][0] += v00*a0 + v01*a1;
                cia[mb][1] += v10*a0 + v11*a1;
                cja[mb][0] += v00*j0 + v01*j1;
                cja[mb][1] += v10*j0 + v11*j1;
            }
        }
    }
    if (aivec) {
        int hh = (col0 + wn) / Gh;
        #pragma unroll
        for (int mb = 0; mb < 2; mb++) {
            #pragma unroll
            for (int hf = 0; hf < 2; hf++) {
                float ci = cia[mb][hf], cj = cja[mb][hf];
                ci += __shfl_xor_sync(0xffffffffu, ci, 1);
                ci += __shfl_xor_sync(0xffffffffu, ci, 2);
                cj += __shfl_xor_sync(0xffffffffu, cj, 1);
                cj += __shfl_xor_sync(0xffffffffu, cj, 2);
                if (tg == 0) {
                    int row = row0 + wm + mb * 16 + g + hf * 8;
                    atomicAdd(&g_ci[hh*NA + row], ci);
                    atomicAdd(&g_cj[hh*NA + row], cj);
                }
            }
        }
    }
}

// ---------------- LSTM pointwise (float4) + fused min/max partials -----------
__global__ void lstm_mm(const float* __restrict__ gates, const float* __restrict__ c0,
                        float* __restrict__ h, float* __restrict__ c)
{
    int i4 = blockIdx.x*256 + threadIdx.x;      // grid 1024 -> covers NA*HD/4
    int n = i4 >> 6, k4 = (i4 & 63) << 2;
    const float* gr = gates + (size_t)n * 1024;
    float4 ig = *(const float4*)(gr + k4);
    float4 fg = *(const float4*)(gr + 256 + k4);
    float4 gg = *(const float4*)(gr + 512 + k4);
    float4 og = *(const float4*)(gr + 768 + k4);
    float4 cv = *(const float4*)(c0 + (size_t)i4 * 4);
    float hv[4], c2[4];
    float igs[4] = {ig.x, ig.y, ig.z, ig.w};
    float fgs[4] = {fg.x, fg.y, fg.z, fg.w};
    float ggs[4] = {gg.x, gg.y, gg.z, gg.w};
    float ogs[4] = {og.x, og.y, og.z, og.w};
    float cvs[4] = {cv.x, cv.y, cv.z, cv.w};
    float mn = 1e30f, mx = -1e30f;
    #pragma unroll
    for (int t = 0; t < 4; t++) {
        float si = 1.f/(1.f+expf(-igs[t]));
        float sf = 1.f/(1.f+expf(-fgs[t]));
        float so = 1.f/(1.f+expf(-ogs[t]));
        c2[t] = sf * cvs[t] + si * tanhf(ggs[t]);
        hv[t] = so * tanhf(c2[t]);
        mn = fminf(mn, hv[t]); mx = fmaxf(mx, hv[t]);
    }
    *(float4*)(h + (size_t)i4*4) = make_float4(hv[0], hv[1], hv[2], hv[3]);
    *(float4*)(c + (size_t)i4*4) = make_float4(c2[0], c2[1], c2[2], c2[3]);

    __shared__ float smn[256], smx[256];
    smn[threadIdx.x] = mn; smx[threadIdx.x] = mx; __syncthreads();
    for (int s = 128; s > 0; s >>= 1) {
        if (threadIdx.x < s) {
            smn[threadIdx.x] = fminf(smn[threadIdx.x], smn[threadIdx.x+s]);
            smx[threadIdx.x] = fmaxf(smx[threadIdx.x], smx[threadIdx.x+s]);
        }
        __syncthreads();
    }
    if (threadIdx.x == 0) { g_pmin[blockIdx.x] = smn[0]; g_pmax[blockIdx.x] = smx[0]; }
}

// fake-quant (vectorized): reduces partials per block, writes bf16 splits + loss.
// Also zeroes g_ci/g_cj for the following GAT projection's fused reduction.
__global__ void quant_split(const float* __restrict__ x,
                            __nv_bfloat16* __restrict__ hi, __nv_bfloat16* __restrict__ lo,
                            int npart)
{
    int gt = blockIdx.x*256 + threadIdx.x;
    if (gt < 4*NA) { g_ci[gt] = 0.f; g_cj[gt] = 0.f; }

    __shared__ float smn[256], smx[256];
    __shared__ float sparam[2];
    float mn = 1e30f, mx = -1e30f;
    for (int i = threadIdx.x; i < npart; i += 256) {
        mn = fminf(mn, g_pmin[i]); mx = fmaxf(mx, g_pmax[i]);
    }
    smn[threadIdx.x] = mn; smx[threadIdx.x] = mx; __syncthreads();
    for (int s = 128; s > 0; s >>= 1) {
        if (threadIdx.x < s) {
            smn[threadIdx.x] = fminf(smn[threadIdx.x], smn[threadIdx.x+s]);
            smx[threadIdx.x] = fmaxf(smx[threadIdx.x], smx[threadIdx.x+s]);
        }
        __syncthreads();
    }
    if (threadIdx.x == 0) {
        float a = smn[0], b = smx[0];
        if (a == b) { a -= 0.01f; b += 0.01f; }
        float scale = (b - a) / 255.f;
        sparam[0] = scale;
        sparam[1] = rintf(-a / scale);
    }
    __syncthreads();
    float scale = sparam[0], zp = sparam[1];

    double part = 0.0;
    int i = blockIdx.x*256 + threadIdx.x;       // grid 1024 covers NA*HD/4
    {
        float4 t = ((const float4*)x)[i];
        float ts[4] = {t.x, t.y, t.z, t.w};
        float ds[4];
        #pragma unroll
        for (int q = 0; q < 4; q++) {
            float r = rintf(ts[q]/scale + zp);
            r = fminf(fmaxf(r, 0.f), 255.f);
            float d = (r - zp) * scale;
            ds[q] = d;
            part += (double)log2f(510.f * fabsf(d) + 1.f);
        }
        __nv_bfloat162 h01, h23, l01, l23;
        __nv_bfloat16 hh, ll;
        bf16split(ds[0], &hh, &ll); h01.x = hh; l01.x = ll;
        bf16split(ds[1], &hh, &ll); h01.y = hh; l01.y = ll;
        bf16split(ds[2], &hh, &ll); h23.x = hh; l23.x = ll;
        bf16split(ds[3], &hh, &ll); h23.y = hh; l23.y = ll;
        ((__nv_bfloat162*)hi)[i*2]   = h01;
        ((__nv_bfloat162*)hi)[i*2+1] = h23;
        ((__nv_bfloat162*)lo)[i*2]   = l01;
        ((__nv_bfloat162*)lo)[i*2+1] = l23;
    }
    __shared__ double sd[256];
    sd[threadIdx.x] = part; __syncthreads();
    for (int s = 128; s > 0; s >>= 1) { if (threadIdx.x < s) sd[threadIdx.x] += sd[threadIdx.x+s]; __syncthreads(); }
    if (threadIdx.x == 0) atomicAdd(&g_loss, sd[0]);
}

// ---------------- GAT attention ----------------
// bitonic sort (pair-indexed) + weights + cmax + fused binary search
__global__ void sortk()
{
    __shared__ float key[NA];
    __shared__ int   idx[NA];
    int h = blockIdx.x;
    for (int i = threadIdx.x; i < NA; i += 1024) { key[i] = g_cj[h*NA + i]; idx[i] = i; }
    __syncthreads();
    for (int k = 2; k <= NA; k <<= 1) {
        for (int j = k >> 1; j > 0; j >>= 1) {
            #pragma unroll 2
            for (int p = threadIdx.x; p < NA/2; p += 1024) {
                int i = ((p & ~(j-1)) << 1) | (p & (j-1));
                int l = i | j;
                bool up = ((i & k) == 0);
                float a = key[i], b = key[l];
                if (up ? (a > b) : (a < b)) {
                    key[i] = b; key[l] = a;
                    int tmp = idx[i]; idx[i] = idx[l]; idx[l] = tmp;
                }
            }
            __syncthreads();
        }
    }
    float cm = key[NA-1];
    for (int i = threadIdx.x; i < NA; i += 1024) {
        g_sidx[h*NA + i] = idx[i];
        g_wA  [h*NA + i] = expf(key[i] - cm);
        g_wB  [h*NA + i] = expf(0.2f * (key[i] - cm));
        float t = -g_ci[h*NA + i];
        int lo = 0, hi = NA;
        while (lo < hi) {
            int mid = (lo + hi) >> 1;
            if (key[mid] <= t) lo = mid + 1; else hi = mid;
        }
        g_kcount[h*NA + i] = lo;
    }
    if (threadIdx.x == 0) g_cmax[h] = cm;
}

// scans over sorted order; vector x gathered via sidx from unpermuted hWT
__global__ void scank(int H, int G)
{
    __shared__ float wsum[32];
    int b = blockIdx.x;
    bool scalar = (b >= H*G);
    int c = scalar ? 0 : b;
    int h = scalar ? (b - H*G) : (c / G);
    int tid = threadIdx.x, lane = tid & 31, warp = tid >> 5;
    int t0 = tid * 4;
    const float* xrow = g_hWT + (size_t)c * NA;

    float4 w4 = *(const float4*)&g_wB[h*NA + t0];
    float x0 = 1.f, x1 = 1.f, x2 = 1.f, x3 = 1.f;
    if (!scalar) {
        int4 iv = *(const int4*)&g_sidx[h*NA + t0];
        x0 = xrow[iv.x]; x1 = xrow[iv.y]; x2 = xrow[iv.z]; x3 = xrow[iv.w];
    }
    float v0 = w4.x*x0;
    float v1 = v0 + w4.y*x1;
    float v2 = v1 + w4.z*x2;
    float v3 = v2 + w4.w*x3;
    float tot = v3, s = tot;
    #pragma unroll
    for (int o = 1; o < 32; o <<= 1) { float u = __shfl_up_sync(0xffffffffu, s, o); if (lane >= o) s += u; }
    if (lane == 31) wsum[warp] = s;
    __syncthreads();
    if (warp == 0) {
        float y = wsum[lane];
        #pragma unroll
        for (int o = 1; o < 32; o <<= 1) { float u = __shfl_up_sync(0xffffffffu, y, o); if (lane >= o) y += u; }
        wsum[lane] = y;
    }
    __syncthreads();
    float off = (warp ? wsum[warp-1] : 0.f) + (s - tot);
    {
        float4 o4 = make_float4(off+v0, off+v1, off+v2, off+v3);
        if (scalar) *(float4*)&g_preB_s[h*NA + t0] = o4;
        else        *(float4*)&g_preB_v[(size_t)c*NA + t0] = o4;
    }
    __syncthreads();

    int rbase = NA - 4 - t0;
    float4 wa = *(const float4*)&g_wA[h*NA + rbase];
    float y0 = 1.f, y1 = 1.f, y2 = 1.f, y3 = 1.f;
    if (!scalar) {
        int4 iv = *(const int4*)&g_sidx[h*NA + rbase];
        y0 = xrow[iv.x]; y1 = xrow[iv.y]; y2 = xrow[iv.z]; y3 = xrow[iv.w];
    }
    float u0 = wa.w*y3;
    float u1 = u0 + wa.z*y2;
    float u2 = u1 + wa.y*y1;
    float u3 = u2 + wa.x*y0;
    float tot2 = u3, s2 = tot2;
    #pragma unroll
    for (int o = 1; o < 32; o <<= 1) { float u = __shfl_up_sync(0xffffffffu, s2, o); if (lane >= o) s2 += u; }
    if (lane == 31) wsum[warp] = s2;
    __syncthreads();
    if (warp == 0) {
        float y = wsum[lane];
        #pragma unroll
        for (int o = 1; o < 32; o <<= 1) { float u = __shfl_up_sync(0xffffffffu, y, o); if (lane >= o) y += u; }
        wsum[lane] = y;
    }
    __syncthreads();
    float off2 = (warp ? wsum[warp-1] : 0.f) + (s2 - tot2);
    {
        float4 o4 = make_float4(off2+u3, off2+u2, off2+u1, off2+u0);
        if (scalar) *(float4*)&g_sufA_s[h*NA + rbase] = o4;
        else        *(float4*)&g_sufA_v[(size_t)c*NA + rbase] = o4;
    }
}

// ---------------- combine: tiled, cache-friendly gathers, coalesced writes ---
__global__ void __launch_bounds__(256)
combine2(const float* __restrict__ bias, float* __restrict__ out,
         int G, int do_elu, int do_mm)
{
    __shared__ float s_r[512], s_invd[512];
    __shared__ int   s_k[512];
    __shared__ float tile[512][17];
    int gi0 = blockIdx.x * 16;
    int n0  = blockIdx.y * 512;
    int h = gi0 / G;
    int tid = threadIdx.x;
    float cm = g_cmax[h];

    for (int nl = tid; nl < 512; nl += 256) {
        int n = n0 + nl;
        int k = g_kcount[h*NA + n];
        float r = expf(0.8f * (g_ci[h*NA + n] + cm));
        float A = (k < NA) ? g_sufA_s[h*NA + k]     : 0.f;
        float B = (k > 0)  ? g_preB_s[h*NA + k - 1] : 0.f;
        s_k[nl] = k; s_r[nl] = r; s_invd[nl] = 1.f / (r*A + B);
    }
    __syncthreads();

    float mn = 1e30f, mx = -1e30f;
    #pragma unroll 1
    for (int c = 0; c < 16; c++) {
        int gi = gi0 + c;
        float bv = bias[gi];
        const float* Sv = g_sufA_v + (size_t)gi * NA;
        const float* Pv = g_preB_v + (size_t)gi * NA;
        for (int nl = tid; nl < 512; nl += 256) {
            int k = s_k[nl];
            float Av = (k < NA) ? Sv[k]     : 0.f;
            float Bv = (k > 0)  ? Pv[k - 1] : 0.f;
            float val = (s_r[nl]*Av + Bv) * s_invd[nl] + bv;
            if (do_elu) val = (val > 0.f) ? val : expm1f(val);
            tile[nl][c] = val;
            mn = fminf(mn, val); mx = fmaxf(mx, val);
        }
    }
    __syncthreads();
    for (int i = tid; i < 512*16; i += 256) {
        int nl = i >> 4, c = i & 15;
        out[(size_t)(n0 + nl) * HG + gi0 + c] = tile[nl][c];
    }
    if (do_mm) {
        __shared__ float smn[256], smx[256];
        smn[tid] = mn; smx[tid] = mx; __syncthreads();
        for (int s = 128; s > 0; s >>= 1) {
            if (tid < s) {
                smn[tid] = fminf(smn[tid], smn[tid+s]);
                smx[tid] = fmaxf(smx[tid], smx[tid+s]);
            }
            __syncthreads();
        }
        if (tid == 0) {
            int bid = blockIdx.y * 16 + blockIdx.x;
            g_pmin[bid] = smn[0]; g_pmax[bid] = smx[0];
        }
    }
}

// ---------------- fused policy + value head (+ loss write) ----------------
__global__ void __launch_bounds__(256)
policyk(const float* __restrict__ A0, const float* __restrict__ A1,
        const float* __restrict__ Wa, const float* __restrict__ ba,
        const float* __restrict__ Wv, const float* __restrict__ bv,
        float* __restrict__ out_logp, float* __restrict__ out_value,
        float* __restrict__ out_loss)
{
    if (blockIdx.x == 0 && threadIdx.x == 0) out_loss[0] = (float)g_loss;
    __shared__ float As[16][68];
    __shared__ float Bs[16][68];
    __shared__ float Ss[64][65];
    int tid = threadIdx.x;
    int tx = tid % 16, ty = tid / 16;
    int row0 = blockIdx.x * 64;
    float acc[4][4] = {};
    float vacc = 0.f;

    for (int k0 = 0; k0 < 512; k0 += 16) {
        const float* Asrc = (k0 < 256) ? A0 : A1;
        int kb = (k0 < 256) ? k0 : k0 - 256;
        {
            int lin = tid * 4;
            int m = lin >> 4, kk = lin & 15;
            float4 v = *(const float4*)&Asrc[(size_t)(row0+m)*256 + kb + kk];
            As[kk+0][m] = v.x; As[kk+1][m] = v.y; As[kk+2][m] = v.z; As[kk+3][m] = v.w;
        }
        {
            int lin = tid * 4;
            int kk = lin >> 6, n = lin & 63;
            *(float4*)&Bs[kk][n] = *(const float4*)&Wa[(size_t)(k0+kk)*64 + n];
        }
        __syncthreads();
        #pragma unroll
        for (int kk = 0; kk < 16; kk++) {
            float a[4], bb[4];
            #pragma unroll
            for (int i = 0; i < 4; i++) a[i] = As[kk][ty*4+i];
            #pragma unroll
            for (int j = 0; j < 4; j++) bb[j] = Bs[kk][tx*4+j];
            #pragma unroll
            for (int i = 0; i < 4; i++)
                #pragma unroll
                for (int j = 0; j < 4; j++)
                    acc[i][j] = fmaf(a[i], bb[j], acc[i][j]);
        }
        if (tid < 64) {
            #pragma unroll
            for (int kk = 0; kk < 16; kk++)
                vacc = fmaf(As[kk][tid], Wv[k0+kk], vacc);
        }
        __syncthreads();
    }
    if (tid < 64) out_value[row0 + tid] = vacc + bv[0];

    #pragma unroll
    for (int i = 0; i < 4; i++)
        #pragma unroll
        for (int j = 0; j < 4; j++)
            Ss[ty*4+i][tx*4+j] = acc[i][j] + ba[tx*4+j];
    __syncthreads();

    int row = tid >> 2, quad = tid & 3;
    float m = -1e30f;
    #pragma unroll
    for (int c = 0; c < 16; c++) m = fmaxf(m, Ss[row][quad*16 + c]);
    m = fmaxf(m, __shfl_xor_sync(0xffffffffu, m, 1));
    m = fmaxf(m, __shfl_xor_sync(0xffffffffu, m, 2));
    float s = 0.f;
    #pragma unroll
    for (int c = 0; c < 16; c++) s += expf(Ss[row][quad*16 + c] - m);
    s += __shfl_xor_sync(0xffffffffu, s, 1);
    s += __shfl_xor_sync(0xffffffffu, s, 2);
    float lse = m + logf(s);
    #pragma unroll
    for (int c = 0; c < 16; c++)
        out_logp[(size_t)(row0+row)*64 + quad*16 + c] = Ss[row][quad*16 + c] - lse;
}

// ---------------- host ----------------
extern "C" void kernel_launch(void* const* d_in, const int* in_sizes, int n_in,
                              void* d_out, int out_size)
{
    const float* obs  = (const float*)d_in[0];
    const float* h0   = (const float*)d_in[1];
    const float* c0   = (const float*)d_in[2];
    const float* Wobs = (const float*)d_in[3];
    const float* bobs = (const float*)d_in[4];
    const float* Wih  = (const float*)d_in[5];
    const float* Whh  = (const float*)d_in[6];
    const float* bih  = (const float*)d_in[7];
    const float* bhh  = (const float*)d_in[8];
    const float* W1   = (const float*)d_in[9];
    const float* ai1  = (const float*)d_in[10];
    const float* aj1  = (const float*)d_in[11];
    const float* b1   = (const float*)d_in[12];
    const float* W2   = (const float*)d_in[13];
    const float* ai2  = (const float*)d_in[14];
    const float* aj2  = (const float*)d_in[15];
    const float* b2   = (const float*)d_in[16];
    const float* Wv   = (const float*)d_in[17];
    const float* bv   = (const float*)d_in[18];
    const float* Wa   = (const float*)d_in[19];
    const float* ba   = (const float*)d_in[20];

    float* out       = (float*)d_out;
    float* out_logp  = out;
    float* out_value = out + NA*ACT;
    float* out_h     = out_value + NA;
    float* out_c     = out_h + NA*HD;
    float* out_loss  = out_c + NA*HD;

    float *p_gates, *p_hWT, *p_comm1, *p_comm2, *p_bsum;
    __nv_bfloat16 *p_Ah, *p_Al, *p_A2h, *p_A2l;
    __nv_bfloat16 *p_B0h, *p_B0l, *p_Bgh, *p_Bgl, *p_B1h, *p_B1l, *p_B2h, *p_B2l;
    cudaGetSymbolAddress((void**)&p_gates,  g_gates);
    cudaGetSymbolAddress((void**)&p_hWT,    g_hWT);
    cudaGetSymbolAddress((void**)&p_comm1,  g_comm1);
    cudaGetSymbolAddress((void**)&p_comm2,  g_comm2);
    cudaGetSymbolAddress((void**)&p_bsum,   g_bsum);
    cudaGetSymbolAddress((void**)&p_Ah,     g_Ah);
    cudaGetSymbolAddress((void**)&p_Al,     g_Al);
    cudaGetSymbolAddress((void**)&p_A2h,    g_A2h);
    cudaGetSymbolAddress((void**)&p_A2l,    g_A2l);
    cudaGetSymbolAddress((void**)&p_B0h,    g_B0h);
    cudaGetSymbolAddress((void**)&p_B0l,    g_B0l);
    cudaGetSymbolAddress((void**)&p_Bgh,    g_Bgh);
    cudaGetSymbolAddress((void**)&p_Bgl,    g_Bgl);
    cudaGetSymbolAddress((void**)&p_B1h,    g_B1h);
    cudaGetSymbolAddress((void**)&p_B1l,    g_B1l);
    cudaGetSymbolAddress((void**)&p_B2h,    g_B2h);
    cudaGetSymbolAddress((void**)&p_B2l,    g_B2l);

    const int SM128 = (2*(2*128*TG_STRIDE + 2*128*TG_STRIDE)) * 2;
    const int SM64  = (2*(2*64*TG_STRIDE  + 2*128*TG_STRIDE)) * 2;
    cudaFuncSetAttribute((const void*)tgemm<128>, cudaFuncAttributeMaxDynamicSharedMemorySize, SM128);
    cudaFuncSetAttribute((const void*)tgemm<64>,  cudaFuncAttributeMaxDynamicSharedMemorySize, SM64);

    // 1. prep (also zeroes loss)
    wprep<<<(WP_S6 + 255)/256, 256>>>(obs, h0, Wobs, Wih, Whh, W1, W2, bih, bhh);
    // 2. enc GEMM -> split-bf16 into gates A operand (cols 0..255 of ld-512)
    tgemm<64><<<dim3(2, 64), 256, SM64>>>(p_A2h, p_A2l, p_B0h, p_B0l, bobs,
                                          nullptr, p_Ah, p_Al, 512,
                                          nullptr, nullptr, nullptr, 0, 256, 256);
    // 3. gates GEMM
    tgemm<128><<<dim3(8, 32), 256, SM128>>>(p_Ah, p_Al, p_Bgh, p_Bgl, p_bsum,
                                            p_gates, nullptr, nullptr, 0,
                                            nullptr, nullptr, nullptr, 0, 1024, 512);
    // 4. LSTM + min/max partials
    lstm_mm<<<MMB, 256>>>(p_gates, c0, out_h, out_c);
    // 5. quant #1 (zeroes ci/cj for GAT1)
    quant_split<<<MMB, 256>>>(out_h, p_Ah, p_Al, MMB);
    // 6. GAT1 projection -> transposed out + fused ci/cj
    tgemm<64><<<dim3(2, 64), 256, SM64>>>(p_Ah, p_Al, p_B1h, p_B1l, nullptr,
                                          nullptr, nullptr, nullptr, 0,
                                          p_hWT, ai1, aj1, 64, 256, 256);
    // 7-9. GAT1 attention
    sortk<<<4, 1024>>>();
    scank<<<4*64 + 4, 1024>>>(4, 64);
    combine2<<<dim3(16, 8), 256>>>(b1, p_comm1, 64, 1, 1);
    // 10. quant #2 (zeroes ci/cj for GAT2)
    quant_split<<<MMB, 256>>>(p_comm1, p_Ah, p_Al, 128);
    // 11. GAT2 projection
    tgemm<64><<<dim3(2, 64), 256, SM64>>>(p_Ah, p_Al, p_B2h, p_B2l, nullptr,
                                          nullptr, nullptr, nullptr, 0,
                                          p_hWT, ai2, aj2, 256, 256, 256);
    // 12-14. GAT2 attention
    sortk<<<1, 1024>>>();
    scank<<<1*256 + 1, 1024>>>(1, 256);
    combine2<<<dim3(16, 8), 256>>>(b2, p_comm2, 256, 0, 0);
    // 15. fused policy + value heads + loss write
    policyk<<<NA/64, 256>>>(out_h, p_comm2, Wa, ba, Wv, bv, out_logp, out_value, out_loss);
}

// round 8
// speedup vs baseline: 4.1948x; 1.0770x over previous
#include <cuda_runtime.h>
#include <cuda_bf16.h>
#include <math.h>
#include <stdint.h>

#define NA   4096
#define HD   256
#define HG   256
#define ACT  64
#define MMB  1024

// ---------------- device scratch ----------------
__device__ float g_hWT[HG*NA];
__device__ float g_commT[HG*NA];
__device__ float g_bsum[4*HD];
__device__ __nv_bfloat16 g_Ah[NA*512];
__device__ __nv_bfloat16 g_Al[NA*512];
__device__ __nv_bfloat16 g_A2h[NA*256];
__device__ __nv_bfloat16 g_A2l[NA*256];
__device__ __nv_bfloat16 g_B0h[256*256], g_B0l[256*256];
__device__ __nv_bfloat16 g_Bgh[1024*512], g_Bgl[1024*512];
__device__ __nv_bfloat16 g_B1h[256*256], g_B1l[256*256];
__device__ __nv_bfloat16 g_B2h[256*256], g_B2l[256*256];
__device__ float g_ci[4*NA];
__device__ float g_cj[4*NA];
__device__ int   g_kcount[4*NA];
__device__ int   g_sidx[4*NA];
__device__ float g_wA[4*NA];
__device__ float g_wB[4*NA];
__device__ float g_rn[4*NA];
__device__ float g_invd[4*NA];
__device__ float g_pmin[MMB];
__device__ float g_pmax[MMB];
__device__ double g_loss;

__device__ __forceinline__ void bf16split(float x, __nv_bfloat16* hi, __nv_bfloat16* lo) {
    __nv_bfloat16 h = __float2bfloat16(x);
    *hi = h;
    *lo = __float2bfloat16(x - __bfloat162float(h));
}

// ---------------- fused weight/input prep ----------------
// Gate weight rows are PERMUTED so gate cols interleave in blocks of 8:
// physical row r -> gate G=(r>>3)&3, unit u=((r>>5)<<3)|(r&7), orig row = G*256+u.
#define WP_S0 (NA*256)
#define WP_S1 (WP_S0 + NA*256)
#define WP_S2 (WP_S1 + 65536)
#define WP_S3 (WP_S2 + 524288)
#define WP_S4 (WP_S3 + 65536)
#define WP_S5 (WP_S4 + 65536)
#define WP_S6 (WP_S5 + 1024)
__global__ void wprep(const float* __restrict__ obs, const float* __restrict__ h0,
                      const float* __restrict__ Wobs,
                      const float* __restrict__ Wih, const float* __restrict__ Whh,
                      const float* __restrict__ W1, const float* __restrict__ W2,
                      const float* __restrict__ bih, const float* __restrict__ bhh)
{
    int idx = blockIdx.x*256 + threadIdx.x;
    if (idx == 0) g_loss = 0.0;
    if (idx < WP_S0) {
        bf16split(obs[idx], &g_A2h[idx], &g_A2l[idx]);
    } else if (idx < WP_S1) {
        int j = idx - WP_S0;
        int n = j >> 8, k = j & 255;
        int d = n*512 + 256 + k;
        bf16split(h0[j], &g_Ah[d], &g_Al[d]);
    } else if (idx < WP_S2) {
        int j = idx - WP_S1;
        int n = j >> 8, k = j & 255;
        bf16split(Wobs[k*256 + n], &g_B0h[j], &g_B0l[j]);
    } else if (idx < WP_S3) {
        int j = idx - WP_S2;
        int r = j >> 9, k = j & 511;
        int G = (r >> 3) & 3;
        int u = ((r >> 5) << 3) | (r & 7);
        int orow = G*256 + u;
        float x = (k < 256) ? Wih[orow*256 + k] : Whh[orow*256 + k - 256];
        bf16split(x, &g_Bgh[j], &g_Bgl[j]);
    } else if (idx < WP_S4) {
        int j = idx - WP_S3;
        int n = j >> 8, k = j & 255;
        bf16split(W1[k*256 + n], &g_B1h[j], &g_B1l[j]);
    } else if (idx < WP_S5) {
        int j = idx - WP_S4;
        int n = j >> 8, k = j & 255;
        bf16split(W2[k*256 + n], &g_B2h[j], &g_B2l[j]);
    } else if (idx < WP_S6) {
        int r = idx - WP_S5;
        int G = (r >> 3) & 3;
        int u = ((r >> 5) << 3) | (r & 7);
        int orow = G*256 + u;
        g_bsum[r] = bih[orow] + bhh[orow];
    }
}

// ---------------- mma.sync helpers ----------------
__device__ __forceinline__ uint32_t cvta_sm(const void* p) {
    uint32_t a;
    asm("{ .reg .u64 t; cvta.to.shared.u64 t, %1; cvt.u32.u64 %0, t; }" : "=r"(a) : "l"(p));
    return a;
}
__device__ __forceinline__ void ldm_x4(uint32_t (&d)[4], uint32_t addr) {
    asm volatile("ldmatrix.sync.aligned.m8n8.x4.shared.b16 {%0,%1,%2,%3}, [%4];"
        : "=r"(d[0]), "=r"(d[1]), "=r"(d[2]), "=r"(d[3]) : "r"(addr));
}
__device__ __forceinline__ void mma16816(float (&c)[4], const uint32_t (&a)[4],
                                         uint32_t b0, uint32_t b1) {
    asm volatile("mma.sync.aligned.m16n8k16.row.col.f32.bf16.bf16.f32 "
        "{%0,%1,%2,%3},{%4,%5,%6,%7},{%8,%9},{%0,%1,%2,%3};"
        : "+f"(c[0]), "+f"(c[1]), "+f"(c[2]), "+f"(c[3])
        : "r"(a[0]), "r"(a[1]), "r"(a[2]), "r"(a[3]), "r"(b0), "r"(b1));
}

// ---------------- split-bf16 tensor GEMM, cp.async 2-stage pipeline ----------
// D[M,N] = A[M,K]@B[N,K]^T (+bias). Output modes (each optional):
//   Shi/Slo : bf16 hi/lo split (ld ldS)
//   hwT+ai  : fp32 transposed + fused ci/cj atomics (head size Gh)
//   c0v     : LSTM epilogue (BM=128, interleaved gate cols) -> hOut,cOut + minmax
#define TG_STRIDE 40

template<int BM>
__global__ void __launch_bounds__(256, BM == 64 ? 2 : 1)
tgemm(const __nv_bfloat16* __restrict__ Ah, const __nv_bfloat16* __restrict__ Al,
      const __nv_bfloat16* __restrict__ Bh, const __nv_bfloat16* __restrict__ Bl,
      const float* __restrict__ bias,
      __nv_bfloat16* __restrict__ Shi, __nv_bfloat16* __restrict__ Slo, int ldS,
      float* __restrict__ hwT, const float* __restrict__ aivec,
      const float* __restrict__ ajvec, int Gh,
      const float* __restrict__ c0v, float* __restrict__ hOut, float* __restrict__ cOut,
      int N, int K)
{
    constexpr int A_ELE = BM * TG_STRIDE;
    constexpr int B_ELE = 128 * TG_STRIDE;
    constexpr int STAGE = 2*A_ELE + 2*B_ELE;
    constexpr int NWM  = BM / 32;
    constexpr int WN   = 128 / (8 / NWM);
    constexpr int NB16 = WN / 16;
    constexpr int NB   = WN / 8;
    constexpr int A_U4 = BM * 4;
    constexpr int B_U4 = 512;
    constexpr int TOT_U4 = 2*A_U4 + 2*B_U4;

    extern __shared__ __nv_bfloat16 sm[];
    int tid = threadIdx.x, lane = tid & 31, wid = tid >> 5;
    int col0 = blockIdx.x * 128, row0 = blockIdx.y * BM;
    int wm = (wid % NWM) * 32, wn = (wid / NWM) * WN;
    uint32_t sb = cvta_sm(sm);

    float acc[2][NB][4] = {};

    auto issue = [&](int stage, int k0) {
        uint32_t stb = sb + (uint32_t)stage * STAGE * 2;
        #pragma unroll
        for (int l = 0; l < TOT_U4/256; l++) {
            int i = tid + l * 256;
            const __nv_bfloat16* src;
            int r, c8;
            uint32_t soff;
            if (i < 2*A_U4) {
                int a = i / A_U4, j = i % A_U4;
                r = j >> 2; c8 = j & 3;
                src = (a ? Al : Ah) + (size_t)(row0 + r) * K;
                soff = (uint32_t)a * A_ELE;
            } else {
                int i2 = i - 2*A_U4;
                int a = i2 / B_U4, j = i2 % B_U4;
                r = j >> 2; c8 = j & 3;
                src = (a ? Bl : Bh) + (size_t)(col0 + r) * K;
                soff = 2*A_ELE + (uint32_t)a * B_ELE;
            }
            uint32_t dst = stb + (soff + r * TG_STRIDE + c8 * 8) * 2;
            const __nv_bfloat16* g = src + k0 + c8 * 8;
            asm volatile("cp.async.cg.shared.global [%0], [%1], 16;" :: "r"(dst), "l"(g));
        }
        asm volatile("cp.async.commit_group;" ::: "memory");
    };

    auto compute = [&](int stage) {
        uint32_t stb = sb + (uint32_t)stage * STAGE * 2;
        uint32_t bA_h = stb, bA_l = stb + A_ELE*2;
        uint32_t bB_h = stb + 2*A_ELE*2, bB_l = stb + (2*A_ELE + B_ELE)*2;
        #pragma unroll
        for (int kk = 0; kk < 32; kk += 16) {
            uint32_t ah[2][4], al[2][4];
            #pragma unroll
            for (int mb = 0; mb < 2; mb++) {
                int r = wm + mb * 16 + (lane & 15);
                int c = kk + (lane >> 4) * 8;
                uint32_t off = (uint32_t)(r * TG_STRIDE + c) * 2;
                ldm_x4(ah[mb], bA_h + off);
                ldm_x4(al[mb], bA_l + off);
            }
            #pragma unroll
            for (int nb = 0; nb < NB16; nb++) {
                int r = wn + nb * 16 + ((lane >> 4) << 3) + (lane & 7);
                int c = kk + ((lane >> 3) & 1) * 8;
                uint32_t off = (uint32_t)(r * TG_STRIDE + c) * 2;
                uint32_t bh[4], bl[4];
                ldm_x4(bh, bB_h + off);
                ldm_x4(bl, bB_l + off);
                #pragma unroll
                for (int mb = 0; mb < 2; mb++) {
                    mma16816(acc[mb][2*nb+0], ah[mb], bh[0], bh[1]);
                    mma16816(acc[mb][2*nb+1], ah[mb], bh[2], bh[3]);
                    mma16816(acc[mb][2*nb+0], ah[mb], bl[0], bl[1]);
                    mma16816(acc[mb][2*nb+1], ah[mb], bl[2], bl[3]);
                    mma16816(acc[mb][2*nb+0], al[mb], bh[0], bh[1]);
                    mma16816(acc[mb][2*nb+1], al[mb], bh[2], bh[3]);
                }
            }
        }
    };

    int nch = K >> 5;
    issue(0, 0);
    for (int ck = 0; ck < nch; ck++) {
        if (ck + 1 < nch) {
            issue((ck + 1) & 1, (ck + 1) << 5);
            asm volatile("cp.async.wait_group 1;" ::: "memory");
        } else {
            asm volatile("cp.async.wait_group 0;" ::: "memory");
        }
        __syncthreads();
        compute(ck & 1);
        __syncthreads();
    }

    int g = lane >> 2, tg = lane & 3;

    if constexpr (BM == 128) {
        if (c0v) {
            // LSTM epilogue: interleaved gate cols (blocks of 8: i,f,g,o)
            float mn = 1e30f, mx = -1e30f;
            #pragma unroll
            for (int mb = 0; mb < 2; mb++) {
                #pragma unroll
                for (int ug = 0; ug < 2; ug++) {
                    int cb = col0 + wn + ug*32;
                    int u0 = ((cb >> 5) << 3) + 2*tg;
                    float iv[4], fv[4], gv[4], ov[4];
                    #pragma unroll
                    for (int e = 0; e < 4; e++) {
                        int co = 2*tg + (e & 1);
                        iv[e] = acc[mb][ug*4+0][e] + bias[cb + 0  + co];
                        fv[e] = acc[mb][ug*4+1][e] + bias[cb + 8  + co];
                        gv[e] = acc[mb][ug*4+2][e] + bias[cb + 16 + co];
                        ov[e] = acc[mb][ug*4+3][e] + bias[cb + 24 + co];
                    }
                    #pragma unroll
                    for (int half = 0; half < 2; half++) {
                        int row = row0 + wm + mb*16 + g + half*8;
                        float2 cc = *(const float2*)(c0v + (size_t)row*256 + u0);
                        float cin[2] = {cc.x, cc.y};
                        float hh[2], c2[2];
                        #pragma unroll
                        for (int e2 = 0; e2 < 2; e2++) {
                            int e = half*2 + e2;
                            float si = 1.f/(1.f+expf(-iv[e]));
                            float sf = 1.f/(1.f+expf(-fv[e]));
                            float so = 1.f/(1.f+expf(-ov[e]));
                            c2[e2] = sf * cin[e2] + si * tanhf(gv[e]);
                            hh[e2] = so * tanhf(c2[e2]);
                            mn = fminf(mn, hh[e2]); mx = fmaxf(mx, hh[e2]);
                        }
                        *(float2*)(hOut + (size_t)row*256 + u0) = make_float2(hh[0], hh[1]);
                        *(float2*)(cOut + (size_t)row*256 + u0) = make_float2(c2[0], c2[1]);
                    }
                }
            }
            __shared__ float smn[256], smx[256];
            smn[tid] = mn; smx[tid] = mx; __syncthreads();
            for (int s = 128; s > 0; s >>= 1) {
                if (tid < s) {
                    smn[tid] = fminf(smn[tid], smn[tid+s]);
                    smx[tid] = fmaxf(smx[tid], smx[tid+s]);
                }
                __syncthreads();
            }
            if (tid == 0) {
                int bid = blockIdx.y * gridDim.x + blockIdx.x;
                g_pmin[bid] = smn[0]; g_pmax[bid] = smx[0];
            }
            return;
        }
    }

    float cia[2][2] = {}, cja[2][2] = {};
    #pragma unroll
    for (int mb = 0; mb < 2; mb++) {
        #pragma unroll
        for (int n8 = 0; n8 < NB; n8++) {
            int row = row0 + wm + mb * 16 + g;
            int col = col0 + wn + n8 * 8 + 2 * tg;
            float b0 = bias ? bias[col]   : 0.f;
            float b1 = bias ? bias[col+1] : 0.f;
            float v00 = acc[mb][n8][0] + b0, v01 = acc[mb][n8][1] + b1;
            float v10 = acc[mb][n8][2] + b0, v11 = acc[mb][n8][3] + b1;
            if (Shi) {
                size_t d0 = (size_t)row * ldS + col;
                size_t d1 = (size_t)(row + 8) * ldS + col;
                bf16split(v00, &Shi[d0],   &Slo[d0]);
                bf16split(v01, &Shi[d0+1], &Slo[d0+1]);
                bf16split(v10, &Shi[d1],   &Slo[d1]);
                bf16split(v11, &Shi[d1+1], &Slo[d1+1]);
            }
            if (hwT) {
                hwT[(size_t)col*NA + row]         = v00;
                hwT[(size_t)(col+1)*NA + row]     = v01;
                hwT[(size_t)col*NA + row + 8]     = v10;
                hwT[(size_t)(col+1)*NA + row + 8] = v11;
            }
            if (aivec) {
                float a0 = aivec[col], a1 = aivec[col+1];
                float j0 = ajvec[col], j1 = ajvec[col+1];
                cia[0][mb ? 1 : 0] += 0.f; // keep structure simple below
                cia[mb][0] += v00*a0 + v01*a1;
                cia[mb][1] += v10*a0 + v11*a1;
                cja[mb][0] += v00*j0 + v01*j1;
                cja[mb][1] += v10*j0 + v11*j1;
            }
        }
    }
    if (aivec) {
        int hh = (col0 + wn) / Gh;
        #pragma unroll
        for (int mb = 0; mb < 2; mb++) {
            #pragma unroll
            for (int hf = 0; hf < 2; hf++) {
                float ci = cia[mb][hf], cj = cja[mb][hf];
                ci += __shfl_xor_sync(0xffffffffu, ci, 1);
                ci += __shfl_xor_sync(0xffffffffu, ci, 2);
                cj += __shfl_xor_sync(0xffffffffu, cj, 1);
                cj += __shfl_xor_sync(0xffffffffu, cj, 2);
                if (tg == 0) {
                    int row = row0 + wm + mb * 16 + g + hf * 8;
                    atomicAdd(&g_ci[hh*NA + row], ci);
                    atomicAdd(&g_cj[hh*NA + row], cj);
                }
            }
        }
    }
}

// ---------------- fake-quant A: elementwise (h -> splits), zeroes ci/cj -------
__global__ void quantA(const float* __restrict__ x,
                       __nv_bfloat16* __restrict__ hi, __nv_bfloat16* __restrict__ lo,
                       int npart)
{
    int gt = blockIdx.x*256 + threadIdx.x;
    if (gt < 4*NA) { g_ci[gt] = 0.f; g_cj[gt] = 0.f; }

    __shared__ float smn[256], smx[256];
    __shared__ float sparam[2];
    float mn = 1e30f, mx = -1e30f;
    for (int i = threadIdx.x; i < npart; i += 256) {
        mn = fminf(mn, g_pmin[i]); mx = fmaxf(mx, g_pmax[i]);
    }
    smn[threadIdx.x] = mn; smx[threadIdx.x] = mx; __syncthreads();
    for (int s = 128; s > 0; s >>= 1) {
        if (threadIdx.x < s) {
            smn[threadIdx.x] = fminf(smn[threadIdx.x], smn[threadIdx.x+s]);
            smx[threadIdx.x] = fmaxf(smx[threadIdx.x], smx[threadIdx.x+s]);
        }
        __syncthreads();
    }
    if (threadIdx.x == 0) {
        float a = smn[0], b = smx[0];
        if (a == b) { a -= 0.01f; b += 0.01f; }
        float scale = (b - a) / 255.f;
        sparam[0] = scale;
        sparam[1] = rintf(-a / scale);
    }
    __syncthreads();
    float scale = sparam[0], zp = sparam[1];

    double part = 0.0;
    int i = blockIdx.x*256 + threadIdx.x;
    {
        float4 t = ((const float4*)x)[i];
        float ts[4] = {t.x, t.y, t.z, t.w};
        float ds[4];
        #pragma unroll
        for (int q = 0; q < 4; q++) {
            float r = rintf(ts[q]/scale + zp);
            r = fminf(fmaxf(r, 0.f), 255.f);
            float d = (r - zp) * scale;
            ds[q] = d;
            part += (double)log2f(510.f * fabsf(d) + 1.f);
        }
        __nv_bfloat162 h01, h23, l01, l23;
        __nv_bfloat16 hh, ll;
        bf16split(ds[0], &hh, &ll); h01.x = hh; l01.x = ll;
        bf16split(ds[1], &hh, &ll); h01.y = hh; l01.y = ll;
        bf16split(ds[2], &hh, &ll); h23.x = hh; l23.x = ll;
        bf16split(ds[3], &hh, &ll); h23.y = hh; l23.y = ll;
        ((__nv_bfloat162*)hi)[i*2]   = h01;
        ((__nv_bfloat162*)hi)[i*2+1] = h23;
        ((__nv_bfloat162*)lo)[i*2]   = l01;
        ((__nv_bfloat162*)lo)[i*2+1] = l23;
    }
    __shared__ double sd[256];
    sd[threadIdx.x] = part; __syncthreads();
    for (int s = 128; s > 0; s >>= 1) { if (threadIdx.x < s) sd[threadIdx.x] += sd[threadIdx.x+s]; __syncthreads(); }
    if (threadIdx.x == 0) atomicAdd(&g_loss, sd[0]);
}

// ---------------- fake-quant T: transpose 32x32 (commT -> row-major splits) ---
__global__ void quantT(const float* __restrict__ inT,
                       __nv_bfloat16* __restrict__ hi, __nv_bfloat16* __restrict__ lo,
                       int npart)
{
    __shared__ float tile[32][33];
    __shared__ float smn[256], smx[256];
    __shared__ float sparam[2];
    int tx = threadIdx.x, ty = threadIdx.y;
    int tid = ty*32 + tx;

    float mn = (tid < npart) ? g_pmin[tid] : 1e30f;
    float mx = (tid < npart) ? g_pmax[tid] : -1e30f;
    smn[tid] = mn; smx[tid] = mx; __syncthreads();
    for (int s = 128; s > 0; s >>= 1) {
        if (tid < s) {
            smn[tid] = fminf(smn[tid], smn[tid+s]);
            smx[tid] = fmaxf(smx[tid], smx[tid+s]);
        }
        __syncthreads();
    }
    if (tid == 0) {
        float a = smn[0], b = smx[0];
        if (a == b) { a -= 0.01f; b += 0.01f; }
        float scale = (b - a) / 255.f;
        sparam[0] = scale;
        sparam[1] = rintf(-a / scale);
    }
    __syncthreads();
    float scale = sparam[0], zp = sparam[1];

    int n0 = blockIdx.x * 32, c0 = blockIdx.y * 32;
    double part = 0.0;
    for (int cc = ty; cc < 32; cc += 8) {
        float t = inT[(size_t)(c0+cc)*NA + n0 + tx];
        float r = rintf(t/scale + zp);
        r = fminf(fmaxf(r, 0.f), 255.f);
        float d = (r - zp) * scale;
        tile[cc][tx] = d;
        part += (double)log2f(510.f * fabsf(d) + 1.f);
    }
    __syncthreads();
    for (int nn = ty; nn < 32; nn += 8) {
        float d = tile[tx][nn];
        size_t o = (size_t)(n0+nn)*256 + c0 + tx;
        bf16split(d, &hi[o], &lo[o]);
    }
    __shared__ double sd[256];
    sd[tid] = part; __syncthreads();
    for (int s = 128; s > 0; s >>= 1) { if (tid < s) sd[tid] += sd[tid+s]; __syncthreads(); }
    if (tid == 0) atomicAdd(&g_loss, sd[0]);
}

// ---------------- sortk: bitonic + weights + scalar scans + per-n denom -------
__global__ void __launch_bounds__(1024)
sortk()
{
    extern __shared__ char sms[];
    float* key = (float*)sms;                 // NA floats
    int*   idx = (int*)(key + NA);            // NA ints
    float* sA  = (float*)(idx + NA);          // suffix scan of wA
    float* sB  = sA + NA;                     // prefix scan of wB
    __shared__ float wsum[32];
    int h = blockIdx.x;
    int tid = threadIdx.x, lane = tid & 31, warp = tid >> 5;

    for (int i = tid; i < NA; i += 1024) { key[i] = g_cj[h*NA + i]; idx[i] = i; }
    __syncthreads();
    for (int k = 2; k <= NA; k <<= 1) {
        for (int j = k >> 1; j > 0; j >>= 1) {
            #pragma unroll 2
            for (int p = tid; p < NA/2; p += 1024) {
                int i = ((p & ~(j-1)) << 1) | (p & (j-1));
                int l = i | j;
                bool up = ((i & k) == 0);
                float a = key[i], b = key[l];
                if (up ? (a > b) : (a < b)) {
                    key[i] = b; key[l] = a;
                    int tmp = idx[i]; idx[i] = idx[l]; idx[l] = tmp;
                }
            }
            __syncthreads();
        }
    }
    float cm = key[NA-1];

    int t0 = tid * 4;
    // weights + store perm/weights
    float kw0 = key[t0], kw1 = key[t0+1], kw2 = key[t0+2], kw3 = key[t0+3];
    float wB0 = expf(0.2f*(kw0-cm)), wB1 = expf(0.2f*(kw1-cm));
    float wB2 = expf(0.2f*(kw2-cm)), wB3 = expf(0.2f*(kw3-cm));
    float wA0 = expf(kw0-cm), wA1 = expf(kw1-cm), wA2 = expf(kw2-cm), wA3 = expf(kw3-cm);
    *(int4*)&g_sidx[h*NA + t0] = make_int4(idx[t0], idx[t0+1], idx[t0+2], idx[t0+3]);
    *(float4*)&g_wA[h*NA + t0] = make_float4(wA0, wA1, wA2, wA3);
    *(float4*)&g_wB[h*NA + t0] = make_float4(wB0, wB1, wB2, wB3);

    // prefix scan of wB -> sB
    {
        float v0 = wB0, v1 = v0+wB1, v2 = v1+wB2, v3 = v2+wB3;
        float tot = v3, s = tot;
        #pragma unroll
        for (int o = 1; o < 32; o <<= 1) { float u = __shfl_up_sync(0xffffffffu, s, o); if (lane >= o) s += u; }
        if (lane == 31) wsum[warp] = s;
        __syncthreads();
        if (warp == 0) {
            float y = wsum[lane];
            #pragma unroll
            for (int o = 1; o < 32; o <<= 1) { float u = __shfl_up_sync(0xffffffffu, y, o); if (lane >= o) y += u; }
            wsum[lane] = y;
        }
        __syncthreads();
        float off = (warp ? wsum[warp-1] : 0.f) + (s - tot);
        sB[t0] = off+v0; sB[t0+1] = off+v1; sB[t0+2] = off+v2; sB[t0+3] = off+v3;
    }
    __syncthreads();
    // suffix scan of wA -> sA (reversed-order prefix)
    {
        int rb = NA - 4 - t0;
        float a0 = expf(key[rb]-cm),   a1 = expf(key[rb+1]-cm);
        float a2 = expf(key[rb+2]-cm), a3 = expf(key[rb+3]-cm);
        float u0 = a3, u1 = u0+a2, u2 = u1+a1, u3 = u2+a0;
        float tot = u3, s = tot;
        #pragma unroll
        for (int o = 1; o < 32; o <<= 1) { float u = __shfl_up_sync(0xffffffffu, s, o); if (lane >= o) s += u; }
        if (lane == 31) wsum[warp] = s;
        __syncthreads();
        if (warp == 0) {
            float y = wsum[lane];
            #pragma unroll
            for (int o = 1; o < 32; o <<= 1) { float u = __shfl_up_sync(0xffffffffu, y, o); if (lane >= o) y += u; }
            wsum[lane] = y;
        }
        __syncthreads();
        float off = (warp ? wsum[warp-1] : 0.f) + (s - tot);
        sA[rb] = off+u3; sA[rb+1] = off+u2; sA[rb+2] = off+u1; sA[rb+3] = off+u0;
    }
    __syncthreads();

    // per-n: bsearch + r + 1/denom; zero ci/cj for next projection
    for (int l = 0; l < 4; l++) {
        int n = tid + l*1024;
        float cin = g_ci[h*NA + n];
        float t = -cin;
        int lo = 0, hi = NA;
        while (lo < hi) {
            int mid = (lo + hi) >> 1;
            if (key[mid] <= t) lo = mid + 1; else hi = mid;
        }
        float r = expf(0.8f * (cin + cm));
        float A = (lo < NA) ? sA[lo]     : 0.f;
        float B = (lo > 0)  ? sB[lo - 1] : 0.f;
        g_kcount[h*NA + n] = lo;
        g_rn[h*NA + n]     = r;
        g_invd[h*NA + n]   = 1.f / (r*A + B);
        g_ci[h*NA + n] = 0.f;
        g_cj[h*NA + n] = 0.f;
    }
}

// ---------------- scomb: per-column scan (smem) + direct output (transposed) --
__global__ void __launch_bounds__(1024)
scomb(const float* __restrict__ bias, float* __restrict__ outT,
      int G, int do_elu, int do_mm)
{
    __shared__ float s_pre[NA];
    __shared__ float s_suf[NA];
    __shared__ float wsum[32];
    int c = blockIdx.x;
    int h = c / G;
    int tid = threadIdx.x, lane = tid & 31, warp = tid >> 5;
    int t0 = tid * 4;
    const float* xrow = g_hWT + (size_t)c * NA;

    // prefix of wB*x
    {
        int4 iv = *(const int4*)&g_sidx[h*NA + t0];
        float4 w4 = *(const float4*)&g_wB[h*NA + t0];
        float x0 = xrow[iv.x], x1 = xrow[iv.y], x2 = xrow[iv.z], x3 = xrow[iv.w];
        float v0 = w4.x*x0, v1 = v0 + w4.y*x1, v2 = v1 + w4.z*x2, v3 = v2 + w4.w*x3;
        float tot = v3, s = tot;
        #pragma unroll
        for (int o = 1; o < 32; o <<= 1) { float u = __shfl_up_sync(0xffffffffu, s, o); if (lane >= o) s += u; }
        if (lane == 31) wsum[warp] = s;
        __syncthreads();
        if (warp == 0) {
            float y = wsum[lane];
            #pragma unroll
            for (int o = 1; o < 32; o <<= 1) { float u = __shfl_up_sync(0xffffffffu, y, o); if (lane >= o) y += u; }
            wsum[lane] = y;
        }
        __syncthreads();
        float off = (warp ? wsum[warp-1] : 0.f) + (s - tot);
        s_pre[t0] = off+v0; s_pre[t0+1] = off+v1; s_pre[t0+2] = off+v2; s_pre[t0+3] = off+v3;
    }
    __syncthreads();
    // suffix of wA*x
    {
        int rb = NA - 4 - t0;
        int4 iv = *(const int4*)&g_sidx[h*NA + rb];
        float4 wa = *(const float4*)&g_wA[h*NA + rb];
        float y0 = xrow[iv.x], y1 = xrow[iv.y], y2 = xrow[iv.z], y3 = xrow[iv.w];
        float u0 = wa.w*y3, u1 = u0 + wa.z*y2, u2 = u1 + wa.y*y1, u3 = u2 + wa.x*y0;
        float tot = u3, s = tot;
        #pragma unroll
        for (int o = 1; o < 32; o <<= 1) { float u = __shfl_up_sync(0xffffffffu, s, o); if (lane >= o) s += u; }
        if (lane == 31) wsum[warp] = s;
        __syncthreads();
        if (warp == 0) {
            float y = wsum[lane];
            #pragma unroll
            for (int o = 1; o < 32; o <<= 1) { float u = __shfl_up_sync(0xffffffffu, y, o); if (lane >= o) y += u; }
            wsum[lane] = y;
        }
        __syncthreads();
        float off = (warp ? wsum[warp-1] : 0.f) + (s - tot);
        s_suf[rb] = off+u3; s_suf[rb+1] = off+u2; s_suf[rb+2] = off+u1; s_suf[rb+3] = off+u0;
    }
    __syncthreads();

    float bv = bias[c];
    float mn = 1e30f, mx = -1e30f;
    #pragma unroll
    for (int l = 0; l < 4; l++) {
        int n = tid + l*1024;
        int k = g_kcount[h*NA + n];
        float r = g_rn[h*NA + n];
        float invd = g_invd[h*NA + n];
        float Av = (k < NA) ? s_suf[k]     : 0.f;
        float Bv = (k > 0)  ? s_pre[k - 1] : 0.f;
        float val = (r*Av + Bv) * invd + bv;
        if (do_elu) val = (val > 0.f) ? val : expm1f(val);
        mn = fminf(mn, val); mx = fmaxf(mx, val);
        outT[(size_t)c*NA + n] = val;
    }
    if (do_mm) {
        __shared__ float smn[1024], smx[1024];
        smn[tid] = mn; smx[tid] = mx; __syncthreads();
        for (int s = 512; s > 0; s >>= 1) {
            if (tid < s) {
                smn[tid] = fminf(smn[tid], smn[tid+s]);
                smx[tid] = fmaxf(smx[tid], smx[tid+s]);
            }
            __syncthreads();
        }
        if (tid == 0) { g_pmin[c] = smn[0]; g_pmax[c] = smx[0]; }
    }
}

// ---------------- fused policy + value head (+ loss write) ----------------
// A0 row-major [n,256]; A1T transposed [c, n] (comm2T).
__global__ void __launch_bounds__(256)
policyk(const float* __restrict__ A0, const float* __restrict__ A1T,
        const float* __restrict__ Wa, const float* __restrict__ ba,
        const float* __restrict__ Wv, const float* __restrict__ bv,
        float* __restrict__ out_logp, float* __restrict__ out_value,
        float* __restrict__ out_loss)
{
    if (blockIdx.x == 0 && threadIdx.x == 0) out_loss[0] = (float)g_loss;
    __shared__ float As[16][68];
    __shared__ float Bs[16][68];
    __shared__ float Ss[64][65];
    int tid = threadIdx.x;
    int tx = tid % 16, ty = tid / 16;
    int row0 = blockIdx.x * 64;
    float acc[4][4] = {};
    float vacc = 0.f;

    for (int k0 = 0; k0 < 512; k0 += 16) {
        if (k0 < 256) {
            int lin = tid * 4;
            int m = lin >> 4, kk = lin & 15;
            float4 v = *(const float4*)&A0[(size_t)(row0+m)*256 + k0 + kk];
            As[kk+0][m] = v.x; As[kk+1][m] = v.y; As[kk+2][m] = v.z; As[kk+3][m] = v.w;
        } else {
            int lin = tid * 4;
            int kk = lin >> 6, m4 = lin & 63;
            float4 v = *(const float4*)&A1T[(size_t)(k0-256+kk)*NA + row0 + m4];
            *(float4*)&As[kk][m4] = v;
        }
        {
            int lin = tid * 4;
            int kk = lin >> 6, n = lin & 63;
            *(float4*)&Bs[kk][n] = *(const float4*)&Wa[(size_t)(k0+kk)*64 + n];
        }
        __syncthreads();
        #pragma unroll
        for (int kk = 0; kk < 16; kk++) {
            float a[4], bb[4];
            #pragma unroll
            for (int i = 0; i < 4; i++) a[i] = As[kk][ty*4+i];
            #pragma unroll
            for (int j = 0; j < 4; j++) bb[j] = Bs[kk][tx*4+j];
            #pragma unroll
            for (int i = 0; i < 4; i++)
                #pragma unroll
                for (int j = 0; j < 4; j++)
                    acc[i][j] = fmaf(a[i], bb[j], acc[i][j]);
        }
        if (tid < 64) {
            #pragma unroll
            for (int kk = 0; kk < 16; kk++)
                vacc = fmaf(As[kk][tid], Wv[k0+kk], vacc);
        }
        __syncthreads();
    }
    if (tid < 64) out_value[row0 + tid] = vacc + bv[0];

    #pragma unroll
    for (int i = 0; i < 4; i++)
        #pragma unroll
        for (int j = 0; j < 4; j++)
            Ss[ty*4+i][tx*4+j] = acc[i][j] + ba[tx*4+j];
    __syncthreads();

    int row = tid >> 2, quad = tid & 3;
    float m = -1e30f;
    #pragma unroll
    for (int c = 0; c < 16; c++) m = fmaxf(m, Ss[row][quad*16 + c]);
    m = fmaxf(m, __shfl_xor_sync(0xffffffffu, m, 1));
    m = fmaxf(m, __shfl_xor_sync(0xffffffffu, m, 2));
    float s = 0.f;
    #pragma unroll
    for (int c = 0; c < 16; c++) s += expf(Ss[row][quad*16 + c] - m);
    s += __shfl_xor_sync(0xffffffffu, s, 1);
    s += __shfl_xor_sync(0xffffffffu, s, 2);
    float lse = m + logf(s);
    #pragma unroll
    for (int c = 0; c < 16; c++)
        out_logp[(size_t)(row0+row)*64 + quad*16 + c] = Ss[row][quad*16 + c] - lse;
}

// ---------------- host ----------------
extern "C" void kernel_launch(void* const* d_in, const int* in_sizes, int n_in,
                              void* d_out, int out_size)
{
    const float* obs  = (const float*)d_in[0];
    const float* h0   = (const float*)d_in[1];
    const float* c0   = (const float*)d_in[2];
    const float* Wobs = (const float*)d_in[3];
    const float* bobs = (const float*)d_in[4];
    const float* Wih  = (const float*)d_in[5];
    const float* Whh  = (const float*)d_in[6];
    const float* bih  = (const float*)d_in[7];
    const float* bhh  = (const float*)d_in[8];
    const float* W1   = (const float*)d_in[9];
    const float* ai1  = (const float*)d_in[10];
    const float* aj1  = (const float*)d_in[11];
    const float* b1   = (const float*)d_in[12];
    const float* W2   = (const float*)d_in[13];
    const float* ai2  = (const float*)d_in[14];
    const float* aj2  = (const float*)d_in[15];
    const float* b2   = (const float*)d_in[16];
    const float* Wv   = (const float*)d_in[17];
    const float* bv   = (const float*)d_in[18];
    const float* Wa   = (const float*)d_in[19];
    const float* ba   = (const float*)d_in[20];

    float* out       = (float*)d_out;
    float* out_logp  = out;
    float* out_value = out + NA*ACT;
    float* out_h     = out_value + NA;
    float* out_c     = out_h + NA*HD;
    float* out_loss  = out_c + NA*HD;

    float *p_hWT, *p_commT, *p_bsum;
    __nv_bfloat16 *p_Ah, *p_Al, *p_A2h, *p_A2l;
    __nv_bfloat16 *p_B0h, *p_B0l, *p_Bgh, *p_Bgl, *p_B1h, *p_B1l, *p_B2h, *p_B2l;
    cudaGetSymbolAddress((void**)&p_hWT,    g_hWT);
    cudaGetSymbolAddress((void**)&p_commT,  g_commT);
    cudaGetSymbolAddress((void**)&p_bsum,   g_bsum);
    cudaGetSymbolAddress((void**)&p_Ah,     g_Ah);
    cudaGetSymbolAddress((void**)&p_Al,     g_Al);
    cudaGetSymbolAddress((void**)&p_A2h,    g_A2h);
    cudaGetSymbolAddress((void**)&p_A2l,    g_A2l);
    cudaGetSymbolAddress((void**)&p_B0h,    g_B0h);
    cudaGetSymbolAddress((void**)&p_B0l,    g_B0l);
    cudaGetSymbolAddress((void**)&p_Bgh,    g_Bgh);
    cudaGetSymbolAddress((void**)&p_Bgl,    g_Bgl);
    cudaGetSymbolAddress((void**)&p_B1h,    g_B1h);
    cudaGetSymbolAddress((void**)&p_B1l,    g_B1l);
    cudaGetSymbolAddress((void**)&p_B2h,    g_B2h);
    cudaGetSymbolAddress((void**)&p_B2l,    g_B2l);

    const int SM128 = (2*(2*128*TG_STRIDE + 2*128*TG_STRIDE)) * 2;
    const int SM64  = (2*(2*64*TG_STRIDE  + 2*128*TG_STRIDE)) * 2;
    const int SMSORT = NA * 16;   // key + idx + sA + sB = 64 KB
    cudaFuncSetAttribute((const void*)tgemm<128>, cudaFuncAttributeMaxDynamicSharedMemorySize, SM128);
    cudaFuncSetAttribute((const void*)tgemm<64>,  cudaFuncAttributeMaxDynamicSharedMemorySize, SM64);
    cudaFuncSetAttribute((const void*)sortk,      cudaFuncAttributeMaxDynamicSharedMemorySize, SMSORT);

    // 1. prep (zeroes loss; permutes gate weights)
    wprep<<<(WP_S6 + 255)/256, 256>>>(obs, h0, Wobs, Wih, Whh, W1, W2, bih, bhh);
    // 2. enc GEMM -> split into gates A (cols 0..255 of ld-512)
    tgemm<64><<<dim3(2, 64), 256, SM64>>>(p_A2h, p_A2l, p_B0h, p_B0l, bobs,
                                          p_Ah, p_Al, 512,
                                          nullptr, nullptr, nullptr, 0,
                                          nullptr, nullptr, nullptr, 256, 256);
    // 3. gates GEMM + fused LSTM -> out_h, out_c, minmax[256]
    tgemm<128><<<dim3(8, 32), 256, SM128>>>(p_Ah, p_Al, p_Bgh, p_Bgl, p_bsum,
                                            nullptr, nullptr, 0,
                                            nullptr, nullptr, nullptr, 0,
                                            c0, out_h, out_c, 1024, 512);
    // 4. quant #1 (elementwise; zeroes ci/cj)
    quantA<<<MMB, 256>>>(out_h, p_Ah, p_Al, 256);
    // 5. GAT1 projection -> hWT + fused ci/cj
    tgemm<64><<<dim3(2, 64), 256, SM64>>>(p_Ah, p_Al, p_B1h, p_B1l, nullptr,
                                          nullptr, nullptr, 0,
                                          p_hWT, ai1, aj1, 64,
                                          nullptr, nullptr, nullptr, 256, 256);
    // 6-7. GAT1 attention
    sortk<<<4, 1024, SMSORT>>>();
    scomb<<<256, 1024>>>(b1, p_commT, 64, 1, 1);
    // 8. quant #2 (transpose; splits row-major)
    quantT<<<dim3(NA/32, 8), dim3(32, 8)>>>(p_commT, p_Ah, p_Al, 256);
    // 9. GAT2 projection
    tgemm<64><<<dim3(2, 64), 256, SM64>>>(p_Ah, p_Al, p_B2h, p_B2l, nullptr,
                                          nullptr, nullptr, 0,
                                          p_hWT, ai2, aj2, 256,
                                          nullptr, nullptr, nullptr, 256, 256);
    // 10-11. GAT2 attention
    sortk<<<1, 1024, SMSORT>>>();
    scomb<<<256, 1024>>>(b2, p_commT, 256, 0, 0);
    // 12. fused policy + value heads + loss
    policyk<<<NA/64, 256>>>(out_h, p_commT, Wa, ba, Wv, bv, out_logp, out_value, out_loss);
}

// round 9
// speedup vs baseline: 4.3369x; 1.0339x over previous
#include <cuda_runtime.h>
#include <cuda_bf16.h>
#include <math.h>
#include <stdint.h>

#define NA   4096
#define HD   256
#define HG   256
#define ACT  64
#define MMB  1024

// ---------------- device scratch ----------------
__device__ float g_hWT[HG*NA];
__device__ float g_commT[HG*NA];
__device__ float g_bsum[4*HD];
__device__ __nv_bfloat16 g_Ah[NA*512];       // [obs | h0] gates A (ld 512)
__device__ __nv_bfloat16 g_Al[NA*512];
__device__ __nv_bfloat16 g_A2h[NA*256];      // Wih perm split (wgemm A) / quant splits
__device__ __nv_bfloat16 g_A2l[NA*256];
__device__ __nv_bfloat16 g_B0h[256*256], g_B0l[256*256];    // Wobs raw
__device__ __nv_bfloat16 g_Bgh[1024*512], g_Bgl[1024*512];  // [Wobs*Wih^T | Whh] perm
__device__ __nv_bfloat16 g_B1h[256*256], g_B1l[256*256];    // W1^T
__device__ __nv_bfloat16 g_B2h[256*256], g_B2l[256*256];    // W2^T
__device__ float g_ci[4*NA];
__device__ float g_cj[4*NA];
__device__ int   g_kcount[4*NA];
__device__ int   g_sidx[4*NA];
__device__ float g_wA[4*NA];
__device__ float g_wB[4*NA];
__device__ float g_rn[4*NA];
__device__ float g_invd[4*NA];
__device__ float g_pmin[MMB];
__device__ float g_pmax[MMB];
__device__ double g_loss;

__device__ __forceinline__ void bf16split(float x, __nv_bfloat16* hi, __nv_bfloat16* lo) {
    __nv_bfloat16 h = __float2bfloat16(x);
    *hi = h;
    *lo = __float2bfloat16(x - __bfloat162float(h));
}

// ---------------- fused prep: splits, permutes, bias dots, zeroing -----------
// gate-permutation: physical row r -> gate G=(r>>3)&3, unit u=((r>>5)<<3)|(r&7)
#define WQ0 (NA*256)             // obs -> Ah cols 0..255
#define WQ1 (WQ0 + NA*256)       // h0 -> Ah cols 256..511
#define WQ2 (WQ1 + 65536)        // Wobs raw -> B0
#define WQ3 (WQ2 + 262144)       // Wih perm -> A2
#define WQ4 (WQ3 + 262144)       // Whh perm -> Bg cols 256..511
#define WQ5 (WQ4 + 65536)        // W1^T -> B1
#define WQ6 (WQ5 + 65536)        // W2^T -> B2
#define WQ7 (WQ6 + 16384)        // zero ci/cj
#define WQ8 (WQ7 + 32768)        // bsum warp dots (1024 rows x 32 lanes)
__global__ void wprep(const float* __restrict__ obs, const float* __restrict__ h0,
                      const float* __restrict__ Wobs,
                      const float* __restrict__ Wih, const float* __restrict__ Whh,
                      const float* __restrict__ W1, const float* __restrict__ W2,
                      const float* __restrict__ bih, const float* __restrict__ bhh,
                      const float* __restrict__ bobs)
{
    int idx = blockIdx.x*256 + threadIdx.x;
    if (idx == 0) g_loss = 0.0;
    if (idx < WQ0) {
        int n = idx >> 8, k = idx & 255;
        int d = n*512 + k;
        bf16split(obs[idx], &g_Ah[d], &g_Al[d]);
    } else if (idx < WQ1) {
        int j = idx - WQ0;
        int n = j >> 8, k = j & 255;
        int d = n*512 + 256 + k;
        bf16split(h0[j], &g_Ah[d], &g_Al[d]);
    } else if (idx < WQ2) {
        int j = idx - WQ1;
        bf16split(Wobs[j], &g_B0h[j], &g_B0l[j]);
    } else if (idx < WQ3) {
        int j = idx - WQ2;
        int r = j >> 8, k = j & 255;
        int G = (r >> 3) & 3;
        int u = ((r >> 5) << 3) | (r & 7);
        bf16split(Wih[(G*256 + u)*256 + k], &g_A2h[j], &g_A2l[j]);
    } else if (idx < WQ4) {
        int j = idx - WQ3;
        int r = j >> 8, k = j & 255;
        int G = (r >> 3) & 3;
        int u = ((r >> 5) << 3) | (r & 7);
        int d = r*512 + 256 + k;
        bf16split(Whh[(G*256 + u)*256 + k], &g_Bgh[d], &g_Bgl[d]);
    } else if (idx < WQ5) {
        int j = idx - WQ4;
        int n = j >> 8, k = j & 255;
        bf16split(W1[k*256 + n], &g_B1h[j], &g_B1l[j]);
    } else if (idx < WQ6) {
        int j = idx - WQ5;
        int n = j >> 8, k = j & 255;
        bf16split(W2[k*256 + n], &g_B2h[j], &g_B2l[j]);
    } else if (idx < WQ7) {
        int j = idx - WQ6;
        g_ci[j] = 0.f; g_cj[j] = 0.f;
    } else if (idx < WQ8) {
        int t = idx - WQ7;
        int r = t >> 5, lane = t & 31;
        int G = (r >> 3) & 3;
        int u = ((r >> 5) << 3) | (r & 7);
        int orow = G*256 + u;
        float s = 0.f;
        #pragma unroll
        for (int k = lane; k < 256; k += 32)
            s = fmaf(bobs[k], Wih[orow*256 + k], s);
        for (int o = 16; o > 0; o >>= 1) s += __shfl_down_sync(0xffffffffu, s, o);
        if (lane == 0) g_bsum[r] = s + bih[orow] + bhh[orow];
    }
}

// ---------------- mma.sync helpers ----------------
__device__ __forceinline__ uint32_t cvta_sm(const void* p) {
    uint32_t a;
    asm("{ .reg .u64 t; cvta.to.shared.u64 t, %1; cvt.u32.u64 %0, t; }" : "=r"(a) : "l"(p));
    return a;
}
__device__ __forceinline__ void ldm_x4(uint32_t (&d)[4], uint32_t addr) {
    asm volatile("ldmatrix.sync.aligned.m8n8.x4.shared.b16 {%0,%1,%2,%3}, [%4];"
        : "=r"(d[0]), "=r"(d[1]), "=r"(d[2]), "=r"(d[3]) : "r"(addr));
}
__device__ __forceinline__ void mma16816(float (&c)[4], const uint32_t (&a)[4],
                                         uint32_t b0, uint32_t b1) {
    asm volatile("mma.sync.aligned.m16n8k16.row.col.f32.bf16.bf16.f32 "
        "{%0,%1,%2,%3},{%4,%5,%6,%7},{%8,%9},{%0,%1,%2,%3};"
        : "+f"(c[0]), "+f"(c[1]), "+f"(c[2]), "+f"(c[3])
        : "r"(a[0]), "r"(a[1]), "r"(a[2]), "r"(a[3]), "r"(b0), "r"(b1));
}

// ---------------- split-bf16 tensor GEMM, cp.async 2-stage pipeline ----------
#define TG_STRIDE 40

template<int BM>
__global__ void __launch_bounds__(256, BM == 64 ? 2 : 1)
tgemm(const __nv_bfloat16* __restrict__ Ah, const __nv_bfloat16* __restrict__ Al,
      const __nv_bfloat16* __restrict__ Bh, const __nv_bfloat16* __restrict__ Bl,
      const float* __restrict__ bias,
      __nv_bfloat16* __restrict__ Shi, __nv_bfloat16* __restrict__ Slo, int ldS,
      float* __restrict__ hwT, const float* __restrict__ aivec,
      const float* __restrict__ ajvec, int Gh,
      const float* __restrict__ c0v, float* __restrict__ hOut, float* __restrict__ cOut,
      int N, int K)
{
    constexpr int A_ELE = BM * TG_STRIDE;
    constexpr int B_ELE = 128 * TG_STRIDE;
    constexpr int STAGE = 2*A_ELE + 2*B_ELE;
    constexpr int NWM  = BM / 32;
    constexpr int WN   = 128 / (8 / NWM);
    constexpr int NB16 = WN / 16;
    constexpr int NB   = WN / 8;
    constexpr int A_U4 = BM * 4;
    constexpr int B_U4 = 512;
    constexpr int TOT_U4 = 2*A_U4 + 2*B_U4;

    extern __shared__ __nv_bfloat16 sm[];
    int tid = threadIdx.x, lane = tid & 31, wid = tid >> 5;
    int col0 = blockIdx.x * 128, row0 = blockIdx.y * BM;
    int wm = (wid % NWM) * 32, wn = (wid / NWM) * WN;
    uint32_t sb = cvta_sm(sm);

    float acc[2][NB][4] = {};

    auto issue = [&](int stage, int k0) {
        uint32_t stb = sb + (uint32_t)stage * STAGE * 2;
        #pragma unroll
        for (int l = 0; l < TOT_U4/256; l++) {
            int i = tid + l * 256;
            const __nv_bfloat16* src;
            int r, c8;
            uint32_t soff;
            if (i < 2*A_U4) {
                int a = i / A_U4, j = i % A_U4;
                r = j >> 2; c8 = j & 3;
                src = (a ? Al : Ah) + (size_t)(row0 + r) * K;
                soff = (uint32_t)a * A_ELE;
            } else {
                int i2 = i - 2*A_U4;
                int a = i2 / B_U4, j = i2 % B_U4;
                r = j >> 2; c8 = j & 3;
                src = (a ? Bl : Bh) + (size_t)(col0 + r) * K;
                soff = 2*A_ELE + (uint32_t)a * B_ELE;
            }
            uint32_t dst = stb + (soff + r * TG_STRIDE + c8 * 8) * 2;
            const __nv_bfloat16* g = src + k0 + c8 * 8;
            asm volatile("cp.async.cg.shared.global [%0], [%1], 16;" :: "r"(dst), "l"(g));
        }
        asm volatile("cp.async.commit_group;" ::: "memory");
    };

    auto compute = [&](int stage) {
        uint32_t stb = sb + (uint32_t)stage * STAGE * 2;
        uint32_t bA_h = stb, bA_l = stb + A_ELE*2;
        uint32_t bB_h = stb + 2*A_ELE*2, bB_l = stb + (2*A_ELE + B_ELE)*2;
        #pragma unroll
        for (int kk = 0; kk < 32; kk += 16) {
            uint32_t ah[2][4], al[2][4];
            #pragma unroll
            for (int mb = 0; mb < 2; mb++) {
                int r = wm + mb * 16 + (lane & 15);
                int c = kk + (lane >> 4) * 8;
                uint32_t off = (uint32_t)(r * TG_STRIDE + c) * 2;
                ldm_x4(ah[mb], bA_h + off);
                ldm_x4(al[mb], bA_l + off);
            }
            #pragma unroll
            for (int nb = 0; nb < NB16; nb++) {
                int r = wn + nb * 16 + ((lane >> 4) << 3) + (lane & 7);
                int c = kk + ((lane >> 3) & 1) * 8;
                uint32_t off = (uint32_t)(r * TG_STRIDE + c) * 2;
                uint32_t bh[4], bl[4];
                ldm_x4(bh, bB_h + off);
                ldm_x4(bl, bB_l + off);
                #pragma unroll
                for (int mb = 0; mb < 2; mb++) {
                    mma16816(acc[mb][2*nb+0], ah[mb], bh[0], bh[1]);
                    mma16816(acc[mb][2*nb+1], ah[mb], bh[2], bh[3]);
                    mma16816(acc[mb][2*nb+0], ah[mb], bl[0], bl[1]);
                    mma16816(acc[mb][2*nb+1], ah[mb], bl[2], bl[3]);
                    mma16816(acc[mb][2*nb+0], al[mb], bh[0], bh[1]);
                    mma16816(acc[mb][2*nb+1], al[mb], bh[2], bh[3]);
                }
            }
        }
    };

    int nch = K >> 5;
    issue(0, 0);
    for (int ck = 0; ck < nch; ck++) {
        if (ck + 1 < nch) {
            issue((ck + 1) & 1, (ck + 1) << 5);
            asm volatile("cp.async.wait_group 1;" ::: "memory");
        } else {
            asm volatile("cp.async.wait_group 0;" ::: "memory");
        }
        __syncthreads();
        compute(ck & 1);
        __syncthreads();
    }

    int g = lane >> 2, tg = lane & 3;

    if constexpr (BM == 128) {
        if (c0v) {
            float mn = 1e30f, mx = -1e30f;
            #pragma unroll
            for (int mb = 0; mb < 2; mb++) {
                #pragma unroll
                for (int ug = 0; ug < 2; ug++) {
                    int cb = col0 + wn + ug*32;
                    int u0 = ((cb >> 5) << 3) + 2*tg;
                    float iv[4], fv[4], gv[4], ov[4];
                    #pragma unroll
                    for (int e = 0; e < 4; e++) {
                        int co = 2*tg + (e & 1);
                        iv[e] = acc[mb][ug*4+0][e] + bias[cb + 0  + co];
                        fv[e] = acc[mb][ug*4+1][e] + bias[cb + 8  + co];
                        gv[e] = acc[mb][ug*4+2][e] + bias[cb + 16 + co];
                        ov[e] = acc[mb][ug*4+3][e] + bias[cb + 24 + co];
                    }
                    #pragma unroll
                    for (int half = 0; half < 2; half++) {
                        int row = row0 + wm + mb*16 + g + half*8;
                        float2 cc = *(const float2*)(c0v + (size_t)row*256 + u0);
                        float cin[2] = {cc.x, cc.y};
                        float hh[2], c2[2];
                        #pragma unroll
                        for (int e2 = 0; e2 < 2; e2++) {
                            int e = half*2 + e2;
                            float si = 1.f/(1.f+expf(-iv[e]));
                            float sf = 1.f/(1.f+expf(-fv[e]));
                            float so = 1.f/(1.f+expf(-ov[e]));
                            c2[e2] = sf * cin[e2] + si * tanhf(gv[e]);
                            hh[e2] = so * tanhf(c2[e2]);
                            mn = fminf(mn, hh[e2]); mx = fmaxf(mx, hh[e2]);
                        }
                        *(float2*)(hOut + (size_t)row*256 + u0) = make_float2(hh[0], hh[1]);
                        *(float2*)(cOut + (size_t)row*256 + u0) = make_float2(c2[0], c2[1]);
                    }
                }
            }
            __shared__ float smn[256], smx[256];
            smn[tid] = mn; smx[tid] = mx; __syncthreads();
            for (int s = 128; s > 0; s >>= 1) {
                if (tid < s) {
                    smn[tid] = fminf(smn[tid], smn[tid+s]);
                    smx[tid] = fmaxf(smx[tid], smx[tid+s]);
                }
                __syncthreads();
            }
            if (tid == 0) {
                int bid = blockIdx.y * gridDim.x + blockIdx.x;
                g_pmin[bid] = smn[0]; g_pmax[bid] = smx[0];
            }
            return;
        }
    }

    float cia[2][2] = {}, cja[2][2] = {};
    #pragma unroll
    for (int mb = 0; mb < 2; mb++) {
        #pragma unroll
        for (int n8 = 0; n8 < NB; n8++) {
            int row = row0 + wm + mb * 16 + g;
            int col = col0 + wn + n8 * 8 + 2 * tg;
            float b0 = bias ? bias[col]   : 0.f;
            float b1 = bias ? bias[col+1] : 0.f;
            float v00 = acc[mb][n8][0] + b0, v01 = acc[mb][n8][1] + b1;
            float v10 = acc[mb][n8][2] + b0, v11 = acc[mb][n8][3] + b1;
            if (Shi) {
                size_t d0 = (size_t)row * ldS + col;
                size_t d1 = (size_t)(row + 8) * ldS + col;
                bf16split(v00, &Shi[d0],   &Slo[d0]);
                bf16split(v01, &Shi[d0+1], &Slo[d0+1]);
                bf16split(v10, &Shi[d1],   &Slo[d1]);
                bf16split(v11, &Shi[d1+1], &Slo[d1+1]);
            }
            if (hwT) {
                hwT[(size_t)col*NA + row]         = v00;
                hwT[(size_t)(col+1)*NA + row]     = v01;
                hwT[(size_t)col*NA + row + 8]     = v10;
                hwT[(size_t)(col+1)*NA + row + 8] = v11;
            }
            if (aivec) {
                float a0 = aivec[col], a1 = aivec[col+1];
                float j0 = ajvec[col], j1 = ajvec[col+1];
                cia[mb][0] += v00*a0 + v01*a1;
                cia[mb][1] += v10*a0 + v11*a1;
                cja[mb][0] += v00*j0 + v01*j1;
                cja[mb][1] += v10*j0 + v11*j1;
            }
        }
    }
    if (aivec) {
        int hh = (col0 + wn) / Gh;
        #pragma unroll
        for (int mb = 0; mb < 2; mb++) {
            #pragma unroll
            for (int hf = 0; hf < 2; hf++) {
                float ci = cia[mb][hf], cj = cja[mb][hf];
                ci += __shfl_xor_sync(0xffffffffu, ci, 1);
                ci += __shfl_xor_sync(0xffffffffu, ci, 2);
                cj += __shfl_xor_sync(0xffffffffu, cj, 1);
                cj += __shfl_xor_sync(0xffffffffu, cj, 2);
                if (tg == 0) {
                    int row = row0 + wm + mb * 16 + g + hf * 8;
                    atomicAdd(&g_ci[hh*NA + row], ci);
                    atomicAdd(&g_cj[hh*NA + row], cj);
                }
            }
        }
    }
}

// ---------------- fake-quant A: 256 blocks, 16 elem/thread -------------------
__global__ void quantA(const float* __restrict__ x,
                       __nv_bfloat16* __restrict__ hi, __nv_bfloat16* __restrict__ lo,
                       int npart)
{
    __shared__ float smn[256], smx[256];
    __shared__ float sparam[2];
    float mn = 1e30f, mx = -1e30f;
    for (int i = threadIdx.x; i < npart; i += 256) {
        mn = fminf(mn, g_pmin[i]); mx = fmaxf(mx, g_pmax[i]);
    }
    smn[threadIdx.x] = mn; smx[threadIdx.x] = mx; __syncthreads();
    for (int s = 128; s > 0; s >>= 1) {
        if (threadIdx.x < s) {
            smn[threadIdx.x] = fminf(smn[threadIdx.x], smn[threadIdx.x+s]);
            smx[threadIdx.x] = fmaxf(smx[threadIdx.x], smx[threadIdx.x+s]);
        }
        __syncthreads();
    }
    if (threadIdx.x == 0) {
        float a = smn[0], b = smx[0];
        if (a == b) { a -= 0.01f; b += 0.01f; }
        float scale = (b - a) / 255.f;
        sparam[0] = scale;
        sparam[1] = rintf(-a / scale);
    }
    __syncthreads();
    float scale = sparam[0], zp = sparam[1];

    double part = 0.0;
    #pragma unroll
    for (int l = 0; l < 4; l++) {
        int i = blockIdx.x*256 + threadIdx.x + l*65536;
        float4 t = ((const float4*)x)[i];
        float ts[4] = {t.x, t.y, t.z, t.w};
        float ds[4];
        #pragma unroll
        for (int q = 0; q < 4; q++) {
            float r = rintf(ts[q]/scale + zp);
            r = fminf(fmaxf(r, 0.f), 255.f);
            float d = (r - zp) * scale;
            ds[q] = d;
            part += (double)log2f(510.f * fabsf(d) + 1.f);
        }
        __nv_bfloat162 h01, h23, l01, l23;
        __nv_bfloat16 hh, ll;
        bf16split(ds[0], &hh, &ll); h01.x = hh; l01.x = ll;
        bf16split(ds[1], &hh, &ll); h01.y = hh; l01.y = ll;
        bf16split(ds[2], &hh, &ll); h23.x = hh; l23.x = ll;
        bf16split(ds[3], &hh, &ll); h23.y = hh; l23.y = ll;
        ((__nv_bfloat162*)hi)[i*2]   = h01;
        ((__nv_bfloat162*)hi)[i*2+1] = h23;
        ((__nv_bfloat162*)lo)[i*2]   = l01;
        ((__nv_bfloat162*)lo)[i*2+1] = l23;
    }
    __shared__ double sd[256];
    sd[threadIdx.x] = part; __syncthreads();
    for (int s = 128; s > 0; s >>= 1) { if (threadIdx.x < s) sd[threadIdx.x] += sd[threadIdx.x+s]; __syncthreads(); }
    if (threadIdx.x == 0) atomicAdd(&g_loss, sd[0]);
}

// ---------------- fake-quant T: 4 transposed 32x32 tiles per block -----------
__global__ void quantT(const float* __restrict__ inT,
                       __nv_bfloat16* __restrict__ hi, __nv_bfloat16* __restrict__ lo,
                       int npart)
{
    __shared__ float tile[32][33];
    __shared__ float smn[256], smx[256];
    __shared__ float sparam[2];
    int tx = threadIdx.x, ty = threadIdx.y;
    int tid = ty*32 + tx;

    float mn = (tid < npart) ? g_pmin[tid] : 1e30f;
    float mx = (tid < npart) ? g_pmax[tid] : -1e30f;
    smn[tid] = mn; smx[tid] = mx; __syncthreads();
    for (int s = 128; s > 0; s >>= 1) {
        if (tid < s) {
            smn[tid] = fminf(smn[tid], smn[tid+s]);
            smx[tid] = fmaxf(smx[tid], smx[tid+s]);
        }
        __syncthreads();
    }
    if (tid == 0) {
        float a = smn[0], b = smx[0];
        if (a == b) { a -= 0.01f; b += 0.01f; }
        float scale = (b - a) / 255.f;
        sparam[0] = scale;
        sparam[1] = rintf(-a / scale);
    }
    __syncthreads();
    float scale = sparam[0], zp = sparam[1];

    int c0 = blockIdx.y * 32;
    double part = 0.0;
    #pragma unroll 1
    for (int nt = 0; nt < 4; nt++) {
        int n0 = blockIdx.x * 128 + nt * 32;
        for (int cc = ty; cc < 32; cc += 8) {
            float t = inT[(size_t)(c0+cc)*NA + n0 + tx];
            float r = rintf(t/scale + zp);
            r = fminf(fmaxf(r, 0.f), 255.f);
            float d = (r - zp) * scale;
            tile[cc][tx] = d;
            part += (double)log2f(510.f * fabsf(d) + 1.f);
        }
        __syncthreads();
        for (int nn = ty; nn < 32; nn += 8) {
            float d = tile[tx][nn];
            size_t o = (size_t)(n0+nn)*256 + c0 + tx;
            bf16split(d, &hi[o], &lo[o]);
        }
        __syncthreads();
    }
    __shared__ double sd[256];
    sd[tid] = part; __syncthreads();
    for (int s = 128; s > 0; s >>= 1) { if (tid < s) sd[tid] += sd[tid+s]; __syncthreads(); }
    if (tid == 0) atomicAdd(&g_loss, sd[0]);
}

// ---------------- sortk: bitonic (warp-local inner stages) + scans + denom ----
__global__ void __launch_bounds__(1024)
sortk()
{
    extern __shared__ char sms[];
    float* key = (float*)sms;
    int*   idx = (int*)(key + NA);
    float* sA  = (float*)(idx + NA);
    float* sB  = sA + NA;
    __shared__ float wsum[32];
    int h = blockIdx.x;
    int tid = threadIdx.x, lane = tid & 31, warp = tid >> 5;

    for (int i = tid; i < NA; i += 1024) { key[i] = g_cj[h*NA + i]; idx[i] = i; }
    __syncthreads();
    for (int k = 2; k <= NA; k <<= 1) {
        int j = k >> 1;
        for (; j >= 128; j >>= 1) {
            #pragma unroll 2
            for (int p = tid; p < NA/2; p += 1024) {
                int i = ((p & ~(j-1)) << 1) | (p & (j-1));
                int il = i | j;
                bool up = ((i & k) == 0);
                float a = key[i], b = key[il];
                if (up ? (a > b) : (a < b)) {
                    key[i] = b; key[il] = a;
                    int tmp = idx[i]; idx[i] = idx[il]; idx[il] = tmp;
                }
            }
            __syncthreads();
        }
        // warp-local: j <= 64, warp w owns elements [128w, 128w+128)
        for (; j >= 1; j >>= 1) {
            #pragma unroll 2
            for (int q = lane; q < 64; q += 32) {
                int p = (warp << 6) | q;
                int i = ((p & ~(j-1)) << 1) | (p & (j-1));
                int il = i | j;
                bool up = ((i & k) == 0);
                float a = key[i], b = key[il];
                if (up ? (a > b) : (a < b)) {
                    key[i] = b; key[il] = a;
                    int tmp = idx[i]; idx[i] = idx[il]; idx[il] = tmp;
                }
            }
            __syncwarp();
        }
        __syncthreads();
    }
    float cm = key[NA-1];

    int t0 = tid * 4;
    float kw0 = key[t0], kw1 = key[t0+1], kw2 = key[t0+2], kw3 = key[t0+3];
    float wB0 = expf(0.2f*(kw0-cm)), wB1 = expf(0.2f*(kw1-cm));
    float wB2 = expf(0.2f*(kw2-cm)), wB3 = expf(0.2f*(kw3-cm));
    float wA0 = expf(kw0-cm), wA1 = expf(kw1-cm), wA2 = expf(kw2-cm), wA3 = expf(kw3-cm);
    *(int4*)&g_sidx[h*NA + t0] = make_int4(idx[t0], idx[t0+1], idx[t0+2], idx[t0+3]);
    *(float4*)&g_wA[h*NA + t0] = make_float4(wA0, wA1, wA2, wA3);
    *(float4*)&g_wB[h*NA + t0] = make_float4(wB0, wB1, wB2, wB3);

    {
        float v0 = wB0, v1 = v0+wB1, v2 = v1+wB2, v3 = v2+wB3;
        float tot = v3, s = tot;
        #pragma unroll
        for (int o = 1; o < 32; o <<= 1) { float u = __shfl_up_sync(0xffffffffu, s, o); if (lane >= o) s += u; }
        if (lane == 31) wsum[warp] = s;
        __syncthreads();
        if (warp == 0) {
            float y = wsum[lane];
            #pragma unroll
            for (int o = 1; o < 32; o <<= 1) { float u = __shfl_up_sync(0xffffffffu, y, o); if (lane >= o) y += u; }
            wsum[lane] = y;
        }
        __syncthreads();
        float off = (warp ? wsum[warp-1] : 0.f) + (s - tot);
        sB[t0] = off+v0; sB[t0+1] = off+v1; sB[t0+2] = off+v2; sB[t0+3] = off+v3;
    }
    __syncthreads();
    {
        int rb = NA - 4 - t0;
        float a0 = expf(key[rb]-cm),   a1 = expf(key[rb+1]-cm);
        float a2 = expf(key[rb+2]-cm), a3 = expf(key[rb+3]-cm);
        float u0 = a3, u1 = u0+a2, u2 = u1+a1, u3 = u2+a0;
        float tot = u3, s = tot;
        #pragma unroll
        for (int o = 1; o < 32; o <<= 1) { float u = __shfl_up_sync(0xffffffffu, s, o); if (lane >= o) s += u; }
        if (lane == 31) wsum[warp] = s;
        __syncthreads();
        if (warp == 0) {
            float y = wsum[lane];
            #pragma unroll
            for (int o = 1; o < 32; o <<= 1) { float u = __shfl_up_sync(0xffffffffu, y, o); if (lane >= o) y += u; }
            wsum[lane] = y;
        }
        __syncthreads();
        float off = (warp ? wsum[warp-1] : 0.f) + (s - tot);
        sA[rb] = off+u3; sA[rb+1] = off+u2; sA[rb+2] = off+u1; sA[rb+3] = off+u0;
    }
    __syncthreads();

    for (int l = 0; l < 4; l++) {
        int n = tid + l*1024;
        float cin = g_ci[h*NA + n];
        float t = -cin;
        int lo = 0, hi = NA;
        while (lo < hi) {
            int mid = (lo + hi) >> 1;
            if (key[mid] <= t) lo = mid + 1; else hi = mid;
        }
        float r = expf(0.8f * (cin + cm));
        float A = (lo < NA) ? sA[lo]     : 0.f;
        float B = (lo > 0)  ? sB[lo - 1] : 0.f;
        g_kcount[h*NA + n] = lo;
        g_rn[h*NA + n]     = r;
        g_invd[h*NA + n]   = 1.f / (r*A + B);
        g_ci[h*NA + n] = 0.f;
        g_cj[h*NA + n] = 0.f;
    }
}

// ---------------- scomb: 512 threads, per-column scan + transposed output ----
__global__ void __launch_bounds__(512)
scomb(const float* __restrict__ bias, float* __restrict__ outT,
      int G, int do_elu, int do_mm)
{
    __shared__ float s_pre[NA];
    __shared__ float s_suf[NA];
    __shared__ float wsum[16];
    int c = blockIdx.x;
    int h = c / G;
    int tid = threadIdx.x, lane = tid & 31, warp = tid >> 5;
    int t0 = tid * 8;
    const float* xrow = g_hWT + (size_t)c * NA;

    // prefix of wB*x
    {
        int4 iva = *(const int4*)&g_sidx[h*NA + t0];
        int4 ivb = *(const int4*)&g_sidx[h*NA + t0 + 4];
        float4 wa = *(const float4*)&g_wB[h*NA + t0];
        float4 wb = *(const float4*)&g_wB[h*NA + t0 + 4];
        float v[8];
        float run = wa.x * xrow[iva.x];              v[0] = run;
        run += wa.y * xrow[iva.y];                   v[1] = run;
        run += wa.z * xrow[iva.z];                   v[2] = run;
        run += wa.w * xrow[iva.w];                   v[3] = run;
        run += wb.x * xrow[ivb.x];                   v[4] = run;
        run += wb.y * xrow[ivb.y];                   v[5] = run;
        run += wb.z * xrow[ivb.z];                   v[6] = run;
        run += wb.w * xrow[ivb.w];                   v[7] = run;
        float tot = run, s = tot;
        #pragma unroll
        for (int o = 1; o < 32; o <<= 1) { float u = __shfl_up_sync(0xffffffffu, s, o); if (lane >= o) s += u; }
        if (lane == 31) wsum[warp] = s;
        __syncthreads();
        if (warp == 0 && lane < 16) {
            float y = wsum[lane];
            #pragma unroll
            for (int o = 1; o < 16; o <<= 1) { float u = __shfl_up_sync(0xffffu, y, o); if (lane >= o) y += u; }
            wsum[lane] = y;
        }
        __syncthreads();
        float off = (warp ? wsum[warp-1] : 0.f) + (s - tot);
        #pragma unroll
        for (int e = 0; e < 8; e++) s_pre[t0+e] = off + v[e];
    }
    __syncthreads();
    // suffix of wA*x (reversed prefix)
    {
        int rb = NA - 8 - t0;
        int4 iva = *(const int4*)&g_sidx[h*NA + rb];
        int4 ivb = *(const int4*)&g_sidx[h*NA + rb + 4];
        float4 wa = *(const float4*)&g_wA[h*NA + rb];
        float4 wb = *(const float4*)&g_wA[h*NA + rb + 4];
        float xs[8] = { xrow[iva.x], xrow[iva.y], xrow[iva.z], xrow[iva.w],
                        xrow[ivb.x], xrow[ivb.y], xrow[ivb.z], xrow[ivb.w] };
        float ws[8] = { wa.x, wa.y, wa.z, wa.w, wb.x, wb.y, wb.z, wb.w };
        float u[8];
        float run = ws[7]*xs[7];  u[0] = run;   // -> rb+7
        #pragma unroll
        for (int e = 1; e < 8; e++) { run += ws[7-e]*xs[7-e]; u[e] = run; }
        float tot = run, s = tot;
        #pragma unroll
        for (int o = 1; o < 32; o <<= 1) { float uu = __shfl_up_sync(0xffffffffu, s, o); if (lane >= o) s += uu; }
        if (lane == 31) wsum[warp] = s;
        __syncthreads();
        if (warp == 0 && lane < 16) {
            float y = wsum[lane];
            #pragma unroll
            for (int o = 1; o < 16; o <<= 1) { float uu = __shfl_up_sync(0xffffu, y, o); if (lane >= o) y += uu; }
            wsum[lane] = y;
        }
        __syncthreads();
        float off = (warp ? wsum[warp-1] : 0.f) + (s - tot);
        #pragma unroll
        for (int e = 0; e < 8; e++) s_suf[rb + 7 - e] = off + u[e];
    }
    __syncthreads();

    float bv = bias[c];
    float mn = 1e30f, mx = -1e30f;
    #pragma unroll
    for (int l = 0; l < 8; l++) {
        int n = tid + l*512;
        int k = g_kcount[h*NA + n];
        float r = g_rn[h*NA + n];
        float invd = g_invd[h*NA + n];
        float Av = (k < NA) ? s_suf[k]     : 0.f;
        float Bv = (k > 0)  ? s_pre[k - 1] : 0.f;
        float val = (r*Av + Bv) * invd + bv;
        if (do_elu) val = (val > 0.f) ? val : expm1f(val);
        mn = fminf(mn, val); mx = fmaxf(mx, val);
        outT[(size_t)c*NA + n] = val;
    }
    if (do_mm) {
        __shared__ float smn[512], smx[512];
        smn[tid] = mn; smx[tid] = mx; __syncthreads();
        for (int s = 256; s > 0; s >>= 1) {
            if (tid < s) {
                smn[tid] = fminf(smn[tid], smn[tid+s]);
                smx[tid] = fmaxf(smx[tid], smx[tid+s]);
            }
            __syncthreads();
        }
        if (tid == 0) { g_pmin[c] = smn[0]; g_pmax[c] = smx[0]; }
    }
}

// ---------------- fused policy + value head (+ loss write) ----------------
__global__ void __launch_bounds__(256)
policyk(const float* __restrict__ A0, const float* __restrict__ A1T,
        const float* __restrict__ Wa, const float* __restrict__ ba,
        const float* __restrict__ Wv, const float* __restrict__ bv,
        float* __restrict__ out_logp, float* __restrict__ out_value,
        float* __restrict__ out_loss)
{
    if (blockIdx.x == 0 && threadIdx.x == 0) out_loss[0] = (float)g_loss;
    __shared__ float As[16][68];
    __shared__ float Bs[16][68];
    __shared__ float Ss[64][65];
    int tid = threadIdx.x;
    int tx = tid % 16, ty = tid / 16;
    int row0 = blockIdx.x * 64;
    float acc[4][4] = {};
    float vacc = 0.f;

    for (int k0 = 0; k0 < 512; k0 += 16) {
        if (k0 < 256) {
            int lin = tid * 4;
            int m = lin >> 4, kk = lin & 15;
            float4 v = *(const float4*)&A0[(size_t)(row0+m)*256 + k0 + kk];
            As[kk+0][m] = v.x; As[kk+1][m] = v.y; As[kk+2][m] = v.z; As[kk+3][m] = v.w;
        } else {
            int lin = tid * 4;
            int kk = lin >> 6, m4 = lin & 63;
            float4 v = *(const float4*)&A1T[(size_t)(k0-256+kk)*NA + row0 + m4];
            *(float4*)&As[kk][m4] = v;
        }
        {
            int lin = tid * 4;
            int kk = lin >> 6, n = lin & 63;
            *(float4*)&Bs[kk][n] = *(const float4*)&Wa[(size_t)(k0+kk)*64 + n];
        }
        __syncthreads();
        #pragma unroll
        for (int kk = 0; kk < 16; kk++) {
            float a[4], bb[4];
            #pragma unroll
            for (int i = 0; i < 4; i++) a[i] = As[kk][ty*4+i];
            #pragma unroll
            for (int j = 0; j < 4; j++) bb[j] = Bs[kk][tx*4+j];
            #pragma unroll
            for (int i = 0; i < 4; i++)
                #pragma unroll
                for (int j = 0; j < 4; j++)
                    acc[i][j] = fmaf(a[i], bb[j], acc[i][j]);
        }
        if (tid < 64) {
            #pragma unroll
            for (int kk = 0; kk < 16; kk++)
                vacc = fmaf(As[kk][tid], Wv[k0+kk], vacc);
        }
        __syncthreads();
    }
    if (tid < 64) out_value[row0 + tid] = vacc + bv[0];

    #pragma unroll
    for (int i = 0; i < 4; i++)
        #pragma unroll
        for (int j = 0; j < 4; j++)
            Ss[ty*4+i][tx*4+j] = acc[i][j] + ba[tx*4+j];
    __syncthreads();

    int row = tid >> 2, quad = tid & 3;
    float m = -1e30f;
    #pragma unroll
    for (int c = 0; c < 16; c++) m = fmaxf(m, Ss[row][quad*16 + c]);
    m = fmaxf(m, __shfl_xor_sync(0xffffffffu, m, 1));
    m = fmaxf(m, __shfl_xor_sync(0xffffffffu, m, 2));
    float s = 0.f;
    #pragma unroll
    for (int c = 0; c < 16; c++) s += expf(Ss[row][quad*16 + c] - m);
    s += __shfl_xor_sync(0xffffffffu, s, 1);
    s += __shfl_xor_sync(0xffffffffu, s, 2);
    float lse = m + logf(s);
    #pragma unroll
    for (int c = 0; c < 16; c++)
        out_logp[(size_t)(row0+row)*64 + quad*16 + c] = Ss[row][quad*16 + c] - lse;
}

// ---------------- host ----------------
extern "C" void kernel_launch(void* const* d_in, const int* in_sizes, int n_in,
                              void* d_out, int out_size)
{
    const float* obs  = (const float*)d_in[0];
    const float* h0   = (const float*)d_in[1];
    const float* c0   = (const float*)d_in[2];
    const float* Wobs = (const float*)d_in[3];
    const float* bobs = (const float*)d_in[4];
    const float* Wih  = (const float*)d_in[5];
    const float* Whh  = (const float*)d_in[6];
    const float* bih  = (const float*)d_in[7];
    const float* bhh  = (const float*)d_in[8];
    const float* W1   = (const float*)d_in[9];
    const float* ai1  = (const float*)d_in[10];
    const float* aj1  = (const float*)d_in[11];
    const float* b1   = (const float*)d_in[12];
    const float* W2   = (const float*)d_in[13];
    const float* ai2  = (const float*)d_in[14];
    const float* aj2  = (const float*)d_in[15];
    const float* b2   = (const float*)d_in[16];
    const float* Wv   = (const float*)d_in[17];
    const float* bv   = (const float*)d_in[18];
    const float* Wa   = (const float*)d_in[19];
    const float* ba   = (const float*)d_in[20];

    float* out       = (float*)d_out;
    float* out_logp  = out;
    float* out_value = out + NA*ACT;
    float* out_h     = out_value + NA;
    float* out_c     = out_h + NA*HD;
    float* out_loss  = out_c + NA*HD;

    float *p_hWT, *p_commT, *p_bsum;
    __nv_bfloat16 *p_Ah, *p_Al, *p_A2h, *p_A2l;
    __nv_bfloat16 *p_B0h, *p_B0l, *p_Bgh, *p_Bgl, *p_B1h, *p_B1l, *p_B2h, *p_B2l;
    cudaGetSymbolAddress((void**)&p_hWT,    g_hWT);
    cudaGetSymbolAddress((void**)&p_commT,  g_commT);
    cudaGetSymbolAddress((void**)&p_bsum,   g_bsum);
    cudaGetSymbolAddress((void**)&p_Ah,     g_Ah);
    cudaGetSymbolAddress((void**)&p_Al,     g_Al);
    cudaGetSymbolAddress((void**)&p_A2h,    g_A2h);
    cudaGetSymbolAddress((void**)&p_A2l,    g_A2l);
    cudaGetSymbolAddress((void**)&p_B0h,    g_B0h);
    cudaGetSymbolAddress((void**)&p_B0l,    g_B0l);
    cudaGetSymbolAddress((void**)&p_Bgh,    g_Bgh);
    cudaGetSymbolAddress((void**)&p_Bgl,    g_Bgl);
    cudaGetSymbolAddress((void**)&p_B1h,    g_B1h);
    cudaGetSymbolAddress((void**)&p_B1l,    g_B1l);
    cudaGetSymbolAddress((void**)&p_B2h,    g_B2h);
    cudaGetSymbolAddress((void**)&p_B2l,    g_B2l);

    const int SM128 = (2*(2*128*TG_STRIDE + 2*128*TG_STRIDE)) * 2;
    const int SM64  = (2*(2*64*TG_STRIDE  + 2*128*TG_STRIDE)) * 2;
    const int SMSORT = NA * 16;
    cudaFuncSetAttribute((const void*)tgemm<128>, cudaFuncAttributeMaxDynamicSharedMemorySize, SM128);
    cudaFuncSetAttribute((const void*)tgemm<64>,  cudaFuncAttributeMaxDynamicSharedMemorySize, SM64);
    cudaFuncSetAttribute((const void*)sortk,      cudaFuncAttributeMaxDynamicSharedMemorySize, SMSORT);

    // 1. prep: splits, permutes, fused bias dots, zero ci/cj + loss
    wprep<<<WQ8/256, 256>>>(obs, h0, Wobs, Wih, Whh, W1, W2, bih, bhh, bobs);
    // 2. weight-product GEMM: (Wih_perm @ Wobs^T-free form) -> Bg cols 0..255
    tgemm<64><<<dim3(2, 16), 256, SM64>>>(p_A2h, p_A2l, p_B0h, p_B0l, nullptr,
                                          p_Bgh, p_Bgl, 512,
                                          nullptr, nullptr, nullptr, 0,
                                          nullptr, nullptr, nullptr, 256, 256);
    // 3. gates GEMM ([obs|h0] @ Bg^T) + fused LSTM -> out_h, out_c, minmax[256]
    tgemm<128><<<dim3(8, 32), 256, SM128>>>(p_Ah, p_Al, p_Bgh, p_Bgl, p_bsum,
                                            nullptr, nullptr, 0,
                                            nullptr, nullptr, nullptr, 0,
                                            c0, out_h, out_c, 1024, 512);
    // 4. quant #1 -> splits into A2 (row-major [n][256])
    quantA<<<256, 256>>>(out_h, p_A2h, p_A2l, 256);
    // 5. GAT1 projection -> hWT + fused ci/cj
    tgemm<64><<<dim3(2, 64), 256, SM64>>>(p_A2h, p_A2l, p_B1h, p_B1l, nullptr,
                                          nullptr, nullptr, 0,
                                          p_hWT, ai1, aj1, 64,
                                          nullptr, nullptr, nullptr, 256, 256);
    // 6-7. GAT1 attention
    sortk<<<4, 1024, SMSORT>>>();
    scomb<<<256, 512>>>(b1, p_commT, 64, 1, 1);
    // 8. quant #2 (transposed input)
    quantT<<<dim3(NA/128, 8), dim3(32, 8)>>>(p_commT, p_A2h, p_A2l, 256);
    // 9. GAT2 projection
    tgemm<64><<<dim3(2, 64), 256, SM64>>>(p_A2h, p_A2l, p_B2h, p_B2l, nullptr,
                                          nullptr, nullptr, 0,
                                          p_hWT, ai2, aj2, 256,
                                          nullptr, nullptr, nullptr, 256, 256);
    // 10-11. GAT2 attention
    sortk<<<1, 1024, SMSORT>>>();
    scomb<<<256, 512>>>(b2, p_commT, 256, 0, 0);
    // 12. fused policy + value heads + loss
    policyk<<<NA/64, 256>>>(out_h, p_commT, Wa, ba, Wv, bv, out_logp, out_value, out_loss);
}